// round 11
// baseline (speedup 1.0000x reference)
#include <cuda_runtime.h>
#include <cuda_fp16.h>
#include <math.h>

// ---- problem dims ----
#define BB 16
#define NCC 1024
#define NTT 2048
#define GAPD 128
#define CTRLD 8
#define RD 256
#define NHD 4
#define HDD 64
#define HIDD 128
#define LHD 192
#define CIN (CTRLD + GAPD)          // 136
#define DIN (2 * RD + GAPD + CTRLD) // 648

// ---- scratch ----
__device__ unsigned short g_h12h [BB * NCC * 2 * HIDD];
__device__ float g_rep  [BB * NCC * RD];
__device__ float g_hle  [BB * NCC * RD];
__device__ float g_part [BB * 32 * RD];
__device__ float g_hmean[BB * RD];
__device__ float g_z    [BB * RD];
__device__ unsigned short g_qkvh [BB * NCC * 3 * RD];
__device__ unsigned short g_attnoh[BB * NCC * RD];
__device__ float g_oproj[BB * NCC * RD];
__device__ unsigned short g_rep2h[BB * NCC * RD];
__device__ unsigned short g_qth  [(size_t)BB * NTT * RD];
__device__ unsigned short g_deth [(size_t)BB * NTT * RD];

// ===================== fp16 mma helpers =====================
__device__ __forceinline__ unsigned h2p(float a, float b) {
    __half2 h = __floats2half2_rn(a, b);
    return *reinterpret_cast<unsigned*>(&h);
}
__device__ __forceinline__ void mma16(float* d, const unsigned* a, const unsigned* b) {
    asm volatile(
        "mma.sync.aligned.m16n8k16.row.col.f32.f16.f16.f32 "
        "{%0,%1,%2,%3},{%4,%5,%6,%7},{%8,%9},{%0,%1,%2,%3};\n"
        : "+f"(d[0]), "+f"(d[1]), "+f"(d[2]), "+f"(d[3])
        : "r"(a[0]), "r"(a[1]), "r"(a[2]), "r"(a[3]), "r"(b[0]), "r"(b[1]));
}
__device__ __forceinline__ float4 ld_guard(const float* src, int gk, int K) {
    if (gk + 4 <= K) return *(const float4*)src;
    float4 v = make_float4(0.f, 0.f, 0.f, 0.f);
    if (gk     < K) v.x = src[0];
    if (gk + 1 < K) v.y = src[1];
    if (gk + 2 < K) v.z = src[2];
    if (gk + 3 < K) v.w = src[3];
    return v;
}
__device__ __forceinline__ unsigned ilo(unsigned a, unsigned b) { return __byte_perm(a, b, 0x5410); }
__device__ __forceinline__ unsigned ihi(unsigned a, unsigned b) { return __byte_perm(a, b, 0x7632); }

// ===================== fp16 GEMM (reg-pipelined), B = [K,N] row-major ====
#define XBM 128
#define XBK 32

// MODE 0: plain A. MODE 2: A = [cy | cx], K=CIN.
// HA 1: A is half (MODE 0 only). BMODE 1: B cols split B/B2. OUTH 1: C half.
template<int WNT, int ACT, int MODE, int BMODE, int OUTH, int HA>
__global__ void __launch_bounds__(256, 2) mma_gemm(
    const float* __restrict__ A, const float* __restrict__ B,
    const float* __restrict__ bias, float* __restrict__ C,
    int M, int N, int K, int lda, int ldb, int ldc,
    float alpha,
    const float* __restrict__ zt, const float* __restrict__ txt,
    const float* __restrict__ pct,
    const float* __restrict__ B2, const float* __restrict__ bias2)
{
    constexpr int XBN_ = WNT * 4;
    constexpr int NI = WNT / 8;

    __shared__ unsigned As2[XBM][20];
    __shared__ unsigned Bs2[XBK / 2][XBN_ + 8];

    int tid = threadIdx.x;
    int wid = tid >> 5, lane = tid & 31;
    int g = lane >> 2, t4 = lane & 3;
    int wm = wid & 1, wn = wid >> 1;
    int m0 = blockIdx.x * XBM, n0 = blockIdx.y * XBN_;

    float acc[4][NI][4];
#pragma unroll
    for (int i = 0; i < 4; i++)
#pragma unroll
        for (int j = 0; j < NI; j++)
#pragma unroll
            for (int l = 0; l < 4; l++) acc[i][j][l] = 0.f;

    float4 ra[4]; uint2 rah[4];
    float4 rbE[2], rbO[2];
    constexpr int C4  = XBN_ / 4;
    constexpr int RP2 = 256 / C4;
    constexpr int ITS2 = (XBK / 2) / RP2;

    const int ac = (tid & 7) * 4;
    const int ar = tid >> 3;
    const int bc4 = tid % C4;
    const int brb = tid / C4;

    auto loadA = [&](int k0) {
        int gk = k0 + ac;
#pragma unroll
        for (int p = 0; p < 4; p++) {
            int gm = m0 + p * 32 + ar;
            if (MODE == 2) {
                const float* s;
                if (gk < CTRLD)    s = zt  + (long)gm * CTRLD + gk;
                else if (gk < CIN) s = txt + (long)gm * GAPD + (gk - CTRLD);
                else               s = nullptr;
                ra[p] = s ? *(const float4*)s : make_float4(0.f, 0.f, 0.f, 0.f);
            } else if (HA) {
                const unsigned short* Ah = (const unsigned short*)A;
                rah[p] = (gk + 4 <= K) ? *(const uint2*)(Ah + (long)gm * lda + gk)
                                       : make_uint2(0u, 0u);
            } else {
                ra[p] = ld_guard(A + (long)gm * lda + gk, gk, K);
            }
        }
    };
    auto loadB = [&](int k0) {
        int gn = n0 + bc4 * 4;
#pragma unroll
        for (int it = 0; it < ITS2; it++) {
            int kp = k0 + (it * RP2 + brb) * 2;
            if (BMODE == 1) {
                const float* base0 = (gn < HIDD) ? B : B2;
                int gq = (gn < HIDD) ? gn : gn - HIDD;
                rbE[it] = (kp     < K) ? *(const float4*)(base0 + (long)kp * ldb + gq)
                                       : make_float4(0.f, 0.f, 0.f, 0.f);
                rbO[it] = (kp + 1 < K) ? *(const float4*)(base0 + (long)(kp + 1) * ldb + gq)
                                       : make_float4(0.f, 0.f, 0.f, 0.f);
            } else {
                bool okn = (gn + 3 < N);
                rbE[it] = (kp     < K && okn) ? *(const float4*)(B + (long)kp * ldb + gn)
                                              : make_float4(0.f, 0.f, 0.f, 0.f);
                rbO[it] = (kp + 1 < K && okn) ? *(const float4*)(B + (long)(kp + 1) * ldb + gn)
                                              : make_float4(0.f, 0.f, 0.f, 0.f);
            }
        }
    };
    auto stsAB = [&]() {
#pragma unroll
        for (int p = 0; p < 4; p++) {
            if (HA && MODE == 0) {
                *(uint2*)&As2[p * 32 + ar][ac >> 1] = rah[p];
            } else {
                uint2 u = make_uint2(h2p(ra[p].x, ra[p].y), h2p(ra[p].z, ra[p].w));
                *(uint2*)&As2[p * 32 + ar][ac >> 1] = u;
            }
        }
#pragma unroll
        for (int it = 0; it < ITS2; it++) {
            uint4 u = make_uint4(h2p(rbE[it].x, rbO[it].x), h2p(rbE[it].y, rbO[it].y),
                                 h2p(rbE[it].z, rbO[it].z), h2p(rbE[it].w, rbO[it].w));
            *(uint4*)&Bs2[it * RP2 + brb][bc4 * 4] = u;
        }
    };

    int kT = (K + XBK - 1) / XBK;
    loadA(0); loadB(0);

    for (int t = 0; t < kT; t++) {
        stsAB();
        __syncthreads();
        if (t + 1 < kT) { loadA((t + 1) * XBK); loadB((t + 1) * XBK); }
#pragma unroll
        for (int ks = 0; ks < 2; ks++) {
            int kb2 = ks * 8;
            unsigned af[4][4], bf[NI][2];
#pragma unroll
            for (int mi = 0; mi < 4; mi++) {
                int ma = wm * 64 + mi * 16 + g;
                af[mi][0] = As2[ma    ][kb2 + t4];
                af[mi][1] = As2[ma + 8][kb2 + t4];
                af[mi][2] = As2[ma    ][kb2 + t4 + 4];
                af[mi][3] = As2[ma + 8][kb2 + t4 + 4];
            }
#pragma unroll
            for (int ni = 0; ni < NI; ni++) {
                int nb = wn * WNT + ni * 8 + g;
                bf[ni][0] = Bs2[kb2 + t4    ][nb];
                bf[ni][1] = Bs2[kb2 + t4 + 4][nb];
            }
#pragma unroll
            for (int mi = 0; mi < 4; mi++)
#pragma unroll
                for (int ni = 0; ni < NI; ni++)
                    mma16(acc[mi][ni], af[mi], bf[ni]);
        }
        __syncthreads();
    }

#pragma unroll
    for (int mi = 0; mi < 4; mi++) {
        int gm = m0 + wm * 64 + mi * 16 + g;
#pragma unroll
        for (int ni = 0; ni < NI; ni++) {
            int gn = n0 + wn * WNT + ni * 8 + t4 * 2;
            if (gn >= N) continue;
            float b0, b1;
            if (BMODE == 1) {
                const float* bp = (gn < HIDD) ? bias : bias2;
                int gq = (gn < HIDD) ? gn : gn - HIDD;
                b0 = bp[gq]; b1 = bp[gq + 1];
            } else {
                b0 = bias ? bias[gn] : 0.f;
                b1 = bias ? bias[gn + 1] : 0.f;
            }
            float v0 = acc[mi][ni][0] * alpha + b0;
            float v1 = acc[mi][ni][1] * alpha + b1;
            float v2 = acc[mi][ni][2] * alpha + b0;
            float v3 = acc[mi][ni][3] * alpha + b1;
            if (ACT == 1) {
                v0 = fmaxf(v0, 0.f); v1 = fmaxf(v1, 0.f);
                v2 = fmaxf(v2, 0.f); v3 = fmaxf(v3, 0.f);
            }
            if (OUTH) {
                unsigned short* Ch = (unsigned short*)C;
                *(unsigned*)&Ch[(long)gm * ldc + gn]       = h2p(v0, v1);
                *(unsigned*)&Ch[(long)(gm + 8) * ldc + gn] = h2p(v2, v3);
            } else {
                *(float2*)&C[(long)gm * ldc + gn]       = make_float2(v0, v1);
                *(float2*)&C[(long)(gm + 8) * ldc + gn] = make_float2(v2, v3);
            }
        }
    }
}

// ===================== fused decoder: dec1 (K=648) + dec2 (128->16) + epilogue ====
// grid 256, 256 threads. A gathered from [det(half) | z | tx | pc].
#define DEC_DSMEM ((128 * 132 + 128 * 17 + 16) * 4)

__global__ void __launch_bounds__(256) dec_fused_k(
    const unsigned short* __restrict__ deth, const float* __restrict__ zt,
    const float* __restrict__ txt, const float* __restrict__ pct,
    const float* __restrict__ B, const float* __restrict__ bias,
    const float* __restrict__ w2, const float* __restrict__ b2,
    float* __restrict__ out)
{
    extern __shared__ float dsm[];
    float* dh_s = dsm;                     // [128][132]
    float* w2s  = dsm + 128 * 132;         // [128][17]
    float* b2s  = w2s + 128 * 17;          // [16]

    __shared__ unsigned As2[XBM][20];
    __shared__ unsigned Bs2[XBK / 2][136];

    const int N = HIDD, K = DIN, ldb = HIDD;
    int tid = threadIdx.x;
    int wid = tid >> 5, lane = tid & 31;
    int g = lane >> 2, t4 = lane & 3;
    int wm = wid & 1, wn = wid >> 1;
    int m0 = blockIdx.x * XBM;

    float acc[4][4][4];
#pragma unroll
    for (int i = 0; i < 4; i++)
#pragma unroll
        for (int j = 0; j < 4; j++)
#pragma unroll
            for (int l = 0; l < 4; l++) acc[i][j][l] = 0.f;

    float4 ra[4]; uint2 rah[4];
    float4 rbE[2], rbO[2];
    const int ac = (tid & 7) * 4;
    const int ar = tid >> 3;
    const int bc4 = tid & 31;      // C4 = 32
    const int brb = tid >> 5;      // RP2 = 8

    auto loadA = [&](int k0) {
        int gk = k0 + ac;
#pragma unroll
        for (int p = 0; p < 4; p++) {
            int gm = m0 + p * 32 + ar;
            if (gk < RD) {
                rah[p] = *(const uint2*)(deth + (long)gm * RD + gk);
            } else {
                const float* s;
                if (gk < 2 * RD)             s = zt  + (long)(gm >> 11) * RD + (gk - RD);
                else if (gk < 2 * RD + GAPD) s = txt + (long)gm * GAPD + (gk - 2 * RD);
                else if (gk < DIN)           s = pct + (long)gm * CTRLD + (gk - 2 * RD - GAPD);
                else                         s = nullptr;
                ra[p] = s ? *(const float4*)s : make_float4(0.f, 0.f, 0.f, 0.f);
            }
        }
    };
    auto loadB = [&](int k0) {
#pragma unroll
        for (int it = 0; it < 2; it++) {
            int kp = k0 + (it * 8 + brb) * 2;
            rbE[it] = (kp     < K) ? *(const float4*)(B + (long)kp * ldb + bc4 * 4)
                                   : make_float4(0.f, 0.f, 0.f, 0.f);
            rbO[it] = (kp + 1 < K) ? *(const float4*)(B + (long)(kp + 1) * ldb + bc4 * 4)
                                   : make_float4(0.f, 0.f, 0.f, 0.f);
        }
    };
    auto stsAB = [&](int k0) {
        int gk = k0 + ac;
#pragma unroll
        for (int p = 0; p < 4; p++) {
            if (gk < RD) {
                *(uint2*)&As2[p * 32 + ar][ac >> 1] = rah[p];
            } else {
                uint2 u = make_uint2(h2p(ra[p].x, ra[p].y), h2p(ra[p].z, ra[p].w));
                *(uint2*)&As2[p * 32 + ar][ac >> 1] = u;
            }
        }
#pragma unroll
        for (int it = 0; it < 2; it++) {
            uint4 u = make_uint4(h2p(rbE[it].x, rbO[it].x), h2p(rbE[it].y, rbO[it].y),
                                 h2p(rbE[it].z, rbO[it].z), h2p(rbE[it].w, rbO[it].w));
            *(uint4*)&Bs2[it * 8 + brb][bc4 * 4] = u;
        }
    };

    // preload w2/b2 while mainloop runs? keep simple: after. (b2s/w2s in dsm)
    int kT = (K + XBK - 1) / XBK;   // 21
    loadA(0); loadB(0);

    for (int t = 0; t < kT; t++) {
        stsAB(t * XBK);
        __syncthreads();
        if (t + 1 < kT) { loadA((t + 1) * XBK); loadB((t + 1) * XBK); }
#pragma unroll
        for (int ks = 0; ks < 2; ks++) {
            int kb2 = ks * 8;
            unsigned af[4][4], bf[4][2];
#pragma unroll
            for (int mi = 0; mi < 4; mi++) {
                int ma = wm * 64 + mi * 16 + g;
                af[mi][0] = As2[ma    ][kb2 + t4];
                af[mi][1] = As2[ma + 8][kb2 + t4];
                af[mi][2] = As2[ma    ][kb2 + t4 + 4];
                af[mi][3] = As2[ma + 8][kb2 + t4 + 4];
            }
#pragma unroll
            for (int ni = 0; ni < 4; ni++) {
                int nb = wn * 32 + ni * 8 + g;
                bf[ni][0] = Bs2[kb2 + t4    ][nb];
                bf[ni][1] = Bs2[kb2 + t4 + 4][nb];
            }
#pragma unroll
            for (int mi = 0; mi < 4; mi++)
#pragma unroll
                for (int ni = 0; ni < 4; ni++)
                    mma16(acc[mi][ni], af[mi], bf[ni]);
        }
        __syncthreads();
    }

    // ---- dec1 epilogue into smem (bias + ReLU), fp32 ----
#pragma unroll
    for (int mi = 0; mi < 4; mi++) {
        int rl = wm * 64 + mi * 16 + g;
#pragma unroll
        for (int ni = 0; ni < 4; ni++) {
            int gn = wn * 32 + ni * 8 + t4 * 2;
            float b0 = bias[gn], b1 = bias[gn + 1];
            dh_s[rl * 132 + gn]           = fmaxf(acc[mi][ni][0] + b0, 0.f);
            dh_s[rl * 132 + gn + 1]       = fmaxf(acc[mi][ni][1] + b1, 0.f);
            dh_s[(rl + 8) * 132 + gn]     = fmaxf(acc[mi][ni][2] + b0, 0.f);
            dh_s[(rl + 8) * 132 + gn + 1] = fmaxf(acc[mi][ni][3] + b1, 0.f);
        }
    }
    // load w2/b2
    for (int i = tid; i < 128 * 16; i += 256) w2s[(i >> 4) * 17 + (i & 15)] = w2[i];
    if (tid < 16) b2s[tid] = b2[tid];
    __syncthreads();

    // ---- dec2: [128 rows] x [16 cols], fp32 ----
    int c = tid & 15, rg = tid >> 4;   // rg 0..15, 8 rows each
    float accd[8];
#pragma unroll
    for (int i = 0; i < 8; i++) accd[i] = b2s[c];
    for (int k = 0; k < 128; k++) {
        float wv = w2s[k * 17 + c];
#pragma unroll
        for (int i = 0; i < 8; i++)
            accd[i] += dh_s[(rg * 8 + i) * 132 + k] * wv;
    }
    const long TOT = (long)BB * NTT * CTRLD;
#pragma unroll
    for (int i = 0; i < 8; i++) {
        long row = m0 + rg * 8 + i;
        float s = accd[i];
        if (c < CTRLD) out[row * CTRLD + c] = s;
        else {
            float sp = fmaxf(s, 0.f) + log1pf(expf(-fabsf(s)));
            out[TOT + row * CTRLD + (c - CTRLD)] = 0.9f * sp + 0.1f;
        }
    }
}

// ===================== flash self-attention (fp16 I/O, 2 CTAs/SM) =====================
#define SELF_SMEM (23040 * 4)

__global__ void __launch_bounds__(256, 2) flash_self_k(
    const unsigned short* __restrict__ qkvh, unsigned short* __restrict__ attnoh)
{
    extern __shared__ unsigned smu[];
    unsigned* Qs = smu;
    unsigned* Ks = smu + 4608;
    unsigned* Vs = smu + 9216;
    unsigned* Ps = smu + 13824;
    float*    red = (float*)(smu + 22528);

    const int b = blockIdx.z, h = blockIdx.y;
    const int m0 = blockIdx.x * 128;
    const unsigned short* base = qkvh + (long)b * NCC * 768;
    const unsigned short* qp = base + h * 64;
    const unsigned short* kp = base + 256 + h * 64;
    const unsigned short* vp = base + 512 + h * 64;

    const int tid = threadIdx.x, wid = tid >> 5, lane = tid & 31;
    const int g = lane >> 2, t4 = lane & 3;
    const int wm = wid & 1, wn = wid >> 1;
    const int c4h = (tid & 15) * 4, r0 = tid >> 4;

    const __half2 sc8 = __floats2half2_rn(0.125f, 0.125f);
#pragma unroll
    for (int p = 0; p < 8; p++) {
        int r = p * 16 + r0;
        uint2 u = *(const uint2*)(qp + (long)(m0 + r) * 768 + c4h);
        __half2 ha = __hmul2(*(__half2*)&u.x, sc8);
        __half2 hb = __hmul2(*(__half2*)&u.y, sc8);
        *(uint2*)&Qs[r * 36 + (c4h >> 1)] = make_uint2(*(unsigned*)&ha, *(unsigned*)&hb);
    }

    float l_run[4][2], acc_o[4][2][4];
#pragma unroll
    for (int mi = 0; mi < 4; mi++)
#pragma unroll
        for (int hf = 0; hf < 2; hf++) l_run[mi][hf] = 0.f;
#pragma unroll
    for (int mi = 0; mi < 4; mi++)
#pragma unroll
        for (int ni = 0; ni < 2; ni++)
#pragma unroll
            for (int c = 0; c < 4; c++) acc_o[mi][ni][c] = 0.f;

    for (int tk = 0; tk < 8; tk++) {
        __syncthreads();
#pragma unroll
        for (int p = 0; p < 8; p++) {
            int r = p * 16 + r0;
            *(uint2*)&Ks[r * 36 + (c4h >> 1)] =
                *(const uint2*)(kp + (long)(tk * 128 + r) * 768 + c4h);
        }
#pragma unroll
        for (int p = 0; p < 4; p++) {
            int q = p * 16 + r0;
            uint2 e = *(const uint2*)(vp + (long)(tk * 128 + 2 * q) * 768 + c4h);
            uint2 o = *(const uint2*)(vp + (long)(tk * 128 + 2 * q + 1) * 768 + c4h);
            *(uint4*)&Vs[q * 72 + c4h] = make_uint4(
                ilo(e.x, o.x), ihi(e.x, o.x), ilo(e.y, o.y), ihi(e.y, o.y));
        }
        __syncthreads();

        float s[4][4][4];
#pragma unroll
        for (int mi = 0; mi < 4; mi++)
#pragma unroll
            for (int ni = 0; ni < 4; ni++)
#pragma unroll
                for (int c = 0; c < 4; c++) s[mi][ni][c] = 0.f;
#pragma unroll
        for (int ks = 0; ks < 4; ks++) {
            int kb2 = ks * 8;
            unsigned af[4][4], bf[4][2];
#pragma unroll
            for (int mi = 0; mi < 4; mi++) {
                int ma = wm * 64 + mi * 16 + g;
                af[mi][0] = Qs[ma * 36 + kb2 + t4];
                af[mi][1] = Qs[(ma + 8) * 36 + kb2 + t4];
                af[mi][2] = Qs[ma * 36 + kb2 + t4 + 4];
                af[mi][3] = Qs[(ma + 8) * 36 + kb2 + t4 + 4];
            }
#pragma unroll
            for (int ni = 0; ni < 4; ni++) {
                int nb = wn * 32 + ni * 8 + g;
                bf[ni][0] = Ks[nb * 36 + kb2 + t4];
                bf[ni][1] = Ks[nb * 36 + kb2 + t4 + 4];
            }
#pragma unroll
            for (int mi = 0; mi < 4; mi++)
#pragma unroll
                for (int ni = 0; ni < 4; ni++)
                    mma16(s[mi][ni], af[mi], bf[ni]);
        }

#pragma unroll
        for (int mi = 0; mi < 4; mi++)
#pragma unroll
            for (int hf = 0; hf < 2; hf++) {
                float ls = 0.f;
#pragma unroll
                for (int ni = 0; ni < 4; ni++) {
                    float p0 = __expf(s[mi][ni][hf * 2]);
                    float p1 = __expf(s[mi][ni][hf * 2 + 1]);
                    s[mi][ni][hf * 2] = p0; s[mi][ni][hf * 2 + 1] = p1;
                    ls += p0 + p1;
                }
                ls += __shfl_xor_sync(0xffffffffu, ls, 1);
                ls += __shfl_xor_sync(0xffffffffu, ls, 2);
                if (t4 == 0) red[wn * 128 + wm * 64 + mi * 16 + hf * 8 + g] = ls;
            }
        __syncthreads();
#pragma unroll
        for (int mi = 0; mi < 4; mi++)
#pragma unroll
            for (int hf = 0; hf < 2; hf++) {
                int r = wm * 64 + mi * 16 + hf * 8 + g;
                l_run[mi][hf] += red[r] + red[128 + r] + red[256 + r] + red[384 + r];
            }
#pragma unroll
        for (int mi = 0; mi < 4; mi++) {
            int r = wm * 64 + mi * 16 + g;
#pragma unroll
            for (int ni = 0; ni < 4; ni++) {
                int c2 = wn * 16 + ni * 4 + t4;
                Ps[r * 68 + c2]       = h2p(s[mi][ni][0], s[mi][ni][1]);
                Ps[(r + 8) * 68 + c2] = h2p(s[mi][ni][2], s[mi][ni][3]);
            }
        }
        __syncthreads();

#pragma unroll
        for (int ks = 0; ks < 8; ks++) {
            int kb2 = ks * 8;
            unsigned af[4][4], bf[2][2];
#pragma unroll
            for (int mi = 0; mi < 4; mi++) {
                int ma = wm * 64 + mi * 16 + g;
                af[mi][0] = Ps[ma * 68 + kb2 + t4];
                af[mi][1] = Ps[(ma + 8) * 68 + kb2 + t4];
                af[mi][2] = Ps[ma * 68 + kb2 + t4 + 4];
                af[mi][3] = Ps[(ma + 8) * 68 + kb2 + t4 + 4];
            }
#pragma unroll
            for (int ni = 0; ni < 2; ni++) {
                int nb = wn * 16 + ni * 8 + g;
                bf[ni][0] = Vs[(kb2 + t4) * 72 + nb];
                bf[ni][1] = Vs[(kb2 + t4 + 4) * 72 + nb];
            }
#pragma unroll
            for (int mi = 0; mi < 4; mi++)
#pragma unroll
                for (int ni = 0; ni < 2; ni++)
                    mma16(acc_o[mi][ni], af[mi], bf[ni]);
        }
    }

#pragma unroll
    for (int mi = 0; mi < 4; mi++) {
        int row = m0 + wm * 64 + mi * 16 + g;
        float inv0 = 1.f / l_run[mi][0], inv1 = 1.f / l_run[mi][1];
#pragma unroll
        for (int ni = 0; ni < 2; ni++) {
            int col = h * 64 + wn * 16 + ni * 8 + t4 * 2;
            long o0 = ((long)b * NCC + row) * 256 + col;
            long o1 = ((long)b * NCC + row + 8) * 256 + col;
            *(unsigned*)&attnoh[o0] = h2p(acc_o[mi][ni][0] * inv0, acc_o[mi][ni][1] * inv0);
            *(unsigned*)&attnoh[o1] = h2p(acc_o[mi][ni][2] * inv1, acc_o[mi][ni][3] * inv1);
        }
    }
}

// ===================== flash cross-attention (fp16 I/O, 2 CTAs/SM) =====================
#define CROSS_SMEM (27904 * 4)

__global__ void __launch_bounds__(256, 2) flash_cross_k(
    const unsigned short* __restrict__ qth, const unsigned short* __restrict__ rep2h,
    unsigned short* __restrict__ deth)
{
    extern __shared__ unsigned smu[];
    unsigned* Qs  = smu;
    unsigned* KVs = smu + 8448;
    unsigned* Vsc = smu + 16896;
    unsigned* Psc = smu + 25344;
    float*    red = (float*)(smu + 27648);

    const int b = blockIdx.z;
    const int m0 = blockIdx.x * 64;
    const unsigned short* qb  = qth   + (long)b * NTT * 256;
    const unsigned short* kvb = rep2h + (long)b * NCC * 256;

    const int tid = threadIdx.x, wid = tid >> 5, lane = tid & 31;
    const int g = lane >> 2, t4 = lane & 3;
    const int wm = wid & 1, wn = wid >> 1;
    const int c4h = (tid & 63) * 4, r0 = tid >> 6;

    const __half2 sc16 = __floats2half2_rn(0.0625f, 0.0625f);
#pragma unroll
    for (int p = 0; p < 16; p++) {
        int r = p * 4 + r0;
        uint2 u = *(const uint2*)(qb + (long)(m0 + r) * 256 + c4h);
        __half2 ha = __hmul2(*(__half2*)&u.x, sc16);
        __half2 hb = __hmul2(*(__half2*)&u.y, sc16);
        *(uint2*)&Qs[r * 132 + (c4h >> 1)] = make_uint2(*(unsigned*)&ha, *(unsigned*)&hb);
    }

    float l_run[2][2], acc_o[2][8][4];
#pragma unroll
    for (int mi = 0; mi < 2; mi++)
#pragma unroll
        for (int hf = 0; hf < 2; hf++) l_run[mi][hf] = 0.f;
#pragma unroll
    for (int mi = 0; mi < 2; mi++)
#pragma unroll
        for (int ni = 0; ni < 8; ni++)
#pragma unroll
            for (int c = 0; c < 4; c++) acc_o[mi][ni][c] = 0.f;

    for (int tk = 0; tk < 16; tk++) {
        __syncthreads();
#pragma unroll
        for (int p = 0; p < 8; p++) {
            int q = p * 4 + r0;
            uint2 e = *(const uint2*)(kvb + (long)(tk * 64 + 2 * q) * 256 + c4h);
            uint2 o = *(const uint2*)(kvb + (long)(tk * 64 + 2 * q + 1) * 256 + c4h);
            *(uint2*)&KVs[(2 * q) * 132 + (c4h >> 1)]     = e;
            *(uint2*)&KVs[(2 * q + 1) * 132 + (c4h >> 1)] = o;
            *(uint4*)&Vsc[q * 264 + c4h] = make_uint4(
                ilo(e.x, o.x), ihi(e.x, o.x), ilo(e.y, o.y), ihi(e.y, o.y));
        }
        __syncthreads();

        float s[2][2][4];
#pragma unroll
        for (int mi = 0; mi < 2; mi++)
#pragma unroll
            for (int ni = 0; ni < 2; ni++)
#pragma unroll
                for (int c = 0; c < 4; c++) s[mi][ni][c] = 0.f;
#pragma unroll
        for (int ks = 0; ks < 16; ks++) {
            int kb2 = ks * 8;
            unsigned af[2][4], bf[2][2];
#pragma unroll
            for (int mi = 0; mi < 2; mi++) {
                int ma = wm * 32 + mi * 16 + g;
                af[mi][0] = Qs[ma * 132 + kb2 + t4];
                af[mi][1] = Qs[(ma + 8) * 132 + kb2 + t4];
                af[mi][2] = Qs[ma * 132 + kb2 + t4 + 4];
                af[mi][3] = Qs[(ma + 8) * 132 + kb2 + t4 + 4];
            }
#pragma unroll
            for (int ni = 0; ni < 2; ni++) {
                int nb = wn * 16 + ni * 8 + g;
                bf[ni][0] = KVs[nb * 132 + kb2 + t4];
                bf[ni][1] = KVs[nb * 132 + kb2 + t4 + 4];
            }
#pragma unroll
            for (int mi = 0; mi < 2; mi++)
#pragma unroll
                for (int ni = 0; ni < 2; ni++)
                    mma16(s[mi][ni], af[mi], bf[ni]);
        }

#pragma unroll
        for (int mi = 0; mi < 2; mi++)
#pragma unroll
            for (int hf = 0; hf < 2; hf++) {
                float ls = 0.f;
#pragma unroll
                for (int ni = 0; ni < 2; ni++) {
                    float p0 = __expf(s[mi][ni][hf * 2]);
                    float p1 = __expf(s[mi][ni][hf * 2 + 1]);
                    s[mi][ni][hf * 2] = p0; s[mi][ni][hf * 2 + 1] = p1;
                    ls += p0 + p1;
                }
                ls += __shfl_xor_sync(0xffffffffu, ls, 1);
                ls += __shfl_xor_sync(0xffffffffu, ls, 2);
                if (t4 == 0) red[wn * 64 + wm * 32 + mi * 16 + hf * 8 + g] = ls;
            }
        __syncthreads();
#pragma unroll
        for (int mi = 0; mi < 2; mi++)
#pragma unroll
            for (int hf = 0; hf < 2; hf++) {
                int r = wm * 32 + mi * 16 + hf * 8 + g;
                l_run[mi][hf] += red[r] + red[64 + r] + red[128 + r] + red[192 + r];
            }
#pragma unroll
        for (int mi = 0; mi < 2; mi++) {
            int r = wm * 32 + mi * 16 + g;
#pragma unroll
            for (int ni = 0; ni < 2; ni++) {
                int c2 = wn * 8 + ni * 4 + t4;
                Psc[r * 36 + c2]       = h2p(s[mi][ni][0], s[mi][ni][1]);
                Psc[(r + 8) * 36 + c2] = h2p(s[mi][ni][2], s[mi][ni][3]);
            }
        }
        __syncthreads();

#pragma unroll
        for (int ks = 0; ks < 4; ks++) {
            int kb2 = ks * 8;
            unsigned af[2][4], bf[8][2];
#pragma unroll
            for (int mi = 0; mi < 2; mi++) {
                int ma = wm * 32 + mi * 16 + g;
                af[mi][0] = Psc[ma * 36 + kb2 + t4];
                af[mi][1] = Psc[(ma + 8) * 36 + kb2 + t4];
                af[mi][2] = Psc[ma * 36 + kb2 + t4 + 4];
                af[mi][3] = Psc[(ma + 8) * 36 + kb2 + t4 + 4];
            }
#pragma unroll
            for (int ni = 0; ni < 8; ni++) {
                int nb = wn * 64 + ni * 8 + g;
                bf[ni][0] = Vsc[(kb2 + t4) * 264 + nb];
                bf[ni][1] = Vsc[(kb2 + t4 + 4) * 264 + nb];
            }
#pragma unroll
            for (int mi = 0; mi < 2; mi++)
#pragma unroll
                for (int ni = 0; ni < 8; ni++)
                    mma16(acc_o[mi][ni], af[mi], bf[ni]);
        }
    }

#pragma unroll
    for (int mi = 0; mi < 2; mi++) {
        int row = m0 + wm * 32 + mi * 16 + g;
        float inv0 = 1.f / l_run[mi][0], inv1 = 1.f / l_run[mi][1];
#pragma unroll
        for (int ni = 0; ni < 8; ni++) {
            int col = wn * 64 + ni * 8 + t4 * 2;
            long o0 = ((long)b * NTT + row) * 256 + col;
            long o1 = ((long)b * NTT + row + 8) * 256 + col;
            *(unsigned*)&deth[o0] = h2p(acc_o[mi][ni][0] * inv0, acc_o[mi][ni][1] * inv0);
            *(unsigned*)&deth[o1] = h2p(acc_o[mi][ni][2] * inv1, acc_o[mi][ni][3] * inv1);
        }
    }
}

// ===================== small kernels =====================

__global__ void mean1_k(const float* __restrict__ h, float* __restrict__ part)
{
    int b = blockIdx.x, ch = blockIdx.y, j = threadIdx.x * 4;
    const float* p = h + (long)b * NCC * RD + (long)ch * 32 * RD + j;
    float4 s = make_float4(0.f, 0.f, 0.f, 0.f);
#pragma unroll 4
    for (int n = 0; n < 32; n++) {
        float4 v = *(const float4*)(p + (long)n * RD);
        s.x += v.x; s.y += v.y; s.z += v.z; s.w += v.w;
    }
    *(float4*)&part[(long)(b * 32 + ch) * RD + j] = s;
}

__global__ void mean2_k(const float* __restrict__ part, float* __restrict__ out)
{
    int b = blockIdx.x, j = threadIdx.x;
    float s = 0.f;
#pragma unroll
    for (int c = 0; c < 32; c++) s += part[(long)(b * 32 + c) * RD + j];
    out[b * RD + j] = s * (1.f / NCC);
}

__global__ void latent_k(const float* __restrict__ hmean,
                         const float* __restrict__ pw, const float* __restrict__ pb,
                         const float* __restrict__ mw, const float* __restrict__ mb,
                         const float* __restrict__ sw, const float* __restrict__ sb,
                         const float* __restrict__ eps, float* __restrict__ z)
{
    __shared__ float h2s[LHD];
    int b = blockIdx.x, tid = threadIdx.x;
    if (tid < LHD) {
        float s = pb[tid];
        const float* hm = hmean + b * RD;
        for (int k = 0; k < RD; k++) s += hm[k] * pw[k * LHD + tid];
        h2s[tid] = s;
    }
    __syncthreads();
    float mu = mb[tid], ls = sb[tid];
    for (int k = 0; k < LHD; k++) {
        mu += h2s[k] * mw[k * RD + tid];
        ls += h2s[k] * sw[k * RD + tid];
    }
    float sig = 0.9f / (1.f + expf(-ls)) + 0.1f;
    z[b * RD + tid] = mu + sig * eps[b * RD + tid];
}

// residual + layernorm -> half output
__global__ void __launch_bounds__(256) ln_k(
    const float* __restrict__ x, const float* __restrict__ y,
    const float* __restrict__ g, const float* __restrict__ b,
    unsigned short* __restrict__ outh)
{
    int w = threadIdx.x >> 5, lane = threadIdx.x & 31;
    long row = (long)blockIdx.x * 8 + w;
    const float4* xr = (const float4*)(x + row * RD);
    const float4* yr = (const float4*)(y + row * RD);
    float4 a0 = xr[lane], a1 = xr[lane + 32];
    float4 c0 = yr[lane], c1 = yr[lane + 32];
    a0.x += c0.x; a0.y += c0.y; a0.z += c0.z; a0.w += c0.w;
    a1.x += c1.x; a1.y += c1.y; a1.z += c1.z; a1.w += c1.w;

    float sum = a0.x + a0.y + a0.z + a0.w + a1.x + a1.y + a1.z + a1.w;
#pragma unroll
    for (int o = 16; o; o >>= 1) sum += __shfl_xor_sync(0xffffffffu, sum, o);
    float mean = sum * (1.f / RD);

    float d0x = a0.x - mean, d0y = a0.y - mean, d0z = a0.z - mean, d0w = a0.w - mean;
    float d1x = a1.x - mean, d1y = a1.y - mean, d1z = a1.z - mean, d1w = a1.w - mean;
    float vs = d0x * d0x + d0y * d0y + d0z * d0z + d0w * d0w
             + d1x * d1x + d1y * d1y + d1z * d1z + d1w * d1w;
#pragma unroll
    for (int o = 16; o; o >>= 1) vs += __shfl_xor_sync(0xffffffffu, vs, o);
    float inv = rsqrtf(vs * (1.f / RD) + 1e-5f);

    float4 g0 = ((const float4*)g)[lane], g1 = ((const float4*)g)[lane + 32];
    float4 b0 = ((const float4*)b)[lane], b1 = ((const float4*)b)[lane + 32];
    uint2 u0 = make_uint2(h2p(d0x * inv * g0.x + b0.x, d0y * inv * g0.y + b0.y),
                          h2p(d0z * inv * g0.z + b0.z, d0w * inv * g0.w + b0.w));
    uint2 u1 = make_uint2(h2p(d1x * inv * g1.x + b1.x, d1y * inv * g1.y + b1.y),
                          h2p(d1z * inv * g1.z + b1.z, d1w * inv * g1.w + b1.w));
    ((uint2*)(outh + row * RD))[lane] = u0;
    ((uint2*)(outh + row * RD))[lane + 32] = u1;
}

// ===================== host side =====================

static void* symv(const void* s) { void* p = nullptr; cudaGetSymbolAddress(&p, s); return p; }

extern "C" void kernel_launch(void* const* d_in, const int* in_sizes, int n_in,
                              void* d_out, int out_size)
{
    const float* context_x = (const float*)d_in[0];
    const float* context_y = (const float*)d_in[1];
    const float* target_x  = (const float*)d_in[2];
    const float* pred_ctrl = (const float*)d_in[3];
    const float* eps       = (const float*)d_in[4];
    const float* ce_w1 = (const float*)d_in[5];  const float* ce_b1 = (const float*)d_in[6];
    const float* ce_w2 = (const float*)d_in[7];  const float* ce_b2 = (const float*)d_in[8];
    const float* sa_in_w = (const float*)d_in[9];  const float* sa_in_b = (const float*)d_in[10];
    const float* sa_out_w = (const float*)d_in[11]; const float* sa_out_b = (const float*)d_in[12];
    const float* sa_ln_g = (const float*)d_in[13];  const float* sa_ln_b = (const float*)d_in[14];
    const float* qp_w = (const float*)d_in[15]; const float* qp_b = (const float*)d_in[16];
    const float* le_w1 = (const float*)d_in[17]; const float* le_b1 = (const float*)d_in[18];
    const float* le_w2 = (const float*)d_in[19]; const float* le_b2 = (const float*)d_in[20];
    const float* le_pw = (const float*)d_in[21]; const float* le_pb = (const float*)d_in[22];
    const float* le_mw = (const float*)d_in[23]; const float* le_mb = (const float*)d_in[24];
    const float* le_sw = (const float*)d_in[25]; const float* le_sb = (const float*)d_in[26];
    const float* dec_w1 = (const float*)d_in[27]; const float* dec_b1 = (const float*)d_in[28];
    const float* dec_w2 = (const float*)d_in[29]; const float* dec_b2 = (const float*)d_in[30];
    float* out = (float*)d_out;

    unsigned short* h12h  = (unsigned short*)symv(g_h12h);
    float* rep   = (float*)symv(g_rep);
    float* hle   = (float*)symv(g_hle);
    float* part  = (float*)symv(g_part);
    float* hmean = (float*)symv(g_hmean);
    float* z     = (float*)symv(g_z);
    unsigned short* qkvh   = (unsigned short*)symv(g_qkvh);
    unsigned short* attnoh = (unsigned short*)symv(g_attnoh);
    float* oproj = (float*)symv(g_oproj);
    unsigned short* rep2h  = (unsigned short*)symv(g_rep2h);
    unsigned short* qth    = (unsigned short*)symv(g_qth);
    unsigned short* deth   = (unsigned short*)symv(g_deth);

    const int MC = BB * NCC;   // 16384
    const int MT = BB * NTT;   // 32768

    static cudaStream_t s2 = nullptr;
    static cudaEvent_t ev0 = nullptr, evA = nullptr, evB = nullptr, evC = nullptr;
    if (!s2) {
        cudaStreamCreateWithFlags(&s2, cudaStreamNonBlocking);
        cudaEventCreateWithFlags(&ev0, cudaEventDisableTiming);
        cudaEventCreateWithFlags(&evA, cudaEventDisableTiming);
        cudaEventCreateWithFlags(&evB, cudaEventDisableTiming);
        cudaEventCreateWithFlags(&evC, cudaEventDisableTiming);
    }

    cudaFuncSetAttribute(flash_self_k,  cudaFuncAttributeMaxDynamicSharedMemorySize, SELF_SMEM);
    cudaFuncSetAttribute(flash_cross_k, cudaFuncAttributeMaxDynamicSharedMemorySize, CROSS_SMEM);
    cudaFuncSetAttribute(dec_fused_k,   cudaFuncAttributeMaxDynamicSharedMemorySize, DEC_DSMEM);

    // legal fork: ev0 on capture stream BEFORE s2's first op
    cudaEventRecord(ev0, 0);
    cudaStreamWaitEvent(s2, ev0, 0);

    // qt (half out) on s2
    mma_gemm<32, 0, 0, 0, 1, 0><<<dim3(MT / 128, 2, 1), 256, 0, s2>>>(target_x, qp_w, qp_b, (float*)qth,
        MT, RD, GAPD, GAPD, RD, RD, 1.f, nullptr, nullptr, nullptr, nullptr, nullptr);
    cudaEventRecord(evC, s2);

    // merged MLP1 (le|ce) -> half
    mma_gemm<32, 1, 2, 1, 1, 0><<<dim3(MC / 128, 2, 1), 256>>>(nullptr, le_w1, le_b1, (float*)h12h,
        MC, 2 * HIDD, CIN, CIN, HIDD, 2 * HIDD, 1.f, context_y, context_x, nullptr,
        ce_w1, ce_b1);

    // fork: latent path on s2
    cudaEventRecord(evA, 0);
    cudaStreamWaitEvent(s2, evA, 0);
    mma_gemm<32, 0, 0, 0, 0, 1><<<dim3(MC / 128, 2, 1), 256, 0, s2>>>((const float*)h12h, le_w2, le_b2, hle,
        MC, RD, HIDD, 2 * HIDD, RD, RD, 1.f, nullptr, nullptr, nullptr, nullptr, nullptr);
    mean1_k<<<dim3(BB, 32), 64, 0, s2>>>(hle, part);
    mean2_k<<<BB, 256, 0, s2>>>(part, hmean);
    latent_k<<<BB, 256, 0, s2>>>(hmean, le_pw, le_pb, le_mw, le_mb, le_sw, le_sb, eps, z);
    cudaEventRecord(evB, s2);

    // deterministic path (A = ce half of h12h)
    mma_gemm<32, 0, 0, 0, 0, 1><<<dim3(MC / 128, 2, 1), 256>>>((const float*)(h12h + HIDD), ce_w2, ce_b2, rep,
        MC, RD, HIDD, 2 * HIDD, RD, RD, 1.f, nullptr, nullptr, nullptr, nullptr, nullptr);

    mma_gemm<32, 0, 0, 0, 1, 0><<<dim3(MC / 128, 6, 1), 256>>>(rep, sa_in_w, sa_in_b, (float*)qkvh,
        MC, 3 * RD, RD, RD, 3 * RD, 3 * RD, 1.f, nullptr, nullptr, nullptr, nullptr, nullptr);

    flash_self_k<<<dim3(NCC / 128, NHD, BB), 256, SELF_SMEM>>>(qkvh, attnoh);

    mma_gemm<32, 0, 0, 0, 0, 1><<<dim3(MC / 128, 2, 1), 256>>>((const float*)attnoh, sa_out_w, sa_out_b, oproj,
        MC, RD, RD, RD, RD, RD, 1.f, nullptr, nullptr, nullptr, nullptr, nullptr);
    ln_k<<<MC / 8, 256>>>(rep, oproj, sa_ln_g, sa_ln_b, rep2h);

    // cross attention (join qt)
    cudaStreamWaitEvent(0, evC, 0);
    flash_cross_k<<<dim3(NTT / 64, 1, BB), 256, CROSS_SMEM>>>(qth, rep2h, deth);

    // join latent path, then fused decoder
    cudaStreamWaitEvent(0, evB, 0);
    dec_fused_k<<<MT / 128, 256, DEC_DSMEM>>>(deth, z, target_x, pred_ctrl,
        dec_w1, dec_b1, dec_w2, dec_b2, out);
}

// round 12
// speedup vs baseline: 1.5076x; 1.5076x over previous
#include <cuda_runtime.h>
#include <cuda_fp16.h>
#include <math.h>

// ---- problem dims ----
#define BB 16
#define NCC 1024
#define NTT 2048
#define GAPD 128
#define CTRLD 8
#define RD 256
#define NHD 4
#define HDD 64
#define HIDD 128
#define LHD 192
#define CIN (CTRLD + GAPD)          // 136
#define DIN (2 * RD + GAPD + CTRLD) // 648

// ---- scratch ----
__device__ unsigned short g_h12h [BB * NCC * 2 * HIDD];
__device__ float g_rep  [BB * NCC * RD];
__device__ float g_hle  [BB * NCC * RD];
__device__ float g_part [BB * 32 * RD];
__device__ float g_hmean[BB * RD];
__device__ float g_z    [BB * RD];
__device__ unsigned short g_qkvh [BB * NCC * 3 * RD];
__device__ unsigned short g_attnoh[BB * NCC * RD];
__device__ float g_oproj[BB * NCC * RD];
__device__ unsigned short g_rep2h[BB * NCC * RD];
__device__ unsigned short g_qth  [(size_t)BB * NTT * RD];
__device__ unsigned short g_deth [(size_t)BB * NTT * RD];

// ===================== fp16 mma helpers =====================
__device__ __forceinline__ unsigned h2p(float a, float b) {
    __half2 h = __floats2half2_rn(a, b);
    return *reinterpret_cast<unsigned*>(&h);
}
__device__ __forceinline__ void mma16(float* d, const unsigned* a, const unsigned* b) {
    asm volatile(
        "mma.sync.aligned.m16n8k16.row.col.f32.f16.f16.f32 "
        "{%0,%1,%2,%3},{%4,%5,%6,%7},{%8,%9},{%0,%1,%2,%3};\n"
        : "+f"(d[0]), "+f"(d[1]), "+f"(d[2]), "+f"(d[3])
        : "r"(a[0]), "r"(a[1]), "r"(a[2]), "r"(a[3]), "r"(b[0]), "r"(b[1]));
}
__device__ __forceinline__ float4 ld_guard(const float* src, int gk, int K) {
    if (gk + 4 <= K) return *(const float4*)src;
    float4 v = make_float4(0.f, 0.f, 0.f, 0.f);
    if (gk     < K) v.x = src[0];
    if (gk + 1 < K) v.y = src[1];
    if (gk + 2 < K) v.z = src[2];
    if (gk + 3 < K) v.w = src[3];
    return v;
}
__device__ __forceinline__ unsigned ilo(unsigned a, unsigned b) { return __byte_perm(a, b, 0x5410); }
__device__ __forceinline__ unsigned ihi(unsigned a, unsigned b) { return __byte_perm(a, b, 0x7632); }

// ===================== fp16 GEMM (reg-pipelined), B = [K,N] row-major ====
#define XBM 128
#define XBK 32

// MODE 0: plain A. MODE 2: A = [cy | cx], K=CIN.
// HA 1: A is half (MODE 0 only). BMODE 1: B cols split B/B2. OUTH 1: C half.
template<int WNT, int ACT, int MODE, int BMODE, int OUTH, int HA>
__global__ void __launch_bounds__(256) mma_gemm(
    const float* __restrict__ A, const float* __restrict__ B,
    const float* __restrict__ bias, float* __restrict__ C,
    int M, int N, int K, int lda, int ldb, int ldc,
    float alpha,
    const float* __restrict__ zt, const float* __restrict__ txt,
    const float* __restrict__ pct,
    const float* __restrict__ B2, const float* __restrict__ bias2)
{
    constexpr int XBN_ = WNT * 4;
    constexpr int NI = WNT / 8;

    __shared__ unsigned As2[XBM][20];
    __shared__ unsigned Bs2[XBK / 2][XBN_ + 8];

    int tid = threadIdx.x;
    int wid = tid >> 5, lane = tid & 31;
    int g = lane >> 2, t4 = lane & 3;
    int wm = wid & 1, wn = wid >> 1;
    int m0 = blockIdx.x * XBM, n0 = blockIdx.y * XBN_;

    float acc[4][NI][4];
#pragma unroll
    for (int i = 0; i < 4; i++)
#pragma unroll
        for (int j = 0; j < NI; j++)
#pragma unroll
            for (int l = 0; l < 4; l++) acc[i][j][l] = 0.f;

    float4 ra[4]; uint2 rah[4];
    float4 rbE[2], rbO[2];
    constexpr int C4  = XBN_ / 4;
    constexpr int RP2 = 256 / C4;
    constexpr int ITS2 = (XBK / 2) / RP2;

    const int ac = (tid & 7) * 4;
    const int ar = tid >> 3;
    const int bc4 = tid % C4;
    const int brb = tid / C4;

    auto loadA = [&](int k0) {
        int gk = k0 + ac;
#pragma unroll
        for (int p = 0; p < 4; p++) {
            int gm = m0 + p * 32 + ar;
            if (MODE == 2) {
                const float* s;
                if (gk < CTRLD)    s = zt  + (long)gm * CTRLD + gk;
                else if (gk < CIN) s = txt + (long)gm * GAPD + (gk - CTRLD);
                else               s = nullptr;
                ra[p] = s ? *(const float4*)s : make_float4(0.f, 0.f, 0.f, 0.f);
            } else if (HA) {
                const unsigned short* Ah = (const unsigned short*)A;
                rah[p] = (gk + 4 <= K) ? *(const uint2*)(Ah + (long)gm * lda + gk)
                                       : make_uint2(0u, 0u);
            } else {
                ra[p] = ld_guard(A + (long)gm * lda + gk, gk, K);
            }
        }
    };
    auto loadB = [&](int k0) {
        int gn = n0 + bc4 * 4;
#pragma unroll
        for (int it = 0; it < ITS2; it++) {
            int kp = k0 + (it * RP2 + brb) * 2;
            if (BMODE == 1) {
                const float* base0 = (gn < HIDD) ? B : B2;
                int gq = (gn < HIDD) ? gn : gn - HIDD;
                rbE[it] = (kp     < K) ? *(const float4*)(base0 + (long)kp * ldb + gq)
                                       : make_float4(0.f, 0.f, 0.f, 0.f);
                rbO[it] = (kp + 1 < K) ? *(const float4*)(base0 + (long)(kp + 1) * ldb + gq)
                                       : make_float4(0.f, 0.f, 0.f, 0.f);
            } else {
                bool okn = (gn + 3 < N);
                rbE[it] = (kp     < K && okn) ? *(const float4*)(B + (long)kp * ldb + gn)
                                              : make_float4(0.f, 0.f, 0.f, 0.f);
                rbO[it] = (kp + 1 < K && okn) ? *(const float4*)(B + (long)(kp + 1) * ldb + gn)
                                              : make_float4(0.f, 0.f, 0.f, 0.f);
            }
        }
    };
    auto stsAB = [&]() {
#pragma unroll
        for (int p = 0; p < 4; p++) {
            if (HA && MODE == 0) {
                *(uint2*)&As2[p * 32 + ar][ac >> 1] = rah[p];
            } else {
                uint2 u = make_uint2(h2p(ra[p].x, ra[p].y), h2p(ra[p].z, ra[p].w));
                *(uint2*)&As2[p * 32 + ar][ac >> 1] = u;
            }
        }
#pragma unroll
        for (int it = 0; it < ITS2; it++) {
            uint4 u = make_uint4(h2p(rbE[it].x, rbO[it].x), h2p(rbE[it].y, rbO[it].y),
                                 h2p(rbE[it].z, rbO[it].z), h2p(rbE[it].w, rbO[it].w));
            *(uint4*)&Bs2[it * RP2 + brb][bc4 * 4] = u;
        }
    };

    int kT = (K + XBK - 1) / XBK;
    loadA(0); loadB(0);

    for (int t = 0; t < kT; t++) {
        stsAB();
        __syncthreads();
        if (t + 1 < kT) { loadA((t + 1) * XBK); loadB((t + 1) * XBK); }
#pragma unroll
        for (int ks = 0; ks < 2; ks++) {
            int kb2 = ks * 8;
            unsigned af[4][4], bf[NI][2];
#pragma unroll
            for (int mi = 0; mi < 4; mi++) {
                int ma = wm * 64 + mi * 16 + g;
                af[mi][0] = As2[ma    ][kb2 + t4];
                af[mi][1] = As2[ma + 8][kb2 + t4];
                af[mi][2] = As2[ma    ][kb2 + t4 + 4];
                af[mi][3] = As2[ma + 8][kb2 + t4 + 4];
            }
#pragma unroll
            for (int ni = 0; ni < NI; ni++) {
                int nb = wn * WNT + ni * 8 + g;
                bf[ni][0] = Bs2[kb2 + t4    ][nb];
                bf[ni][1] = Bs2[kb2 + t4 + 4][nb];
            }
#pragma unroll
            for (int mi = 0; mi < 4; mi++)
#pragma unroll
                for (int ni = 0; ni < NI; ni++)
                    mma16(acc[mi][ni], af[mi], bf[ni]);
        }
        __syncthreads();
    }

#pragma unroll
    for (int mi = 0; mi < 4; mi++) {
        int gm = m0 + wm * 64 + mi * 16 + g;
#pragma unroll
        for (int ni = 0; ni < NI; ni++) {
            int gn = n0 + wn * WNT + ni * 8 + t4 * 2;
            if (gn >= N) continue;
            float b0, b1;
            if (BMODE == 1) {
                const float* bp = (gn < HIDD) ? bias : bias2;
                int gq = (gn < HIDD) ? gn : gn - HIDD;
                b0 = bp[gq]; b1 = bp[gq + 1];
            } else {
                b0 = bias ? bias[gn] : 0.f;
                b1 = bias ? bias[gn + 1] : 0.f;
            }
            float v0 = acc[mi][ni][0] * alpha + b0;
            float v1 = acc[mi][ni][1] * alpha + b1;
            float v2 = acc[mi][ni][2] * alpha + b0;
            float v3 = acc[mi][ni][3] * alpha + b1;
            if (ACT == 1) {
                v0 = fmaxf(v0, 0.f); v1 = fmaxf(v1, 0.f);
                v2 = fmaxf(v2, 0.f); v3 = fmaxf(v3, 0.f);
            }
            if (OUTH) {
                unsigned short* Ch = (unsigned short*)C;
                *(unsigned*)&Ch[(long)gm * ldc + gn]       = h2p(v0, v1);
                *(unsigned*)&Ch[(long)(gm + 8) * ldc + gn] = h2p(v2, v3);
            } else {
                *(float2*)&C[(long)gm * ldc + gn]       = make_float2(v0, v1);
                *(float2*)&C[(long)(gm + 8) * ldc + gn] = make_float2(v2, v3);
            }
        }
    }
}

// ===================== fused decoder: dec1 (K=648) + dec2 (128->16) + epilogue ====
#define DEC_DSMEM ((128 * 132 + 128 * 17 + 16) * 4)

__global__ void __launch_bounds__(256) dec_fused_k(
    const unsigned short* __restrict__ deth, const float* __restrict__ zt,
    const float* __restrict__ txt, const float* __restrict__ pct,
    const float* __restrict__ B, const float* __restrict__ bias,
    const float* __restrict__ w2, const float* __restrict__ b2,
    float* __restrict__ out)
{
    extern __shared__ float dsm[];
    float* dh_s = dsm;                     // [128][132]
    float* w2s  = dsm + 128 * 132;         // [128][17]
    float* b2s  = w2s + 128 * 17;          // [16]

    __shared__ unsigned As2[XBM][20];
    __shared__ unsigned Bs2[XBK / 2][136];

    const int K = DIN, ldb = HIDD;
    int tid = threadIdx.x;
    int wid = tid >> 5, lane = tid & 31;
    int g = lane >> 2, t4 = lane & 3;
    int wm = wid & 1, wn = wid >> 1;
    int m0 = blockIdx.x * XBM;

    float acc[4][4][4];
#pragma unroll
    for (int i = 0; i < 4; i++)
#pragma unroll
        for (int j = 0; j < 4; j++)
#pragma unroll
            for (int l = 0; l < 4; l++) acc[i][j][l] = 0.f;

    float4 ra[4]; uint2 rah[4];
    float4 rbE[2], rbO[2];
    const int ac = (tid & 7) * 4;
    const int ar = tid >> 3;
    const int bc4 = tid & 31;      // C4 = 32
    const int brb = tid >> 5;      // RP2 = 8

    auto loadA = [&](int k0) {
        int gk = k0 + ac;
#pragma unroll
        for (int p = 0; p < 4; p++) {
            int gm = m0 + p * 32 + ar;
            if (gk < RD) {
                rah[p] = *(const uint2*)(deth + (long)gm * RD + gk);
            } else {
                const float* s;
                if (gk < 2 * RD)             s = zt  + (long)(gm >> 11) * RD + (gk - RD);
                else if (gk < 2 * RD + GAPD) s = txt + (long)gm * GAPD + (gk - 2 * RD);
                else if (gk < DIN)           s = pct + (long)gm * CTRLD + (gk - 2 * RD - GAPD);
                else                         s = nullptr;
                ra[p] = s ? *(const float4*)s : make_float4(0.f, 0.f, 0.f, 0.f);
            }
        }
    };
    auto loadB = [&](int k0) {
#pragma unroll
        for (int it = 0; it < 2; it++) {
            int kp = k0 + (it * 8 + brb) * 2;
            rbE[it] = (kp     < K) ? *(const float4*)(B + (long)kp * ldb + bc4 * 4)
                                   : make_float4(0.f, 0.f, 0.f, 0.f);
            rbO[it] = (kp + 1 < K) ? *(const float4*)(B + (long)(kp + 1) * ldb + bc4 * 4)
                                   : make_float4(0.f, 0.f, 0.f, 0.f);
        }
    };
    auto stsAB = [&](int k0) {
        int gk = k0 + ac;
#pragma unroll
        for (int p = 0; p < 4; p++) {
            if (gk < RD) {
                *(uint2*)&As2[p * 32 + ar][ac >> 1] = rah[p];
            } else {
                uint2 u = make_uint2(h2p(ra[p].x, ra[p].y), h2p(ra[p].z, ra[p].w));
                *(uint2*)&As2[p * 32 + ar][ac >> 1] = u;
            }
        }
#pragma unroll
        for (int it = 0; it < 2; it++) {
            uint4 u = make_uint4(h2p(rbE[it].x, rbO[it].x), h2p(rbE[it].y, rbO[it].y),
                                 h2p(rbE[it].z, rbO[it].z), h2p(rbE[it].w, rbO[it].w));
            *(uint4*)&Bs2[it * 8 + brb][bc4 * 4] = u;
        }
    };

    int kT = (K + XBK - 1) / XBK;   // 21
    loadA(0); loadB(0);

    for (int t = 0; t < kT; t++) {
        stsAB(t * XBK);
        __syncthreads();
        if (t + 1 < kT) { loadA((t + 1) * XBK); loadB((t + 1) * XBK); }
#pragma unroll
        for (int ks = 0; ks < 2; ks++) {
            int kb2 = ks * 8;
            unsigned af[4][4], bf[4][2];
#pragma unroll
            for (int mi = 0; mi < 4; mi++) {
                int ma = wm * 64 + mi * 16 + g;
                af[mi][0] = As2[ma    ][kb2 + t4];
                af[mi][1] = As2[ma + 8][kb2 + t4];
                af[mi][2] = As2[ma    ][kb2 + t4 + 4];
                af[mi][3] = As2[ma + 8][kb2 + t4 + 4];
            }
#pragma unroll
            for (int ni = 0; ni < 4; ni++) {
                int nb = wn * 32 + ni * 8 + g;
                bf[ni][0] = Bs2[kb2 + t4    ][nb];
                bf[ni][1] = Bs2[kb2 + t4 + 4][nb];
            }
#pragma unroll
            for (int mi = 0; mi < 4; mi++)
#pragma unroll
                for (int ni = 0; ni < 4; ni++)
                    mma16(acc[mi][ni], af[mi], bf[ni]);
        }
        __syncthreads();
    }

    // dec1 epilogue into smem (bias + ReLU), fp32
#pragma unroll
    for (int mi = 0; mi < 4; mi++) {
        int rl = wm * 64 + mi * 16 + g;
#pragma unroll
        for (int ni = 0; ni < 4; ni++) {
            int gn = wn * 32 + ni * 8 + t4 * 2;
            float b0 = bias[gn], b1 = bias[gn + 1];
            dh_s[rl * 132 + gn]           = fmaxf(acc[mi][ni][0] + b0, 0.f);
            dh_s[rl * 132 + gn + 1]       = fmaxf(acc[mi][ni][1] + b1, 0.f);
            dh_s[(rl + 8) * 132 + gn]     = fmaxf(acc[mi][ni][2] + b0, 0.f);
            dh_s[(rl + 8) * 132 + gn + 1] = fmaxf(acc[mi][ni][3] + b1, 0.f);
        }
    }
    for (int i = tid; i < 128 * 16; i += 256) w2s[(i >> 4) * 17 + (i & 15)] = w2[i];
    if (tid < 16) b2s[tid] = b2[tid];
    __syncthreads();

    // dec2: [128 rows] x [16 cols], fp32
    int c = tid & 15, rg = tid >> 4;
    float accd[8];
#pragma unroll
    for (int i = 0; i < 8; i++) accd[i] = b2s[c];
    for (int k = 0; k < 128; k++) {
        float wv = w2s[k * 17 + c];
#pragma unroll
        for (int i = 0; i < 8; i++)
            accd[i] += dh_s[(rg * 8 + i) * 132 + k] * wv;
    }
    const long TOT = (long)BB * NTT * CTRLD;
#pragma unroll
    for (int i = 0; i < 8; i++) {
        long row = m0 + rg * 8 + i;
        float s = accd[i];
        if (c < CTRLD) out[row * CTRLD + c] = s;
        else {
            float sp = fmaxf(s, 0.f) + log1pf(expf(-fabsf(s)));
            out[TOT + row * CTRLD + (c - CTRLD)] = 0.9f * sp + 0.1f;
        }
    }
}

// ===================== flash self-attention (fp16 I/O, 2 CTAs/SM) =====================
#define SELF_SMEM (23040 * 4)

__global__ void __launch_bounds__(256, 2) flash_self_k(
    const unsigned short* __restrict__ qkvh, unsigned short* __restrict__ attnoh)
{
    extern __shared__ unsigned smu[];
    unsigned* Qs = smu;
    unsigned* Ks = smu + 4608;
    unsigned* Vs = smu + 9216;
    unsigned* Ps = smu + 13824;
    float*    red = (float*)(smu + 22528);

    const int b = blockIdx.z, h = blockIdx.y;
    const int m0 = blockIdx.x * 128;
    const unsigned short* base = qkvh + (long)b * NCC * 768;
    const unsigned short* qp = base + h * 64;
    const unsigned short* kp = base + 256 + h * 64;
    const unsigned short* vp = base + 512 + h * 64;

    const int tid = threadIdx.x, wid = tid >> 5, lane = tid & 31;
    const int g = lane >> 2, t4 = lane & 3;
    const int wm = wid & 1, wn = wid >> 1;
    const int c4h = (tid & 15) * 4, r0 = tid >> 4;

    const __half2 sc8 = __floats2half2_rn(0.125f, 0.125f);
#pragma unroll
    for (int p = 0; p < 8; p++) {
        int r = p * 16 + r0;
        uint2 u = *(const uint2*)(qp + (long)(m0 + r) * 768 + c4h);
        __half2 ha = __hmul2(*(__half2*)&u.x, sc8);
        __half2 hb = __hmul2(*(__half2*)&u.y, sc8);
        *(uint2*)&Qs[r * 36 + (c4h >> 1)] = make_uint2(*(unsigned*)&ha, *(unsigned*)&hb);
    }

    float l_run[4][2], acc_o[4][2][4];
#pragma unroll
    for (int mi = 0; mi < 4; mi++)
#pragma unroll
        for (int hf = 0; hf < 2; hf++) l_run[mi][hf] = 0.f;
#pragma unroll
    for (int mi = 0; mi < 4; mi++)
#pragma unroll
        for (int ni = 0; ni < 2; ni++)
#pragma unroll
            for (int c = 0; c < 4; c++) acc_o[mi][ni][c] = 0.f;

    for (int tk = 0; tk < 8; tk++) {
        __syncthreads();
#pragma unroll
        for (int p = 0; p < 8; p++) {
            int r = p * 16 + r0;
            *(uint2*)&Ks[r * 36 + (c4h >> 1)] =
                *(const uint2*)(kp + (long)(tk * 128 + r) * 768 + c4h);
        }
#pragma unroll
        for (int p = 0; p < 4; p++) {
            int q = p * 16 + r0;
            uint2 e = *(const uint2*)(vp + (long)(tk * 128 + 2 * q) * 768 + c4h);
            uint2 o = *(const uint2*)(vp + (long)(tk * 128 + 2 * q + 1) * 768 + c4h);
            *(uint4*)&Vs[q * 72 + c4h] = make_uint4(
                ilo(e.x, o.x), ihi(e.x, o.x), ilo(e.y, o.y), ihi(e.y, o.y));
        }
        __syncthreads();

        float s[4][4][4];
#pragma unroll
        for (int mi = 0; mi < 4; mi++)
#pragma unroll
            for (int ni = 0; ni < 4; ni++)
#pragma unroll
                for (int c = 0; c < 4; c++) s[mi][ni][c] = 0.f;
#pragma unroll
        for (int ks = 0; ks < 4; ks++) {
            int kb2 = ks * 8;
            unsigned af[4][4], bf[4][2];
#pragma unroll
            for (int mi = 0; mi < 4; mi++) {
                int ma = wm * 64 + mi * 16 + g;
                af[mi][0] = Qs[ma * 36 + kb2 + t4];
                af[mi][1] = Qs[(ma + 8) * 36 + kb2 + t4];
                af[mi][2] = Qs[ma * 36 + kb2 + t4 + 4];
                af[mi][3] = Qs[(ma + 8) * 36 + kb2 + t4 + 4];
            }
#pragma unroll
            for (int ni = 0; ni < 4; ni++) {
                int nb = wn * 32 + ni * 8 + g;
                bf[ni][0] = Ks[nb * 36 + kb2 + t4];
                bf[ni][1] = Ks[nb * 36 + kb2 + t4 + 4];
            }
#pragma unroll
            for (int mi = 0; mi < 4; mi++)
#pragma unroll
                for (int ni = 0; ni < 4; ni++)
                    mma16(s[mi][ni], af[mi], bf[ni]);
        }

#pragma unroll
        for (int mi = 0; mi < 4; mi++)
#pragma unroll
            for (int hf = 0; hf < 2; hf++) {
                float ls = 0.f;
#pragma unroll
                for (int ni = 0; ni < 4; ni++) {
                    float p0 = __expf(s[mi][ni][hf * 2]);
                    float p1 = __expf(s[mi][ni][hf * 2 + 1]);
                    s[mi][ni][hf * 2] = p0; s[mi][ni][hf * 2 + 1] = p1;
                    ls += p0 + p1;
                }
                ls += __shfl_xor_sync(0xffffffffu, ls, 1);
                ls += __shfl_xor_sync(0xffffffffu, ls, 2);
                if (t4 == 0) red[wn * 128 + wm * 64 + mi * 16 + hf * 8 + g] = ls;
            }
        __syncthreads();
#pragma unroll
        for (int mi = 0; mi < 4; mi++)
#pragma unroll
            for (int hf = 0; hf < 2; hf++) {
                int r = wm * 64 + mi * 16 + hf * 8 + g;
                l_run[mi][hf] += red[r] + red[128 + r] + red[256 + r] + red[384 + r];
            }
#pragma unroll
        for (int mi = 0; mi < 4; mi++) {
            int r = wm * 64 + mi * 16 + g;
#pragma unroll
            for (int ni = 0; ni < 4; ni++) {
                int c2 = wn * 16 + ni * 4 + t4;
                Ps[r * 68 + c2]       = h2p(s[mi][ni][0], s[mi][ni][1]);
                Ps[(r + 8) * 68 + c2] = h2p(s[mi][ni][2], s[mi][ni][3]);
            }
        }
        __syncthreads();

#pragma unroll
        for (int ks = 0; ks < 8; ks++) {
            int kb2 = ks * 8;
            unsigned af[4][4], bf[2][2];
#pragma unroll
            for (int mi = 0; mi < 4; mi++) {
                int ma = wm * 64 + mi * 16 + g;
                af[mi][0] = Ps[ma * 68 + kb2 + t4];
                af[mi][1] = Ps[(ma + 8) * 68 + kb2 + t4];
                af[mi][2] = Ps[ma * 68 + kb2 + t4 + 4];
                af[mi][3] = Ps[(ma + 8) * 68 + kb2 + t4 + 4];
            }
#pragma unroll
            for (int ni = 0; ni < 2; ni++) {
                int nb = wn * 16 + ni * 8 + g;
                bf[ni][0] = Vs[(kb2 + t4) * 72 + nb];
                bf[ni][1] = Vs[(kb2 + t4 + 4) * 72 + nb];
            }
#pragma unroll
            for (int mi = 0; mi < 4; mi++)
#pragma unroll
                for (int ni = 0; ni < 2; ni++)
                    mma16(acc_o[mi][ni], af[mi], bf[ni]);
        }
    }

#pragma unroll
    for (int mi = 0; mi < 4; mi++) {
        int row = m0 + wm * 64 + mi * 16 + g;
        float inv0 = 1.f / l_run[mi][0], inv1 = 1.f / l_run[mi][1];
#pragma unroll
        for (int ni = 0; ni < 2; ni++) {
            int col = h * 64 + wn * 16 + ni * 8 + t4 * 2;
            long o0 = ((long)b * NCC + row) * 256 + col;
            long o1 = ((long)b * NCC + row + 8) * 256 + col;
            *(unsigned*)&attnoh[o0] = h2p(acc_o[mi][ni][0] * inv0, acc_o[mi][ni][1] * inv0);
            *(unsigned*)&attnoh[o1] = h2p(acc_o[mi][ni][2] * inv1, acc_o[mi][ni][3] * inv1);
        }
    }
}

// ===================== flash cross-attention (fp16 I/O, 2 CTAs/SM) =====================
#define CROSS_SMEM (27904 * 4)

__global__ void __launch_bounds__(256, 2) flash_cross_k(
    const unsigned short* __restrict__ qth, const unsigned short* __restrict__ rep2h,
    unsigned short* __restrict__ deth)
{
    extern __shared__ unsigned smu[];
    unsigned* Qs  = smu;
    unsigned* KVs = smu + 8448;
    unsigned* Vsc = smu + 16896;
    unsigned* Psc = smu + 25344;
    float*    red = (float*)(smu + 27648);

    const int b = blockIdx.z;
    const int m0 = blockIdx.x * 64;
    const unsigned short* qb  = qth   + (long)b * NTT * 256;
    const unsigned short* kvb = rep2h + (long)b * NCC * 256;

    const int tid = threadIdx.x, wid = tid >> 5, lane = tid & 31;
    const int g = lane >> 2, t4 = lane & 3;
    const int wm = wid & 1, wn = wid >> 1;
    const int c4h = (tid & 63) * 4, r0 = tid >> 6;

    const __half2 sc16 = __floats2half2_rn(0.0625f, 0.0625f);
#pragma unroll
    for (int p = 0; p < 16; p++) {
        int r = p * 4 + r0;
        uint2 u = *(const uint2*)(qb + (long)(m0 + r) * 256 + c4h);
        __half2 ha = __hmul2(*(__half2*)&u.x, sc16);
        __half2 hb = __hmul2(*(__half2*)&u.y, sc16);
        *(uint2*)&Qs[r * 132 + (c4h >> 1)] = make_uint2(*(unsigned*)&ha, *(unsigned*)&hb);
    }

    float l_run[2][2], acc_o[2][8][4];
#pragma unroll
    for (int mi = 0; mi < 2; mi++)
#pragma unroll
        for (int hf = 0; hf < 2; hf++) l_run[mi][hf] = 0.f;
#pragma unroll
    for (int mi = 0; mi < 2; mi++)
#pragma unroll
        for (int ni = 0; ni < 8; ni++)
#pragma unroll
            for (int c = 0; c < 4; c++) acc_o[mi][ni][c] = 0.f;

    for (int tk = 0; tk < 16; tk++) {
        __syncthreads();
#pragma unroll
        for (int p = 0; p < 8; p++) {
            int q = p * 4 + r0;
            uint2 e = *(const uint2*)(kvb + (long)(tk * 64 + 2 * q) * 256 + c4h);
            uint2 o = *(const uint2*)(kvb + (long)(tk * 64 + 2 * q + 1) * 256 + c4h);
            *(uint2*)&KVs[(2 * q) * 132 + (c4h >> 1)]     = e;
            *(uint2*)&KVs[(2 * q + 1) * 132 + (c4h >> 1)] = o;
            *(uint4*)&Vsc[q * 264 + c4h] = make_uint4(
                ilo(e.x, o.x), ihi(e.x, o.x), ilo(e.y, o.y), ihi(e.y, o.y));
        }
        __syncthreads();

        float s[2][2][4];
#pragma unroll
        for (int mi = 0; mi < 2; mi++)
#pragma unroll
            for (int ni = 0; ni < 2; ni++)
#pragma unroll
                for (int c = 0; c < 4; c++) s[mi][ni][c] = 0.f;
#pragma unroll
        for (int ks = 0; ks < 16; ks++) {
            int kb2 = ks * 8;
            unsigned af[2][4], bf[2][2];
#pragma unroll
            for (int mi = 0; mi < 2; mi++) {
                int ma = wm * 32 + mi * 16 + g;
                af[mi][0] = Qs[ma * 132 + kb2 + t4];
                af[mi][1] = Qs[(ma + 8) * 132 + kb2 + t4];
                af[mi][2] = Qs[ma * 132 + kb2 + t4 + 4];
                af[mi][3] = Qs[(ma + 8) * 132 + kb2 + t4 + 4];
            }
#pragma unroll
            for (int ni = 0; ni < 2; ni++) {
                int nb = wn * 16 + ni * 8 + g;
                bf[ni][0] = KVs[nb * 132 + kb2 + t4];
                bf[ni][1] = KVs[nb * 132 + kb2 + t4 + 4];
            }
#pragma unroll
            for (int mi = 0; mi < 2; mi++)
#pragma unroll
                for (int ni = 0; ni < 2; ni++)
                    mma16(s[mi][ni], af[mi], bf[ni]);
        }

#pragma unroll
        for (int mi = 0; mi < 2; mi++)
#pragma unroll
            for (int hf = 0; hf < 2; hf++) {
                float ls = 0.f;
#pragma unroll
                for (int ni = 0; ni < 2; ni++) {
                    float p0 = __expf(s[mi][ni][hf * 2]);
                    float p1 = __expf(s[mi][ni][hf * 2 + 1]);
                    s[mi][ni][hf * 2] = p0; s[mi][ni][hf * 2 + 1] = p1;
                    ls += p0 + p1;
                }
                ls += __shfl_xor_sync(0xffffffffu, ls, 1);
                ls += __shfl_xor_sync(0xffffffffu, ls, 2);
                if (t4 == 0) red[wn * 64 + wm * 32 + mi * 16 + hf * 8 + g] = ls;
            }
        __syncthreads();
#pragma unroll
        for (int mi = 0; mi < 2; mi++)
#pragma unroll
            for (int hf = 0; hf < 2; hf++) {
                int r = wm * 32 + mi * 16 + hf * 8 + g;
                l_run[mi][hf] += red[r] + red[64 + r] + red[128 + r] + red[192 + r];
            }
#pragma unroll
        for (int mi = 0; mi < 2; mi++) {
            int r = wm * 32 + mi * 16 + g;
#pragma unroll
            for (int ni = 0; ni < 2; ni++) {
                int c2 = wn * 8 + ni * 4 + t4;
                Psc[r * 36 + c2]       = h2p(s[mi][ni][0], s[mi][ni][1]);
                Psc[(r + 8) * 36 + c2] = h2p(s[mi][ni][2], s[mi][ni][3]);
            }
        }
        __syncthreads();

#pragma unroll
        for (int ks = 0; ks < 4; ks++) {
            int kb2 = ks * 8;
            unsigned af[2][4], bf[8][2];
#pragma unroll
            for (int mi = 0; mi < 2; mi++) {
                int ma = wm * 32 + mi * 16 + g;
                af[mi][0] = Psc[ma * 36 + kb2 + t4];
                af[mi][1] = Psc[(ma + 8) * 36 + kb2 + t4];
                af[mi][2] = Psc[ma * 36 + kb2 + t4 + 4];
                af[mi][3] = Psc[(ma + 8) * 36 + kb2 + t4 + 4];
            }
#pragma unroll
            for (int ni = 0; ni < 8; ni++) {
                int nb = wn * 64 + ni * 8 + g;
                bf[ni][0] = Vsc[(kb2 + t4) * 264 + nb];
                bf[ni][1] = Vsc[(kb2 + t4 + 4) * 264 + nb];
            }
#pragma unroll
            for (int mi = 0; mi < 2; mi++)
#pragma unroll
                for (int ni = 0; ni < 8; ni++)
                    mma16(acc_o[mi][ni], af[mi], bf[ni]);
        }
    }

#pragma unroll
    for (int mi = 0; mi < 2; mi++) {
        int row = m0 + wm * 32 + mi * 16 + g;
        float inv0 = 1.f / l_run[mi][0], inv1 = 1.f / l_run[mi][1];
#pragma unroll
        for (int ni = 0; ni < 8; ni++) {
            int col = wn * 64 + ni * 8 + t4 * 2;
            long o0 = ((long)b * NTT + row) * 256 + col;
            long o1 = ((long)b * NTT + row + 8) * 256 + col;
            *(unsigned*)&deth[o0] = h2p(acc_o[mi][ni][0] * inv0, acc_o[mi][ni][1] * inv0);
            *(unsigned*)&deth[o1] = h2p(acc_o[mi][ni][2] * inv1, acc_o[mi][ni][3] * inv1);
        }
    }
}

// ===================== small kernels =====================

__global__ void mean1_k(const float* __restrict__ h, float* __restrict__ part)
{
    int b = blockIdx.x, ch = blockIdx.y, j = threadIdx.x * 4;
    const float* p = h + (long)b * NCC * RD + (long)ch * 32 * RD + j;
    float4 s = make_float4(0.f, 0.f, 0.f, 0.f);
#pragma unroll 4
    for (int n = 0; n < 32; n++) {
        float4 v = *(const float4*)(p + (long)n * RD);
        s.x += v.x; s.y += v.y; s.z += v.z; s.w += v.w;
    }
    *(float4*)&part[(long)(b * 32 + ch) * RD + j] = s;
}

__global__ void mean2_k(const float* __restrict__ part, float* __restrict__ out)
{
    int b = blockIdx.x, j = threadIdx.x;
    float s = 0.f;
#pragma unroll
    for (int c = 0; c < 32; c++) s += part[(long)(b * 32 + c) * RD + j];
    out[b * RD + j] = s * (1.f / NCC);
}

__global__ void latent_k(const float* __restrict__ hmean,
                         const float* __restrict__ pw, const float* __restrict__ pb,
                         const float* __restrict__ mw, const float* __restrict__ mb,
                         const float* __restrict__ sw, const float* __restrict__ sb,
                         const float* __restrict__ eps, float* __restrict__ z)
{
    __shared__ float h2s[LHD];
    int b = blockIdx.x, tid = threadIdx.x;
    if (tid < LHD) {
        float s = pb[tid];
        const float* hm = hmean + b * RD;
        for (int k = 0; k < RD; k++) s += hm[k] * pw[k * LHD + tid];
        h2s[tid] = s;
    }
    __syncthreads();
    float mu = mb[tid], ls = sb[tid];
    for (int k = 0; k < LHD; k++) {
        mu += h2s[k] * mw[k * RD + tid];
        ls += h2s[k] * sw[k * RD + tid];
    }
    float sig = 0.9f / (1.f + expf(-ls)) + 0.1f;
    z[b * RD + tid] = mu + sig * eps[b * RD + tid];
}

// residual + layernorm -> half output
__global__ void __launch_bounds__(256) ln_k(
    const float* __restrict__ x, const float* __restrict__ y,
    const float* __restrict__ g, const float* __restrict__ b,
    unsigned short* __restrict__ outh)
{
    int w = threadIdx.x >> 5, lane = threadIdx.x & 31;
    long row = (long)blockIdx.x * 8 + w;
    const float4* xr = (const float4*)(x + row * RD);
    const float4* yr = (const float4*)(y + row * RD);
    float4 a0 = xr[lane], a1 = xr[lane + 32];
    float4 c0 = yr[lane], c1 = yr[lane + 32];
    a0.x += c0.x; a0.y += c0.y; a0.z += c0.z; a0.w += c0.w;
    a1.x += c1.x; a1.y += c1.y; a1.z += c1.z; a1.w += c1.w;

    float sum = a0.x + a0.y + a0.z + a0.w + a1.x + a1.y + a1.z + a1.w;
#pragma unroll
    for (int o = 16; o; o >>= 1) sum += __shfl_xor_sync(0xffffffffu, sum, o);
    float mean = sum * (1.f / RD);

    float d0x = a0.x - mean, d0y = a0.y - mean, d0z = a0.z - mean, d0w = a0.w - mean;
    float d1x = a1.x - mean, d1y = a1.y - mean, d1z = a1.z - mean, d1w = a1.w - mean;
    float vs = d0x * d0x + d0y * d0y + d0z * d0z + d0w * d0w
             + d1x * d1x + d1y * d1y + d1z * d1z + d1w * d1w;
#pragma unroll
    for (int o = 16; o; o >>= 1) vs += __shfl_xor_sync(0xffffffffu, vs, o);
    float inv = rsqrtf(vs * (1.f / RD) + 1e-5f);

    float4 g0 = ((const float4*)g)[lane], g1 = ((const float4*)g)[lane + 32];
    float4 b0 = ((const float4*)b)[lane], b1 = ((const float4*)b)[lane + 32];
    uint2 u0 = make_uint2(h2p(d0x * inv * g0.x + b0.x, d0y * inv * g0.y + b0.y),
                          h2p(d0z * inv * g0.z + b0.z, d0w * inv * g0.w + b0.w));
    uint2 u1 = make_uint2(h2p(d1x * inv * g1.x + b1.x, d1y * inv * g1.y + b1.y),
                          h2p(d1z * inv * g1.z + b1.z, d1w * inv * g1.w + b1.w));
    ((uint2*)(outh + row * RD))[lane] = u0;
    ((uint2*)(outh + row * RD))[lane + 32] = u1;
}

// ===================== host side =====================

static void* symv(const void* s) { void* p = nullptr; cudaGetSymbolAddress(&p, s); return p; }

extern "C" void kernel_launch(void* const* d_in, const int* in_sizes, int n_in,
                              void* d_out, int out_size)
{
    const float* context_x = (const float*)d_in[0];
    const float* context_y = (const float*)d_in[1];
    const float* target_x  = (const float*)d_in[2];
    const float* pred_ctrl = (const float*)d_in[3];
    const float* eps       = (const float*)d_in[4];
    const float* ce_w1 = (const float*)d_in[5];  const float* ce_b1 = (const float*)d_in[6];
    const float* ce_w2 = (const float*)d_in[7];  const float* ce_b2 = (const float*)d_in[8];
    const float* sa_in_w = (const float*)d_in[9];  const float* sa_in_b = (const float*)d_in[10];
    const float* sa_out_w = (const float*)d_in[11]; const float* sa_out_b = (const float*)d_in[12];
    const float* sa_ln_g = (const float*)d_in[13];  const float* sa_ln_b = (const float*)d_in[14];
    const float* qp_w = (const float*)d_in[15]; const float* qp_b = (const float*)d_in[16];
    const float* le_w1 = (const float*)d_in[17]; const float* le_b1 = (const float*)d_in[18];
    const float* le_w2 = (const float*)d_in[19]; const float* le_b2 = (const float*)d_in[20];
    const float* le_pw = (const float*)d_in[21]; const float* le_pb = (const float*)d_in[22];
    const float* le_mw = (const float*)d_in[23]; const float* le_mb = (const float*)d_in[24];
    const float* le_sw = (const float*)d_in[25]; const float* le_sb = (const float*)d_in[26];
    const float* dec_w1 = (const float*)d_in[27]; const float* dec_b1 = (const float*)d_in[28];
    const float* dec_w2 = (const float*)d_in[29]; const float* dec_b2 = (const float*)d_in[30];
    float* out = (float*)d_out;

    unsigned short* h12h  = (unsigned short*)symv(g_h12h);
    float* rep   = (float*)symv(g_rep);
    float* hle   = (float*)symv(g_hle);
    float* part  = (float*)symv(g_part);
    float* hmean = (float*)symv(g_hmean);
    float* z     = (float*)symv(g_z);
    unsigned short* qkvh   = (unsigned short*)symv(g_qkvh);
    unsigned short* attnoh = (unsigned short*)symv(g_attnoh);
    float* oproj = (float*)symv(g_oproj);
    unsigned short* rep2h  = (unsigned short*)symv(g_rep2h);
    unsigned short* qth    = (unsigned short*)symv(g_qth);
    unsigned short* deth   = (unsigned short*)symv(g_deth);

    const int MC = BB * NCC;   // 16384
    const int MT = BB * NTT;   // 32768

    static cudaStream_t s2 = nullptr;
    static cudaEvent_t ev0 = nullptr, evA = nullptr, evB = nullptr, evC = nullptr;
    if (!s2) {
        cudaStreamCreateWithFlags(&s2, cudaStreamNonBlocking);
        cudaEventCreateWithFlags(&ev0, cudaEventDisableTiming);
        cudaEventCreateWithFlags(&evA, cudaEventDisableTiming);
        cudaEventCreateWithFlags(&evB, cudaEventDisableTiming);
        cudaEventCreateWithFlags(&evC, cudaEventDisableTiming);
    }

    cudaFuncSetAttribute(flash_self_k,  cudaFuncAttributeMaxDynamicSharedMemorySize, SELF_SMEM);
    cudaFuncSetAttribute(flash_cross_k, cudaFuncAttributeMaxDynamicSharedMemorySize, CROSS_SMEM);
    cudaFuncSetAttribute(dec_fused_k,   cudaFuncAttributeMaxDynamicSharedMemorySize, DEC_DSMEM);

    // legal fork: ev0 on capture stream BEFORE s2's first op
    cudaEventRecord(ev0, 0);
    cudaStreamWaitEvent(s2, ev0, 0);

    // qt (half out) on s2
    mma_gemm<32, 0, 0, 0, 1, 0><<<dim3(MT / 128, 2, 1), 256, 0, s2>>>(target_x, qp_w, qp_b, (float*)qth,
        MT, RD, GAPD, GAPD, RD, RD, 1.f, nullptr, nullptr, nullptr, nullptr, nullptr);
    cudaEventRecord(evC, s2);

    // merged MLP1 (le|ce) -> half
    mma_gemm<32, 1, 2, 1, 1, 0><<<dim3(MC / 128, 2, 1), 256>>>(nullptr, le_w1, le_b1, (float*)h12h,
        MC, 2 * HIDD, CIN, CIN, HIDD, 2 * HIDD, 1.f, context_y, context_x, nullptr,
        ce_w1, ce_b1);

    // fork: latent path on s2
    cudaEventRecord(evA, 0);
    cudaStreamWaitEvent(s2, evA, 0);
    mma_gemm<32, 0, 0, 0, 0, 1><<<dim3(MC / 128, 2, 1), 256, 0, s2>>>((const float*)h12h, le_w2, le_b2, hle,
        MC, RD, HIDD, 2 * HIDD, RD, RD, 1.f, nullptr, nullptr, nullptr, nullptr, nullptr);
    mean1_k<<<dim3(BB, 32), 64, 0, s2>>>(hle, part);
    mean2_k<<<BB, 256, 0, s2>>>(part, hmean);
    latent_k<<<BB, 256, 0, s2>>>(hmean, le_pw, le_pb, le_mw, le_mb, le_sw, le_sb, eps, z);
    cudaEventRecord(evB, s2);

    // deterministic path (A = ce half of h12h)
    mma_gemm<32, 0, 0, 0, 0, 1><<<dim3(MC / 128, 2, 1), 256>>>((const float*)(h12h + HIDD), ce_w2, ce_b2, rep,
        MC, RD, HIDD, 2 * HIDD, RD, RD, 1.f, nullptr, nullptr, nullptr, nullptr, nullptr);

    mma_gemm<32, 0, 0, 0, 1, 0><<<dim3(MC / 128, 6, 1), 256>>>(rep, sa_in_w, sa_in_b, (float*)qkvh,
        MC, 3 * RD, RD, RD, 3 * RD, 3 * RD, 1.f, nullptr, nullptr, nullptr, nullptr, nullptr);

    flash_self_k<<<dim3(NCC / 128, NHD, BB), 256, SELF_SMEM>>>(qkvh, attnoh);

    mma_gemm<32, 0, 0, 0, 0, 1><<<dim3(MC / 128, 2, 1), 256>>>((const float*)attnoh, sa_out_w, sa_out_b, oproj,
        MC, RD, RD, RD, RD, RD, 1.f, nullptr, nullptr, nullptr, nullptr, nullptr);
    ln_k<<<MC / 8, 256>>>(rep, oproj, sa_ln_g, sa_ln_b, rep2h);

    // cross attention (join qt)
    cudaStreamWaitEvent(0, evC, 0);
    flash_cross_k<<<dim3(NTT / 64, 1, BB), 256, CROSS_SMEM>>>(qth, rep2h, deth);

    // join latent path, then fused decoder
    cudaStreamWaitEvent(0, evB, 0);
    dec_fused_k<<<MT / 128, 256, DEC_DSMEM>>>(deth, z, target_x, pred_ctrl,
        dec_w1, dec_b1, dec_w2, dec_b2, out);
}

// round 13
// speedup vs baseline: 1.5390x; 1.0208x over previous
#include <cuda_runtime.h>
#include <cuda_fp16.h>
#include <math.h>

// ---- problem dims ----
#define BB 16
#define NCC 1024
#define NTT 2048
#define GAPD 128
#define CTRLD 8
#define RD 256
#define NHD 4
#define HDD 64
#define HIDD 128
#define LHD 192
#define CIN (CTRLD + GAPD)          // 136
#define DIN (2 * RD + GAPD + CTRLD) // 648

// ---- scratch ----
__device__ unsigned short g_h12h [BB * NCC * 2 * HIDD];
__device__ float g_rep  [BB * NCC * RD];
__device__ float g_hle  [BB * NCC * RD];
__device__ float g_part [BB * 32 * RD];
__device__ float g_hmean[BB * RD];
__device__ float g_z    [BB * RD];
__device__ unsigned short g_qkvh [BB * NCC * 3 * RD];
__device__ unsigned short g_attnoh[BB * NCC * RD];
__device__ unsigned short g_rep2h[BB * NCC * RD];
__device__ unsigned short g_qth  [(size_t)BB * NTT * RD];
__device__ unsigned short g_deth [(size_t)BB * NTT * RD];
__device__ float g_dh   [BB * NTT * HIDD];

// ===================== fp16 mma helpers =====================
__device__ __forceinline__ unsigned h2p(float a, float b) {
    __half2 h = __floats2half2_rn(a, b);
    return *reinterpret_cast<unsigned*>(&h);
}
__device__ __forceinline__ void mma16(float* d, const unsigned* a, const unsigned* b) {
    asm volatile(
        "mma.sync.aligned.m16n8k16.row.col.f32.f16.f16.f32 "
        "{%0,%1,%2,%3},{%4,%5,%6,%7},{%8,%9},{%0,%1,%2,%3};\n"
        : "+f"(d[0]), "+f"(d[1]), "+f"(d[2]), "+f"(d[3])
        : "r"(a[0]), "r"(a[1]), "r"(a[2]), "r"(a[3]), "r"(b[0]), "r"(b[1]));
}
__device__ __forceinline__ float4 ld_guard(const float* src, int gk, int K) {
    if (gk + 4 <= K) return *(const float4*)src;
    float4 v = make_float4(0.f, 0.f, 0.f, 0.f);
    if (gk     < K) v.x = src[0];
    if (gk + 1 < K) v.y = src[1];
    if (gk + 2 < K) v.z = src[2];
    if (gk + 3 < K) v.w = src[3];
    return v;
}
__device__ __forceinline__ unsigned ilo(unsigned a, unsigned b) { return __byte_perm(a, b, 0x5410); }
__device__ __forceinline__ unsigned ihi(unsigned a, unsigned b) { return __byte_perm(a, b, 0x7632); }

// ===================== fp16 GEMM (reg-pipelined), B = [K,N] row-major ====
#define XBM 128
#define XBK 32

// MODE 0: plain A. MODE 1: A = [deth(half) | z | tx | pc], K=DIN. MODE 2: A = [cy | cx], K=CIN.
// HA 1: A is half (MODE 0). BMODE 1: B cols split B/B2. OUTH 1: C half.
template<int WNT, int ACT, int MODE, int BMODE, int OUTH, int HA>
__global__ void __launch_bounds__(256) mma_gemm(
    const float* __restrict__ A, const float* __restrict__ B,
    const float* __restrict__ bias, float* __restrict__ C,
    int M, int N, int K, int lda, int ldb, int ldc,
    float alpha,
    const float* __restrict__ zt, const float* __restrict__ txt,
    const float* __restrict__ pct,
    const float* __restrict__ B2, const float* __restrict__ bias2)
{
    constexpr int XBN_ = WNT * 4;
    constexpr int NI = WNT / 8;

    __shared__ unsigned As2[XBM][20];
    __shared__ unsigned Bs2[XBK / 2][XBN_ + 8];

    int tid = threadIdx.x;
    int wid = tid >> 5, lane = tid & 31;
    int g = lane >> 2, t4 = lane & 3;
    int wm = wid & 1, wn = wid >> 1;
    int m0 = blockIdx.x * XBM, n0 = blockIdx.y * XBN_;

    float acc[4][NI][4];
#pragma unroll
    for (int i = 0; i < 4; i++)
#pragma unroll
        for (int j = 0; j < NI; j++)
#pragma unroll
            for (int l = 0; l < 4; l++) acc[i][j][l] = 0.f;

    float4 ra[4]; uint2 rah[4];
    float4 rbE[2], rbO[2];
    constexpr int C4  = XBN_ / 4;
    constexpr int RP2 = 256 / C4;
    constexpr int ITS2 = (XBK / 2) / RP2;

    const int ac = (tid & 7) * 4;
    const int ar = tid >> 3;
    const int bc4 = tid % C4;
    const int brb = tid / C4;

    auto loadA = [&](int k0) {
        int gk = k0 + ac;
#pragma unroll
        for (int p = 0; p < 4; p++) {
            int gm = m0 + p * 32 + ar;
            if (MODE == 1) {
                if (gk < RD) {
                    rah[p] = *(const uint2*)((const unsigned short*)A + (long)gm * RD + gk);
                } else {
                    const float* s;
                    if (gk < 2 * RD)             s = zt  + (long)(gm >> 11) * RD + (gk - RD);
                    else if (gk < 2 * RD + GAPD) s = txt + (long)gm * GAPD + (gk - 2 * RD);
                    else if (gk < DIN)           s = pct + (long)gm * CTRLD + (gk - 2 * RD - GAPD);
                    else                         s = nullptr;
                    ra[p] = s ? *(const float4*)s : make_float4(0.f, 0.f, 0.f, 0.f);
                }
            } else if (MODE == 2) {
                const float* s;
                if (gk < CTRLD)    s = zt  + (long)gm * CTRLD + gk;
                else if (gk < CIN) s = txt + (long)gm * GAPD + (gk - CTRLD);
                else               s = nullptr;
                ra[p] = s ? *(const float4*)s : make_float4(0.f, 0.f, 0.f, 0.f);
            } else if (HA) {
                const unsigned short* Ah = (const unsigned short*)A;
                rah[p] = (gk + 4 <= K) ? *(const uint2*)(Ah + (long)gm * lda + gk)
                                       : make_uint2(0u, 0u);
            } else {
                ra[p] = ld_guard(A + (long)gm * lda + gk, gk, K);
            }
        }
    };
    auto loadB = [&](int k0) {
        int gn = n0 + bc4 * 4;
#pragma unroll
        for (int it = 0; it < ITS2; it++) {
            int kp = k0 + (it * RP2 + brb) * 2;
            if (BMODE == 1) {
                const float* base0 = (gn < HIDD) ? B : B2;
                int gq = (gn < HIDD) ? gn : gn - HIDD;
                rbE[it] = (kp     < K) ? *(const float4*)(base0 + (long)kp * ldb + gq)
                                       : make_float4(0.f, 0.f, 0.f, 0.f);
                rbO[it] = (kp + 1 < K) ? *(const float4*)(base0 + (long)(kp + 1) * ldb + gq)
                                       : make_float4(0.f, 0.f, 0.f, 0.f);
            } else {
                bool okn = (gn + 3 < N);
                rbE[it] = (kp     < K && okn) ? *(const float4*)(B + (long)kp * ldb + gn)
                                              : make_float4(0.f, 0.f, 0.f, 0.f);
                rbO[it] = (kp + 1 < K && okn) ? *(const float4*)(B + (long)(kp + 1) * ldb + gn)
                                              : make_float4(0.f, 0.f, 0.f, 0.f);
            }
        }
    };
    auto stsAB = [&](int k0) {
        int gk = k0 + ac;
#pragma unroll
        for (int p = 0; p < 4; p++) {
            if ((MODE == 1 && gk < RD) || (HA && MODE == 0)) {
                *(uint2*)&As2[p * 32 + ar][ac >> 1] = rah[p];
            } else {
                uint2 u = make_uint2(h2p(ra[p].x, ra[p].y), h2p(ra[p].z, ra[p].w));
                *(uint2*)&As2[p * 32 + ar][ac >> 1] = u;
            }
        }
#pragma unroll
        for (int it = 0; it < ITS2; it++) {
            uint4 u = make_uint4(h2p(rbE[it].x, rbO[it].x), h2p(rbE[it].y, rbO[it].y),
                                 h2p(rbE[it].z, rbO[it].z), h2p(rbE[it].w, rbO[it].w));
            *(uint4*)&Bs2[it * RP2 + brb][bc4 * 4] = u;
        }
    };

    int kT = (K + XBK - 1) / XBK;
    loadA(0); loadB(0);

    for (int t = 0; t < kT; t++) {
        stsAB(t * XBK);
        __syncthreads();
        if (t + 1 < kT) { loadA((t + 1) * XBK); loadB((t + 1) * XBK); }
#pragma unroll
        for (int ks = 0; ks < 2; ks++) {
            int kb2 = ks * 8;
            unsigned af[4][4], bf[NI][2];
#pragma unroll
            for (int mi = 0; mi < 4; mi++) {
                int ma = wm * 64 + mi * 16 + g;
                af[mi][0] = As2[ma    ][kb2 + t4];
                af[mi][1] = As2[ma + 8][kb2 + t4];
                af[mi][2] = As2[ma    ][kb2 + t4 + 4];
                af[mi][3] = As2[ma + 8][kb2 + t4 + 4];
            }
#pragma unroll
            for (int ni = 0; ni < NI; ni++) {
                int nb = wn * WNT + ni * 8 + g;
                bf[ni][0] = Bs2[kb2 + t4    ][nb];
                bf[ni][1] = Bs2[kb2 + t4 + 4][nb];
            }
#pragma unroll
            for (int mi = 0; mi < 4; mi++)
#pragma unroll
                for (int ni = 0; ni < NI; ni++)
                    mma16(acc[mi][ni], af[mi], bf[ni]);
        }
        __syncthreads();
    }

#pragma unroll
    for (int mi = 0; mi < 4; mi++) {
        int gm = m0 + wm * 64 + mi * 16 + g;
#pragma unroll
        for (int ni = 0; ni < NI; ni++) {
            int gn = n0 + wn * WNT + ni * 8 + t4 * 2;
            if (gn >= N) continue;
            float b0, b1;
            if (BMODE == 1) {
                const float* bp = (gn < HIDD) ? bias : bias2;
                int gq = (gn < HIDD) ? gn : gn - HIDD;
                b0 = bp[gq]; b1 = bp[gq + 1];
            } else {
                b0 = bias ? bias[gn] : 0.f;
                b1 = bias ? bias[gn + 1] : 0.f;
            }
            float v0 = acc[mi][ni][0] * alpha + b0;
            float v1 = acc[mi][ni][1] * alpha + b1;
            float v2 = acc[mi][ni][2] * alpha + b0;
            float v3 = acc[mi][ni][3] * alpha + b1;
            if (ACT == 1) {
                v0 = fmaxf(v0, 0.f); v1 = fmaxf(v1, 0.f);
                v2 = fmaxf(v2, 0.f); v3 = fmaxf(v3, 0.f);
            }
            if (OUTH) {
                unsigned short* Ch = (unsigned short*)C;
                *(unsigned*)&Ch[(long)gm * ldc + gn]       = h2p(v0, v1);
                *(unsigned*)&Ch[(long)(gm + 8) * ldc + gn] = h2p(v2, v3);
            } else {
                *(float2*)&C[(long)gm * ldc + gn]       = make_float2(v0, v1);
                *(float2*)&C[(long)(gm + 8) * ldc + gn] = make_float2(v2, v3);
            }
        }
    }
}

// ===================== fused oproj GEMM + residual + LayerNorm =====================
// 128x256 tile (full row), K=256. A = attnoh (half). Writes rep2h (half).
__global__ void __launch_bounds__(256) gemm_ln_k(
    const unsigned short* __restrict__ Ah, const float* __restrict__ B,
    const float* __restrict__ bias, const float* __restrict__ resid,
    const float* __restrict__ lng, const float* __restrict__ lnb,
    unsigned short* __restrict__ outh)
{
    __shared__ unsigned As2[128][20];
    __shared__ unsigned Bs2[16][264];
    __shared__ float red[512];

    const int K = RD;
    int tid = threadIdx.x;
    int wid = tid >> 5, lane = tid & 31;
    int g = lane >> 2, t4 = lane & 3;
    int wm = wid & 1, wn = wid >> 1;
    int m0 = blockIdx.x * 128;

    float acc[4][8][4];
#pragma unroll
    for (int i = 0; i < 4; i++)
#pragma unroll
        for (int j = 0; j < 8; j++)
#pragma unroll
            for (int l = 0; l < 4; l++) acc[i][j][l] = 0.f;

    uint2 rah[4];
    float4 rbE[4], rbO[4];
    const int ac = (tid & 7) * 4;
    const int ar = tid >> 3;
    const int bc4 = tid & 63;      // C4 = 64
    const int brb = tid >> 6;      // RP2 = 4

    auto loadA = [&](int k0) {
        int gk = k0 + ac;
#pragma unroll
        for (int p = 0; p < 4; p++)
            rah[p] = *(const uint2*)(Ah + (long)(m0 + p * 32 + ar) * RD + gk);
    };
    auto loadB = [&](int k0) {
#pragma unroll
        for (int it = 0; it < 4; it++) {
            int kp = k0 + (it * 4 + brb) * 2;
            rbE[it] = *(const float4*)(B + (long)kp * RD + bc4 * 4);
            rbO[it] = *(const float4*)(B + (long)(kp + 1) * RD + bc4 * 4);
        }
    };
    auto stsAB = [&]() {
#pragma unroll
        for (int p = 0; p < 4; p++)
            *(uint2*)&As2[p * 32 + ar][ac >> 1] = rah[p];
#pragma unroll
        for (int it = 0; it < 4; it++) {
            uint4 u = make_uint4(h2p(rbE[it].x, rbO[it].x), h2p(rbE[it].y, rbO[it].y),
                                 h2p(rbE[it].z, rbO[it].z), h2p(rbE[it].w, rbO[it].w));
            *(uint4*)&Bs2[it * 4 + brb][bc4 * 4] = u;
        }
    };

    loadA(0); loadB(0);
    for (int t = 0; t < K / XBK; t++) {
        stsAB();
        __syncthreads();
        if (t + 1 < K / XBK) { loadA((t + 1) * XBK); loadB((t + 1) * XBK); }
#pragma unroll
        for (int ks = 0; ks < 2; ks++) {
            int kb2 = ks * 8;
            unsigned af[4][4], bf[8][2];
#pragma unroll
            for (int mi = 0; mi < 4; mi++) {
                int ma = wm * 64 + mi * 16 + g;
                af[mi][0] = As2[ma    ][kb2 + t4];
                af[mi][1] = As2[ma + 8][kb2 + t4];
                af[mi][2] = As2[ma    ][kb2 + t4 + 4];
                af[mi][3] = As2[ma + 8][kb2 + t4 + 4];
            }
#pragma unroll
            for (int ni = 0; ni < 8; ni++) {
                int nb = wn * 64 + ni * 8 + g;
                bf[ni][0] = Bs2[kb2 + t4    ][nb];
                bf[ni][1] = Bs2[kb2 + t4 + 4][nb];
            }
#pragma unroll
            for (int mi = 0; mi < 4; mi++)
#pragma unroll
                for (int ni = 0; ni < 8; ni++)
                    mma16(acc[mi][ni], af[mi], bf[ni]);
        }
        __syncthreads();
    }

    // ---- v = acc + bias + resid ----
#pragma unroll
    for (int mi = 0; mi < 4; mi++) {
        int gr = m0 + wm * 64 + mi * 16 + g;
#pragma unroll
        for (int ni = 0; ni < 8; ni++) {
            int col = wn * 64 + ni * 8 + t4 * 2;
            float2 r0 = *(const float2*)&resid[(long)gr * RD + col];
            float2 r1 = *(const float2*)&resid[(long)(gr + 8) * RD + col];
            float b0 = bias[col], b1 = bias[col + 1];
            acc[mi][ni][0] += b0 + r0.x; acc[mi][ni][1] += b1 + r0.y;
            acc[mi][ni][2] += b0 + r1.x; acc[mi][ni][3] += b1 + r1.y;
        }
    }

    // ---- row mean ----
    float mean[4][2];
#pragma unroll
    for (int mi = 0; mi < 4; mi++)
#pragma unroll
        for (int hf = 0; hf < 2; hf++) {
            float s = 0.f;
#pragma unroll
            for (int ni = 0; ni < 8; ni++) s += acc[mi][ni][hf * 2] + acc[mi][ni][hf * 2 + 1];
            s += __shfl_xor_sync(0xffffffffu, s, 1);
            s += __shfl_xor_sync(0xffffffffu, s, 2);
            if (t4 == 0) red[wn * 128 + wm * 64 + mi * 16 + hf * 8 + g] = s;
        }
    __syncthreads();
#pragma unroll
    for (int mi = 0; mi < 4; mi++)
#pragma unroll
        for (int hf = 0; hf < 2; hf++) {
            int r = wm * 64 + mi * 16 + hf * 8 + g;
            mean[mi][hf] = (red[r] + red[128 + r] + red[256 + r] + red[384 + r]) * (1.f / RD);
        }
    __syncthreads();

    // ---- row var ----
    float inv[4][2];
#pragma unroll
    for (int mi = 0; mi < 4; mi++)
#pragma unroll
        for (int hf = 0; hf < 2; hf++) {
            float s = 0.f;
#pragma unroll
            for (int ni = 0; ni < 8; ni++) {
                float d0 = acc[mi][ni][hf * 2]     - mean[mi][hf];
                float d1 = acc[mi][ni][hf * 2 + 1] - mean[mi][hf];
                s += d0 * d0 + d1 * d1;
            }
            s += __shfl_xor_sync(0xffffffffu, s, 1);
            s += __shfl_xor_sync(0xffffffffu, s, 2);
            if (t4 == 0) red[wn * 128 + wm * 64 + mi * 16 + hf * 8 + g] = s;
        }
    __syncthreads();
#pragma unroll
    for (int mi = 0; mi < 4; mi++)
#pragma unroll
        for (int hf = 0; hf < 2; hf++) {
            int r = wm * 64 + mi * 16 + hf * 8 + g;
            float var = (red[r] + red[128 + r] + red[256 + r] + red[384 + r]) * (1.f / RD);
            inv[mi][hf] = rsqrtf(var + 1e-5f);
        }

    // ---- scale + store half ----
#pragma unroll
    for (int mi = 0; mi < 4; mi++) {
        int gr = m0 + wm * 64 + mi * 16 + g;
#pragma unroll
        for (int ni = 0; ni < 8; ni++) {
            int col = wn * 64 + ni * 8 + t4 * 2;
            float g0 = lng[col], g1 = lng[col + 1];
            float c0 = lnb[col], c1 = lnb[col + 1];
            float v0 = (acc[mi][ni][0] - mean[mi][0]) * inv[mi][0] * g0 + c0;
            float v1 = (acc[mi][ni][1] - mean[mi][0]) * inv[mi][0] * g1 + c1;
            float v2 = (acc[mi][ni][2] - mean[mi][1]) * inv[mi][1] * g0 + c0;
            float v3 = (acc[mi][ni][3] - mean[mi][1]) * inv[mi][1] * g1 + c1;
            *(unsigned*)&outh[(long)gr * RD + col]       = h2p(v0, v1);
            *(unsigned*)&outh[(long)(gr + 8) * RD + col] = h2p(v2, v3);
        }
    }
}

// ===================== flash self-attention (fp16 I/O, 2 CTAs/SM) =====================
#define SELF_SMEM (23040 * 4)

__global__ void __launch_bounds__(256, 2) flash_self_k(
    const unsigned short* __restrict__ qkvh, unsigned short* __restrict__ attnoh)
{
    extern __shared__ unsigned smu[];
    unsigned* Qs = smu;
    unsigned* Ks = smu + 4608;
    unsigned* Vs = smu + 9216;
    unsigned* Ps = smu + 13824;
    float*    red = (float*)(smu + 22528);

    const int b = blockIdx.z, h = blockIdx.y;
    const int m0 = blockIdx.x * 128;
    const unsigned short* base = qkvh + (long)b * NCC * 768;
    const unsigned short* qp = base + h * 64;
    const unsigned short* kp = base + 256 + h * 64;
    const unsigned short* vp = base + 512 + h * 64;

    const int tid = threadIdx.x, wid = tid >> 5, lane = tid & 31;
    const int g = lane >> 2, t4 = lane & 3;
    const int wm = wid & 1, wn = wid >> 1;
    const int c4h = (tid & 15) * 4, r0 = tid >> 4;

    const __half2 sc8 = __floats2half2_rn(0.125f, 0.125f);
#pragma unroll
    for (int p = 0; p < 8; p++) {
        int r = p * 16 + r0;
        uint2 u = *(const uint2*)(qp + (long)(m0 + r) * 768 + c4h);
        __half2 ha = __hmul2(*(__half2*)&u.x, sc8);
        __half2 hb = __hmul2(*(__half2*)&u.y, sc8);
        *(uint2*)&Qs[r * 36 + (c4h >> 1)] = make_uint2(*(unsigned*)&ha, *(unsigned*)&hb);
    }

    float l_run[4][2], acc_o[4][2][4];
#pragma unroll
    for (int mi = 0; mi < 4; mi++)
#pragma unroll
        for (int hf = 0; hf < 2; hf++) l_run[mi][hf] = 0.f;
#pragma unroll
    for (int mi = 0; mi < 4; mi++)
#pragma unroll
        for (int ni = 0; ni < 2; ni++)
#pragma unroll
            for (int c = 0; c < 4; c++) acc_o[mi][ni][c] = 0.f;

    for (int tk = 0; tk < 8; tk++) {
        __syncthreads();
#pragma unroll
        for (int p = 0; p < 8; p++) {
            int r = p * 16 + r0;
            *(uint2*)&Ks[r * 36 + (c4h >> 1)] =
                *(const uint2*)(kp + (long)(tk * 128 + r) * 768 + c4h);
        }
#pragma unroll
        for (int p = 0; p < 4; p++) {
            int q = p * 16 + r0;
            uint2 e = *(const uint2*)(vp + (long)(tk * 128 + 2 * q) * 768 + c4h);
            uint2 o = *(const uint2*)(vp + (long)(tk * 128 + 2 * q + 1) * 768 + c4h);
            *(uint4*)&Vs[q * 72 + c4h] = make_uint4(
                ilo(e.x, o.x), ihi(e.x, o.x), ilo(e.y, o.y), ihi(e.y, o.y));
        }
        __syncthreads();

        float s[4][4][4];
#pragma unroll
        for (int mi = 0; mi < 4; mi++)
#pragma unroll
            for (int ni = 0; ni < 4; ni++)
#pragma unroll
                for (int c = 0; c < 4; c++) s[mi][ni][c] = 0.f;
#pragma unroll
        for (int ks = 0; ks < 4; ks++) {
            int kb2 = ks * 8;
            unsigned af[4][4], bf[4][2];
#pragma unroll
            for (int mi = 0; mi < 4; mi++) {
                int ma = wm * 64 + mi * 16 + g;
                af[mi][0] = Qs[ma * 36 + kb2 + t4];
                af[mi][1] = Qs[(ma + 8) * 36 + kb2 + t4];
                af[mi][2] = Qs[ma * 36 + kb2 + t4 + 4];
                af[mi][3] = Qs[(ma + 8) * 36 + kb2 + t4 + 4];
            }
#pragma unroll
            for (int ni = 0; ni < 4; ni++) {
                int nb = wn * 32 + ni * 8 + g;
                bf[ni][0] = Ks[nb * 36 + kb2 + t4];
                bf[ni][1] = Ks[nb * 36 + kb2 + t4 + 4];
            }
#pragma unroll
            for (int mi = 0; mi < 4; mi++)
#pragma unroll
                for (int ni = 0; ni < 4; ni++)
                    mma16(s[mi][ni], af[mi], bf[ni]);
        }

#pragma unroll
        for (int mi = 0; mi < 4; mi++)
#pragma unroll
            for (int hf = 0; hf < 2; hf++) {
                float ls = 0.f;
#pragma unroll
                for (int ni = 0; ni < 4; ni++) {
                    float p0 = __expf(s[mi][ni][hf * 2]);
                    float p1 = __expf(s[mi][ni][hf * 2 + 1]);
                    s[mi][ni][hf * 2] = p0; s[mi][ni][hf * 2 + 1] = p1;
                    ls += p0 + p1;
                }
                ls += __shfl_xor_sync(0xffffffffu, ls, 1);
                ls += __shfl_xor_sync(0xffffffffu, ls, 2);
                if (t4 == 0) red[wn * 128 + wm * 64 + mi * 16 + hf * 8 + g] = ls;
            }
        __syncthreads();
#pragma unroll
        for (int mi = 0; mi < 4; mi++)
#pragma unroll
            for (int hf = 0; hf < 2; hf++) {
                int r = wm * 64 + mi * 16 + hf * 8 + g;
                l_run[mi][hf] += red[r] + red[128 + r] + red[256 + r] + red[384 + r];
            }
#pragma unroll
        for (int mi = 0; mi < 4; mi++) {
            int r = wm * 64 + mi * 16 + g;
#pragma unroll
            for (int ni = 0; ni < 4; ni++) {
                int c2 = wn * 16 + ni * 4 + t4;
                Ps[r * 68 + c2]       = h2p(s[mi][ni][0], s[mi][ni][1]);
                Ps[(r + 8) * 68 + c2] = h2p(s[mi][ni][2], s[mi][ni][3]);
            }
        }
        __syncthreads();

#pragma unroll
        for (int ks = 0; ks < 8; ks++) {
            int kb2 = ks * 8;
            unsigned af[4][4], bf[2][2];
#pragma unroll
            for (int mi = 0; mi < 4; mi++) {
                int ma = wm * 64 + mi * 16 + g;
                af[mi][0] = Ps[ma * 68 + kb2 + t4];
                af[mi][1] = Ps[(ma + 8) * 68 + kb2 + t4];
                af[mi][2] = Ps[ma * 68 + kb2 + t4 + 4];
                af[mi][3] = Ps[(ma + 8) * 68 + kb2 + t4 + 4];
            }
#pragma unroll
            for (int ni = 0; ni < 2; ni++) {
                int nb = wn * 16 + ni * 8 + g;
                bf[ni][0] = Vs[(kb2 + t4) * 72 + nb];
                bf[ni][1] = Vs[(kb2 + t4 + 4) * 72 + nb];
            }
#pragma unroll
            for (int mi = 0; mi < 4; mi++)
#pragma unroll
                for (int ni = 0; ni < 2; ni++)
                    mma16(acc_o[mi][ni], af[mi], bf[ni]);
        }
    }

#pragma unroll
    for (int mi = 0; mi < 4; mi++) {
        int row = m0 + wm * 64 + mi * 16 + g;
        float inv0 = 1.f / l_run[mi][0], inv1 = 1.f / l_run[mi][1];
#pragma unroll
        for (int ni = 0; ni < 2; ni++) {
            int col = h * 64 + wn * 16 + ni * 8 + t4 * 2;
            long o0 = ((long)b * NCC + row) * 256 + col;
            long o1 = ((long)b * NCC + row + 8) * 256 + col;
            *(unsigned*)&attnoh[o0] = h2p(acc_o[mi][ni][0] * inv0, acc_o[mi][ni][1] * inv0);
            *(unsigned*)&attnoh[o1] = h2p(acc_o[mi][ni][2] * inv1, acc_o[mi][ni][3] * inv1);
        }
    }
}

// ===================== flash cross-attention (fp16 I/O, 2 CTAs/SM) =====================
#define CROSS_SMEM (27904 * 4)

__global__ void __launch_bounds__(256, 2) flash_cross_k(
    const unsigned short* __restrict__ qth, const unsigned short* __restrict__ rep2h,
    unsigned short* __restrict__ deth)
{
    extern __shared__ unsigned smu[];
    unsigned* Qs  = smu;
    unsigned* KVs = smu + 8448;
    unsigned* Vsc = smu + 16896;
    unsigned* Psc = smu + 25344;
    float*    red = (float*)(smu + 27648);

    const int b = blockIdx.z;
    const int m0 = blockIdx.x * 64;
    const unsigned short* qb  = qth   + (long)b * NTT * 256;
    const unsigned short* kvb = rep2h + (long)b * NCC * 256;

    const int tid = threadIdx.x, wid = tid >> 5, lane = tid & 31;
    const int g = lane >> 2, t4 = lane & 3;
    const int wm = wid & 1, wn = wid >> 1;
    const int c4h = (tid & 63) * 4, r0 = tid >> 6;

    const __half2 sc16 = __floats2half2_rn(0.0625f, 0.0625f);
#pragma unroll
    for (int p = 0; p < 16; p++) {
        int r = p * 4 + r0;
        uint2 u = *(const uint2*)(qb + (long)(m0 + r) * 256 + c4h);
        __half2 ha = __hmul2(*(__half2*)&u.x, sc16);
        __half2 hb = __hmul2(*(__half2*)&u.y, sc16);
        *(uint2*)&Qs[r * 132 + (c4h >> 1)] = make_uint2(*(unsigned*)&ha, *(unsigned*)&hb);
    }

    float l_run[2][2], acc_o[2][8][4];
#pragma unroll
    for (int mi = 0; mi < 2; mi++)
#pragma unroll
        for (int hf = 0; hf < 2; hf++) l_run[mi][hf] = 0.f;
#pragma unroll
    for (int mi = 0; mi < 2; mi++)
#pragma unroll
        for (int ni = 0; ni < 8; ni++)
#pragma unroll
            for (int c = 0; c < 4; c++) acc_o[mi][ni][c] = 0.f;

    for (int tk = 0; tk < 16; tk++) {
        __syncthreads();
#pragma unroll
        for (int p = 0; p < 8; p++) {
            int q = p * 4 + r0;
            uint2 e = *(const uint2*)(kvb + (long)(tk * 64 + 2 * q) * 256 + c4h);
            uint2 o = *(const uint2*)(kvb + (long)(tk * 64 + 2 * q + 1) * 256 + c4h);
            *(uint2*)&KVs[(2 * q) * 132 + (c4h >> 1)]     = e;
            *(uint2*)&KVs[(2 * q + 1) * 132 + (c4h >> 1)] = o;
            *(uint4*)&Vsc[q * 264 + c4h] = make_uint4(
                ilo(e.x, o.x), ihi(e.x, o.x), ilo(e.y, o.y), ihi(e.y, o.y));
        }
        __syncthreads();

        float s[2][2][4];
#pragma unroll
        for (int mi = 0; mi < 2; mi++)
#pragma unroll
            for (int ni = 0; ni < 2; ni++)
#pragma unroll
                for (int c = 0; c < 4; c++) s[mi][ni][c] = 0.f;
#pragma unroll
        for (int ks = 0; ks < 16; ks++) {
            int kb2 = ks * 8;
            unsigned af[2][4], bf[2][2];
#pragma unroll
            for (int mi = 0; mi < 2; mi++) {
                int ma = wm * 32 + mi * 16 + g;
                af[mi][0] = Qs[ma * 132 + kb2 + t4];
                af[mi][1] = Qs[(ma + 8) * 132 + kb2 + t4];
                af[mi][2] = Qs[ma * 132 + kb2 + t4 + 4];
                af[mi][3] = Qs[(ma + 8) * 132 + kb2 + t4 + 4];
            }
#pragma unroll
            for (int ni = 0; ni < 2; ni++) {
                int nb = wn * 16 + ni * 8 + g;
                bf[ni][0] = KVs[nb * 132 + kb2 + t4];
                bf[ni][1] = KVs[nb * 132 + kb2 + t4 + 4];
            }
#pragma unroll
            for (int mi = 0; mi < 2; mi++)
#pragma unroll
                for (int ni = 0; ni < 2; ni++)
                    mma16(s[mi][ni], af[mi], bf[ni]);
        }

#pragma unroll
        for (int mi = 0; mi < 2; mi++)
#pragma unroll
            for (int hf = 0; hf < 2; hf++) {
                float ls = 0.f;
#pragma unroll
                for (int ni = 0; ni < 2; ni++) {
                    float p0 = __expf(s[mi][ni][hf * 2]);
                    float p1 = __expf(s[mi][ni][hf * 2 + 1]);
                    s[mi][ni][hf * 2] = p0; s[mi][ni][hf * 2 + 1] = p1;
                    ls += p0 + p1;
                }
                ls += __shfl_xor_sync(0xffffffffu, ls, 1);
                ls += __shfl_xor_sync(0xffffffffu, ls, 2);
                if (t4 == 0) red[wn * 64 + wm * 32 + mi * 16 + hf * 8 + g] = ls;
            }
        __syncthreads();
#pragma unroll
        for (int mi = 0; mi < 2; mi++)
#pragma unroll
            for (int hf = 0; hf < 2; hf++) {
                int r = wm * 32 + mi * 16 + hf * 8 + g;
                l_run[mi][hf] += red[r] + red[64 + r] + red[128 + r] + red[192 + r];
            }
#pragma unroll
        for (int mi = 0; mi < 2; mi++) {
            int r = wm * 32 + mi * 16 + g;
#pragma unroll
            for (int ni = 0; ni < 2; ni++) {
                int c2 = wn * 8 + ni * 4 + t4;
                Psc[r * 36 + c2]       = h2p(s[mi][ni][0], s[mi][ni][1]);
                Psc[(r + 8) * 36 + c2] = h2p(s[mi][ni][2], s[mi][ni][3]);
            }
        }
        __syncthreads();

#pragma unroll
        for (int ks = 0; ks < 4; ks++) {
            int kb2 = ks * 8;
            unsigned af[2][4], bf[8][2];
#pragma unroll
            for (int mi = 0; mi < 2; mi++) {
                int ma = wm * 32 + mi * 16 + g;
                af[mi][0] = Psc[ma * 36 + kb2 + t4];
                af[mi][1] = Psc[(ma + 8) * 36 + kb2 + t4];
                af[mi][2] = Psc[ma * 36 + kb2 + t4 + 4];
                af[mi][3] = Psc[(ma + 8) * 36 + kb2 + t4 + 4];
            }
#pragma unroll
            for (int ni = 0; ni < 8; ni++) {
                int nb = wn * 64 + ni * 8 + g;
                bf[ni][0] = Vsc[(kb2 + t4) * 264 + nb];
                bf[ni][1] = Vsc[(kb2 + t4 + 4) * 264 + nb];
            }
#pragma unroll
            for (int mi = 0; mi < 2; mi++)
#pragma unroll
                for (int ni = 0; ni < 8; ni++)
                    mma16(acc_o[mi][ni], af[mi], bf[ni]);
        }
    }

#pragma unroll
    for (int mi = 0; mi < 2; mi++) {
        int row = m0 + wm * 32 + mi * 16 + g;
        float inv0 = 1.f / l_run[mi][0], inv1 = 1.f / l_run[mi][1];
#pragma unroll
        for (int ni = 0; ni < 8; ni++) {
            int col = wn * 64 + ni * 8 + t4 * 2;
            long o0 = ((long)b * NTT + row) * 256 + col;
            long o1 = ((long)b * NTT + row + 8) * 256 + col;
            *(unsigned*)&deth[o0] = h2p(acc_o[mi][ni][0] * inv0, acc_o[mi][ni][1] * inv0);
            *(unsigned*)&deth[o1] = h2p(acc_o[mi][ni][2] * inv1, acc_o[mi][ni][3] * inv1);
        }
    }
}

// ===================== small kernels =====================

__global__ void mean1_k(const float* __restrict__ h, float* __restrict__ part)
{
    int b = blockIdx.x, ch = blockIdx.y, j = threadIdx.x * 4;
    const float* p = h + (long)b * NCC * RD + (long)ch * 32 * RD + j;
    float4 s = make_float4(0.f, 0.f, 0.f, 0.f);
#pragma unroll 4
    for (int n = 0; n < 32; n++) {
        float4 v = *(const float4*)(p + (long)n * RD);
        s.x += v.x; s.y += v.y; s.z += v.z; s.w += v.w;
    }
    *(float4*)&part[(long)(b * 32 + ch) * RD + j] = s;
}

__global__ void mean2_k(const float* __restrict__ part, float* __restrict__ out)
{
    int b = blockIdx.x, j = threadIdx.x;
    float s = 0.f;
#pragma unroll
    for (int c = 0; c < 32; c++) s += part[(long)(b * 32 + c) * RD + j];
    out[b * RD + j] = s * (1.f / NCC);
}

__global__ void latent_k(const float* __restrict__ hmean,
                         const float* __restrict__ pw, const float* __restrict__ pb,
                         const float* __restrict__ mw, const float* __restrict__ mb,
                         const float* __restrict__ sw, const float* __restrict__ sb,
                         const float* __restrict__ eps, float* __restrict__ z)
{
    __shared__ float h2s[LHD];
    int b = blockIdx.x, tid = threadIdx.x;
    if (tid < LHD) {
        float s = pb[tid];
        const float* hm = hmean + b * RD;
        for (int k = 0; k < RD; k++) s += hm[k] * pw[k * LHD + tid];
        h2s[tid] = s;
    }
    __syncthreads();
    float mu = mb[tid], ls = sb[tid];
    for (int k = 0; k < LHD; k++) {
        mu += h2s[k] * mw[k * RD + tid];
        ls += h2s[k] * sw[k * RD + tid];
    }
    float sig = 0.9f / (1.f + expf(-ls)) + 0.1f;
    z[b * RD + tid] = mu + sig * eps[b * RD + tid];
}

// dec2 (K=128, N=16) fused with mu/sigma epilogue
__global__ void __launch_bounds__(256) dec2_k(
    const float* __restrict__ dh, const float* __restrict__ w2,
    const float* __restrict__ b2, float* __restrict__ out)
{
    __shared__ float w[128][17];
    __shared__ float a[16][132];
    int tid = threadIdx.x;
    for (int i = tid; i < 128 * 16; i += 256) { int k = i >> 4, c = i & 15; w[k][c] = w2[i]; }
    long row0 = (long)blockIdx.x * 16;
    for (int i = tid; i < 512; i += 256) {
        int r = i >> 5, c4 = (i & 31) * 4;
        *(float4*)&a[r][c4] = *(const float4*)&dh[(row0 + r) * 128 + c4];
    }
    __syncthreads();
    int r = tid >> 4, c = tid & 15;
    float s = b2[c];
#pragma unroll
    for (int k = 0; k < 128; k++) s += a[r][k] * w[k][c];
    long row = row0 + r;
    const long TOT = (long)BB * NTT * CTRLD;
    if (c < CTRLD) out[row * CTRLD + c] = s;
    else {
        float sp = fmaxf(s, 0.f) + log1pf(expf(-fabsf(s)));
        out[TOT + row * CTRLD + (c - CTRLD)] = 0.9f * sp + 0.1f;
    }
}

// ===================== host side =====================

static void* symv(const void* s) { void* p = nullptr; cudaGetSymbolAddress(&p, s); return p; }

extern "C" void kernel_launch(void* const* d_in, const int* in_sizes, int n_in,
                              void* d_out, int out_size)
{
    const float* context_x = (const float*)d_in[0];
    const float* context_y = (const float*)d_in[1];
    const float* target_x  = (const float*)d_in[2];
    const float* pred_ctrl = (const float*)d_in[3];
    const float* eps       = (const float*)d_in[4];
    const float* ce_w1 = (const float*)d_in[5];  const float* ce_b1 = (const float*)d_in[6];
    const float* ce_w2 = (const float*)d_in[7];  const float* ce_b2 = (const float*)d_in[8];
    const float* sa_in_w = (const float*)d_in[9];  const float* sa_in_b = (const float*)d_in[10];
    const float* sa_out_w = (const float*)d_in[11]; const float* sa_out_b = (const float*)d_in[12];
    const float* sa_ln_g = (const float*)d_in[13];  const float* sa_ln_b = (const float*)d_in[14];
    const float* qp_w = (const float*)d_in[15]; const float* qp_b = (const float*)d_in[16];
    const float* le_w1 = (const float*)d_in[17]; const float* le_b1 = (const float*)d_in[18];
    const float* le_w2 = (const float*)d_in[19]; const float* le_b2 = (const float*)d_in[20];
    const float* le_pw = (const float*)d_in[21]; const float* le_pb = (const float*)d_in[22];
    const float* le_mw = (const float*)d_in[23]; const float* le_mb = (const float*)d_in[24];
    const float* le_sw = (const float*)d_in[25]; const float* le_sb = (const float*)d_in[26];
    const float* dec_w1 = (const float*)d_in[27]; const float* dec_b1 = (const float*)d_in[28];
    const float* dec_w2 = (const float*)d_in[29]; const float* dec_b2 = (const float*)d_in[30];
    float* out = (float*)d_out;

    unsigned short* h12h  = (unsigned short*)symv(g_h12h);
    float* rep   = (float*)symv(g_rep);
    float* hle   = (float*)symv(g_hle);
    float* part  = (float*)symv(g_part);
    float* hmean = (float*)symv(g_hmean);
    float* z     = (float*)symv(g_z);
    unsigned short* qkvh   = (unsigned short*)symv(g_qkvh);
    unsigned short* attnoh = (unsigned short*)symv(g_attnoh);
    unsigned short* rep2h  = (unsigned short*)symv(g_rep2h);
    unsigned short* qth    = (unsigned short*)symv(g_qth);
    unsigned short* deth   = (unsigned short*)symv(g_deth);
    float* dh    = (float*)symv(g_dh);

    const int MC = BB * NCC;   // 16384
    const int MT = BB * NTT;   // 32768

    static cudaStream_t s2 = nullptr;
    static cudaEvent_t ev0 = nullptr, evA = nullptr, evB = nullptr, evC = nullptr;
    if (!s2) {
        cudaStreamCreateWithFlags(&s2, cudaStreamNonBlocking);
        cudaEventCreateWithFlags(&ev0, cudaEventDisableTiming);
        cudaEventCreateWithFlags(&evA, cudaEventDisableTiming);
        cudaEventCreateWithFlags(&evB, cudaEventDisableTiming);
        cudaEventCreateWithFlags(&evC, cudaEventDisableTiming);
    }

    cudaFuncSetAttribute(flash_self_k,  cudaFuncAttributeMaxDynamicSharedMemorySize, SELF_SMEM);
    cudaFuncSetAttribute(flash_cross_k, cudaFuncAttributeMaxDynamicSharedMemorySize, CROSS_SMEM);

    // legal fork: ev0 on capture stream BEFORE s2's first op
    cudaEventRecord(ev0, 0);
    cudaStreamWaitEvent(s2, ev0, 0);

    // qt (half out) on s2
    mma_gemm<32, 0, 0, 0, 1, 0><<<dim3(MT / 128, 2, 1), 256, 0, s2>>>(target_x, qp_w, qp_b, (float*)qth,
        MT, RD, GAPD, GAPD, RD, RD, 1.f, nullptr, nullptr, nullptr, nullptr, nullptr);
    cudaEventRecord(evC, s2);

    // merged MLP1 (le|ce) -> half
    mma_gemm<32, 1, 2, 1, 1, 0><<<dim3(MC / 128, 2, 1), 256>>>(nullptr, le_w1, le_b1, (float*)h12h,
        MC, 2 * HIDD, CIN, CIN, HIDD, 2 * HIDD, 1.f, context_y, context_x, nullptr,
        ce_w1, ce_b1);

    // fork: latent path on s2
    cudaEventRecord(evA, 0);
    cudaStreamWaitEvent(s2, evA, 0);
    mma_gemm<32, 0, 0, 0, 0, 1><<<dim3(MC / 128, 2, 1), 256, 0, s2>>>((const float*)h12h, le_w2, le_b2, hle,
        MC, RD, HIDD, 2 * HIDD, RD, RD, 1.f, nullptr, nullptr, nullptr, nullptr, nullptr);
    mean1_k<<<dim3(BB, 32), 64, 0, s2>>>(hle, part);
    mean2_k<<<BB, 256, 0, s2>>>(part, hmean);
    latent_k<<<BB, 256, 0, s2>>>(hmean, le_pw, le_pb, le_mw, le_mb, le_sw, le_sb, eps, z);
    cudaEventRecord(evB, s2);

    // deterministic path (A = ce half of h12h)
    mma_gemm<32, 0, 0, 0, 0, 1><<<dim3(MC / 128, 2, 1), 256>>>((const float*)(h12h + HIDD), ce_w2, ce_b2, rep,
        MC, RD, HIDD, 2 * HIDD, RD, RD, 1.f, nullptr, nullptr, nullptr, nullptr, nullptr);

    mma_gemm<32, 0, 0, 0, 1, 0><<<dim3(MC / 128, 6, 1), 256>>>(rep, sa_in_w, sa_in_b, (float*)qkvh,
        MC, 3 * RD, RD, RD, 3 * RD, 3 * RD, 1.f, nullptr, nullptr, nullptr, nullptr, nullptr);

    flash_self_k<<<dim3(NCC / 128, NHD, BB), 256, SELF_SMEM>>>(qkvh, attnoh);

    // fused oproj + residual + LN -> rep2h
    gemm_ln_k<<<MC / 128, 256>>>(attnoh, sa_out_w, sa_out_b, rep, sa_ln_g, sa_ln_b, rep2h);

    // cross attention (join qt)
    cudaStreamWaitEvent(0, evC, 0);
    flash_cross_k<<<dim3(NTT / 64, 1, BB), 256, CROSS_SMEM>>>(qth, rep2h, deth);

    // join latent path, then decoder (dec1 GEMM + dec2)
    cudaStreamWaitEvent(0, evB, 0);
    mma_gemm<32, 1, 1, 0, 0, 0><<<dim3(MT / 128, 1, 1), 256>>>((const float*)deth, dec_w1, dec_b1, dh,
        MT, HIDD, DIN, DIN, HIDD, HIDD, 1.f, z, target_x, pred_ctrl, nullptr, nullptr);
    dec2_k<<<MT / 16, 256>>>(dh, dec_w2, dec_b2, out);
}

// round 14
// speedup vs baseline: 1.6092x; 1.0456x over previous
#include <cuda_runtime.h>
#include <cuda_fp16.h>
#include <math.h>

// ---- problem dims ----
#define BB 16
#define NCC 1024
#define NTT 2048
#define GAPD 128
#define CTRLD 8
#define RD 256
#define NHD 4
#define HDD 64
#define HIDD 128
#define LHD 192
#define CIN (CTRLD + GAPD)          // 136
#define DIN (2 * RD + GAPD + CTRLD) // 648

// ---- scratch ----
__device__ unsigned short g_h12h [BB * NCC * 2 * HIDD];
__device__ float g_rep  [BB * NCC * RD];
__device__ float g_hle  [BB * NCC * RD];
__device__ float g_part [BB * 32 * RD];
__device__ float g_hmean[BB * RD];
__device__ float g_z    [BB * RD];
__device__ unsigned short g_qkvh [BB * NCC * 3 * RD];
__device__ unsigned short g_attnoh[BB * NCC * RD];
__device__ unsigned short g_rep2h[BB * NCC * RD];
__device__ unsigned short g_qth  [(size_t)BB * NTT * RD];
__device__ unsigned short g_deth [(size_t)BB * NTT * RD];
__device__ float g_dh   [BB * NTT * HIDD];

// ===================== fp16 mma helpers =====================
__device__ __forceinline__ unsigned h2p(float a, float b) {
    __half2 h = __floats2half2_rn(a, b);
    return *reinterpret_cast<unsigned*>(&h);
}
__device__ __forceinline__ void mma16(float* d, const unsigned* a, const unsigned* b) {
    asm volatile(
        "mma.sync.aligned.m16n8k16.row.col.f32.f16.f16.f32 "
        "{%0,%1,%2,%3},{%4,%5,%6,%7},{%8,%9},{%0,%1,%2,%3};\n"
        : "+f"(d[0]), "+f"(d[1]), "+f"(d[2]), "+f"(d[3])
        : "r"(a[0]), "r"(a[1]), "r"(a[2]), "r"(a[3]), "r"(b[0]), "r"(b[1]));
}
__device__ __forceinline__ float4 ld_guard(const float* src, int gk, int K) {
    if (gk + 4 <= K) return *(const float4*)src;
    float4 v = make_float4(0.f, 0.f, 0.f, 0.f);
    if (gk     < K) v.x = src[0];
    if (gk + 1 < K) v.y = src[1];
    if (gk + 2 < K) v.z = src[2];
    if (gk + 3 < K) v.w = src[3];
    return v;
}
__device__ __forceinline__ unsigned ilo(unsigned a, unsigned b) { return __byte_perm(a, b, 0x5410); }
__device__ __forceinline__ unsigned ihi(unsigned a, unsigned b) { return __byte_perm(a, b, 0x7632); }

// ===================== fp16 GEMM (reg-pipelined), B = [K,N] row-major ====
#define XBM 128
#define XBK 32

// MODE 0: plain A. MODE 1: A = [deth(half) | z | tx | pc], K=DIN. MODE 2: A = [cy | cx], K=CIN.
// HA 1: A is half (MODE 0). BMODE 1: B cols split B/B2. OUTH 1: C half.
template<int WNT, int ACT, int MODE, int BMODE, int OUTH, int HA>
__global__ void __launch_bounds__(256) mma_gemm(
    const float* __restrict__ A, const float* __restrict__ B,
    const float* __restrict__ bias, float* __restrict__ C,
    int M, int N, int K, int lda, int ldb, int ldc,
    float alpha,
    const float* __restrict__ zt, const float* __restrict__ txt,
    const float* __restrict__ pct,
    const float* __restrict__ B2, const float* __restrict__ bias2)
{
    constexpr int XBN_ = WNT * 4;
    constexpr int NI = WNT / 8;

    __shared__ unsigned As2[XBM][20];
    __shared__ unsigned Bs2[XBK / 2][XBN_ + 8];

    int tid = threadIdx.x;
    int wid = tid >> 5, lane = tid & 31;
    int g = lane >> 2, t4 = lane & 3;
    int wm = wid & 1, wn = wid >> 1;
    int m0 = blockIdx.x * XBM, n0 = blockIdx.y * XBN_;

    float acc[4][NI][4];
#pragma unroll
    for (int i = 0; i < 4; i++)
#pragma unroll
        for (int j = 0; j < NI; j++)
#pragma unroll
            for (int l = 0; l < 4; l++) acc[i][j][l] = 0.f;

    float4 ra[4]; uint2 rah[4];
    float4 rbE[2], rbO[2];
    constexpr int C4  = XBN_ / 4;
    constexpr int RP2 = 256 / C4;
    constexpr int ITS2 = (XBK / 2) / RP2;

    const int ac = (tid & 7) * 4;
    const int ar = tid >> 3;
    const int bc4 = tid % C4;
    const int brb = tid / C4;

    auto loadA = [&](int k0) {
        int gk = k0 + ac;
#pragma unroll
        for (int p = 0; p < 4; p++) {
            int gm = m0 + p * 32 + ar;
            if (MODE == 1) {
                if (gk < RD) {
                    rah[p] = *(const uint2*)((const unsigned short*)A + (long)gm * RD + gk);
                } else {
                    const float* s;
                    if (gk < 2 * RD)             s = zt  + (long)(gm >> 11) * RD + (gk - RD);
                    else if (gk < 2 * RD + GAPD) s = txt + (long)gm * GAPD + (gk - 2 * RD);
                    else if (gk < DIN)           s = pct + (long)gm * CTRLD + (gk - 2 * RD - GAPD);
                    else                         s = nullptr;
                    ra[p] = s ? *(const float4*)s : make_float4(0.f, 0.f, 0.f, 0.f);
                }
            } else if (MODE == 2) {
                const float* s;
                if (gk < CTRLD)    s = zt  + (long)gm * CTRLD + gk;
                else if (gk < CIN) s = txt + (long)gm * GAPD + (gk - CTRLD);
                else               s = nullptr;
                ra[p] = s ? *(const float4*)s : make_float4(0.f, 0.f, 0.f, 0.f);
            } else if (HA) {
                const unsigned short* Ah = (const unsigned short*)A;
                rah[p] = (gk + 4 <= K) ? *(const uint2*)(Ah + (long)gm * lda + gk)
                                       : make_uint2(0u, 0u);
            } else {
                ra[p] = ld_guard(A + (long)gm * lda + gk, gk, K);
            }
        }
    };
    auto loadB = [&](int k0) {
        int gn = n0 + bc4 * 4;
#pragma unroll
        for (int it = 0; it < ITS2; it++) {
            int kp = k0 + (it * RP2 + brb) * 2;
            if (BMODE == 1) {
                const float* base0 = (gn < HIDD) ? B : B2;
                int gq = (gn < HIDD) ? gn : gn - HIDD;
                rbE[it] = (kp     < K) ? *(const float4*)(base0 + (long)kp * ldb + gq)
                                       : make_float4(0.f, 0.f, 0.f, 0.f);
                rbO[it] = (kp + 1 < K) ? *(const float4*)(base0 + (long)(kp + 1) * ldb + gq)
                                       : make_float4(0.f, 0.f, 0.f, 0.f);
            } else {
                bool okn = (gn + 3 < N);
                rbE[it] = (kp     < K && okn) ? *(const float4*)(B + (long)kp * ldb + gn)
                                              : make_float4(0.f, 0.f, 0.f, 0.f);
                rbO[it] = (kp + 1 < K && okn) ? *(const float4*)(B + (long)(kp + 1) * ldb + gn)
                                              : make_float4(0.f, 0.f, 0.f, 0.f);
            }
        }
    };
    auto stsAB = [&](int k0) {
        int gk = k0 + ac;
#pragma unroll
        for (int p = 0; p < 4; p++) {
            if ((MODE == 1 && gk < RD) || (HA && MODE == 0)) {
                *(uint2*)&As2[p * 32 + ar][ac >> 1] = rah[p];
            } else {
                uint2 u = make_uint2(h2p(ra[p].x, ra[p].y), h2p(ra[p].z, ra[p].w));
                *(uint2*)&As2[p * 32 + ar][ac >> 1] = u;
            }
        }
#pragma unroll
        for (int it = 0; it < ITS2; it++) {
            uint4 u = make_uint4(h2p(rbE[it].x, rbO[it].x), h2p(rbE[it].y, rbO[it].y),
                                 h2p(rbE[it].z, rbO[it].z), h2p(rbE[it].w, rbO[it].w));
            *(uint4*)&Bs2[it * RP2 + brb][bc4 * 4] = u;
        }
    };

    int kT = (K + XBK - 1) / XBK;
    loadA(0); loadB(0);

    for (int t = 0; t < kT; t++) {
        stsAB(t * XBK);
        __syncthreads();
        if (t + 1 < kT) { loadA((t + 1) * XBK); loadB((t + 1) * XBK); }
#pragma unroll
        for (int ks = 0; ks < 2; ks++) {
            int kb2 = ks * 8;
            unsigned af[4][4], bf[NI][2];
#pragma unroll
            for (int mi = 0; mi < 4; mi++) {
                int ma = wm * 64 + mi * 16 + g;
                af[mi][0] = As2[ma    ][kb2 + t4];
                af[mi][1] = As2[ma + 8][kb2 + t4];
                af[mi][2] = As2[ma    ][kb2 + t4 + 4];
                af[mi][3] = As2[ma + 8][kb2 + t4 + 4];
            }
#pragma unroll
            for (int ni = 0; ni < NI; ni++) {
                int nb = wn * WNT + ni * 8 + g;
                bf[ni][0] = Bs2[kb2 + t4    ][nb];
                bf[ni][1] = Bs2[kb2 + t4 + 4][nb];
            }
#pragma unroll
            for (int mi = 0; mi < 4; mi++)
#pragma unroll
                for (int ni = 0; ni < NI; ni++)
                    mma16(acc[mi][ni], af[mi], bf[ni]);
        }
        __syncthreads();
    }

#pragma unroll
    for (int mi = 0; mi < 4; mi++) {
        int gm = m0 + wm * 64 + mi * 16 + g;
#pragma unroll
        for (int ni = 0; ni < NI; ni++) {
            int gn = n0 + wn * WNT + ni * 8 + t4 * 2;
            if (gn >= N) continue;
            float b0, b1;
            if (BMODE == 1) {
                const float* bp = (gn < HIDD) ? bias : bias2;
                int gq = (gn < HIDD) ? gn : gn - HIDD;
                b0 = bp[gq]; b1 = bp[gq + 1];
            } else {
                b0 = bias ? bias[gn] : 0.f;
                b1 = bias ? bias[gn + 1] : 0.f;
            }
            float v0 = acc[mi][ni][0] * alpha + b0;
            float v1 = acc[mi][ni][1] * alpha + b1;
            float v2 = acc[mi][ni][2] * alpha + b0;
            float v3 = acc[mi][ni][3] * alpha + b1;
            if (ACT == 1) {
                v0 = fmaxf(v0, 0.f); v1 = fmaxf(v1, 0.f);
                v2 = fmaxf(v2, 0.f); v3 = fmaxf(v3, 0.f);
            }
            if (OUTH) {
                unsigned short* Ch = (unsigned short*)C;
                *(unsigned*)&Ch[(long)gm * ldc + gn]       = h2p(v0, v1);
                *(unsigned*)&Ch[(long)(gm + 8) * ldc + gn] = h2p(v2, v3);
            } else {
                *(float2*)&C[(long)gm * ldc + gn]       = make_float2(v0, v1);
                *(float2*)&C[(long)(gm + 8) * ldc + gn] = make_float2(v2, v3);
            }
        }
    }
}

// ===================== fused oproj GEMM + residual + LayerNorm =====================
// 128x256 tile (full row), K=256. A = attnoh (half). Writes rep2h (half).
__global__ void __launch_bounds__(256) gemm_ln_k(
    const unsigned short* __restrict__ Ah, const float* __restrict__ B,
    const float* __restrict__ bias, const float* __restrict__ resid,
    const float* __restrict__ lng, const float* __restrict__ lnb,
    unsigned short* __restrict__ outh)
{
    __shared__ unsigned As2[128][20];
    __shared__ unsigned Bs2[16][264];
    __shared__ float red[512];

    const int K = RD;
    int tid = threadIdx.x;
    int wid = tid >> 5, lane = tid & 31;
    int g = lane >> 2, t4 = lane & 3;
    int wm = wid & 1, wn = wid >> 1;
    int m0 = blockIdx.x * 128;

    float acc[4][8][4];
#pragma unroll
    for (int i = 0; i < 4; i++)
#pragma unroll
        for (int j = 0; j < 8; j++)
#pragma unroll
            for (int l = 0; l < 4; l++) acc[i][j][l] = 0.f;

    uint2 rah[4];
    float4 rbE[4], rbO[4];
    const int ac = (tid & 7) * 4;
    const int ar = tid >> 3;
    const int bc4 = tid & 63;
    const int brb = tid >> 6;

    auto loadA = [&](int k0) {
        int gk = k0 + ac;
#pragma unroll
        for (int p = 0; p < 4; p++)
            rah[p] = *(const uint2*)(Ah + (long)(m0 + p * 32 + ar) * RD + gk);
    };
    auto loadB = [&](int k0) {
#pragma unroll
        for (int it = 0; it < 4; it++) {
            int kp = k0 + (it * 4 + brb) * 2;
            rbE[it] = *(const float4*)(B + (long)kp * RD + bc4 * 4);
            rbO[it] = *(const float4*)(B + (long)(kp + 1) * RD + bc4 * 4);
        }
    };
    auto stsAB = [&]() {
#pragma unroll
        for (int p = 0; p < 4; p++)
            *(uint2*)&As2[p * 32 + ar][ac >> 1] = rah[p];
#pragma unroll
        for (int it = 0; it < 4; it++) {
            uint4 u = make_uint4(h2p(rbE[it].x, rbO[it].x), h2p(rbE[it].y, rbO[it].y),
                                 h2p(rbE[it].z, rbO[it].z), h2p(rbE[it].w, rbO[it].w));
            *(uint4*)&Bs2[it * 4 + brb][bc4 * 4] = u;
        }
    };

    loadA(0); loadB(0);
    for (int t = 0; t < K / XBK; t++) {
        stsAB();
        __syncthreads();
        if (t + 1 < K / XBK) { loadA((t + 1) * XBK); loadB((t + 1) * XBK); }
#pragma unroll
        for (int ks = 0; ks < 2; ks++) {
            int kb2 = ks * 8;
            unsigned af[4][4], bf[8][2];
#pragma unroll
            for (int mi = 0; mi < 4; mi++) {
                int ma = wm * 64 + mi * 16 + g;
                af[mi][0] = As2[ma    ][kb2 + t4];
                af[mi][1] = As2[ma + 8][kb2 + t4];
                af[mi][2] = As2[ma    ][kb2 + t4 + 4];
                af[mi][3] = As2[ma + 8][kb2 + t4 + 4];
            }
#pragma unroll
            for (int ni = 0; ni < 8; ni++) {
                int nb = wn * 64 + ni * 8 + g;
                bf[ni][0] = Bs2[kb2 + t4    ][nb];
                bf[ni][1] = Bs2[kb2 + t4 + 4][nb];
            }
#pragma unroll
            for (int mi = 0; mi < 4; mi++)
#pragma unroll
                for (int ni = 0; ni < 8; ni++)
                    mma16(acc[mi][ni], af[mi], bf[ni]);
        }
        __syncthreads();
    }

#pragma unroll
    for (int mi = 0; mi < 4; mi++) {
        int gr = m0 + wm * 64 + mi * 16 + g;
#pragma unroll
        for (int ni = 0; ni < 8; ni++) {
            int col = wn * 64 + ni * 8 + t4 * 2;
            float2 r0 = *(const float2*)&resid[(long)gr * RD + col];
            float2 r1 = *(const float2*)&resid[(long)(gr + 8) * RD + col];
            float b0 = bias[col], b1 = bias[col + 1];
            acc[mi][ni][0] += b0 + r0.x; acc[mi][ni][1] += b1 + r0.y;
            acc[mi][ni][2] += b0 + r1.x; acc[mi][ni][3] += b1 + r1.y;
        }
    }

    float mean[4][2];
#pragma unroll
    for (int mi = 0; mi < 4; mi++)
#pragma unroll
        for (int hf = 0; hf < 2; hf++) {
            float s = 0.f;
#pragma unroll
            for (int ni = 0; ni < 8; ni++) s += acc[mi][ni][hf * 2] + acc[mi][ni][hf * 2 + 1];
            s += __shfl_xor_sync(0xffffffffu, s, 1);
            s += __shfl_xor_sync(0xffffffffu, s, 2);
            if (t4 == 0) red[wn * 128 + wm * 64 + mi * 16 + hf * 8 + g] = s;
        }
    __syncthreads();
#pragma unroll
    for (int mi = 0; mi < 4; mi++)
#pragma unroll
        for (int hf = 0; hf < 2; hf++) {
            int r = wm * 64 + mi * 16 + hf * 8 + g;
            mean[mi][hf] = (red[r] + red[128 + r] + red[256 + r] + red[384 + r]) * (1.f / RD);
        }
    __syncthreads();

    float inv[4][2];
#pragma unroll
    for (int mi = 0; mi < 4; mi++)
#pragma unroll
        for (int hf = 0; hf < 2; hf++) {
            float s = 0.f;
#pragma unroll
            for (int ni = 0; ni < 8; ni++) {
                float d0 = acc[mi][ni][hf * 2]     - mean[mi][hf];
                float d1 = acc[mi][ni][hf * 2 + 1] - mean[mi][hf];
                s += d0 * d0 + d1 * d1;
            }
            s += __shfl_xor_sync(0xffffffffu, s, 1);
            s += __shfl_xor_sync(0xffffffffu, s, 2);
            if (t4 == 0) red[wn * 128 + wm * 64 + mi * 16 + hf * 8 + g] = s;
        }
    __syncthreads();
#pragma unroll
    for (int mi = 0; mi < 4; mi++)
#pragma unroll
        for (int hf = 0; hf < 2; hf++) {
            int r = wm * 64 + mi * 16 + hf * 8 + g;
            float var = (red[r] + red[128 + r] + red[256 + r] + red[384 + r]) * (1.f / RD);
            inv[mi][hf] = rsqrtf(var + 1e-5f);
        }

#pragma unroll
    for (int mi = 0; mi < 4; mi++) {
        int gr = m0 + wm * 64 + mi * 16 + g;
#pragma unroll
        for (int ni = 0; ni < 8; ni++) {
            int col = wn * 64 + ni * 8 + t4 * 2;
            float g0 = lng[col], g1 = lng[col + 1];
            float c0 = lnb[col], c1 = lnb[col + 1];
            float v0 = (acc[mi][ni][0] - mean[mi][0]) * inv[mi][0] * g0 + c0;
            float v1 = (acc[mi][ni][1] - mean[mi][0]) * inv[mi][0] * g1 + c1;
            float v2 = (acc[mi][ni][2] - mean[mi][1]) * inv[mi][1] * g0 + c0;
            float v3 = (acc[mi][ni][3] - mean[mi][1]) * inv[mi][1] * g1 + c1;
            *(unsigned*)&outh[(long)gr * RD + col]       = h2p(v0, v1);
            *(unsigned*)&outh[(long)(gr + 8) * RD + col] = h2p(v2, v3);
        }
    }
}

// ===================== flash self-attention (deferred l-reduction, 3 syncs/iter) ====
#define SELF_SMEM (23040 * 4)

__global__ void __launch_bounds__(256, 2) flash_self_k(
    const unsigned short* __restrict__ qkvh, unsigned short* __restrict__ attnoh)
{
    extern __shared__ unsigned smu[];
    unsigned* Qs = smu;
    unsigned* Ks = smu + 4608;
    unsigned* Vs = smu + 9216;
    unsigned* Ps = smu + 13824;
    float*    red = (float*)(smu + 22528);

    const int b = blockIdx.z, h = blockIdx.y;
    const int m0 = blockIdx.x * 128;
    const unsigned short* base = qkvh + (long)b * NCC * 768;
    const unsigned short* qp = base + h * 64;
    const unsigned short* kp = base + 256 + h * 64;
    const unsigned short* vp = base + 512 + h * 64;

    const int tid = threadIdx.x, wid = tid >> 5, lane = tid & 31;
    const int g = lane >> 2, t4 = lane & 3;
    const int wm = wid & 1, wn = wid >> 1;
    const int c4h = (tid & 15) * 4, r0 = tid >> 4;

    const __half2 sc8 = __floats2half2_rn(0.125f, 0.125f);
#pragma unroll
    for (int p = 0; p < 8; p++) {
        int r = p * 16 + r0;
        uint2 u = *(const uint2*)(qp + (long)(m0 + r) * 768 + c4h);
        __half2 ha = __hmul2(*(__half2*)&u.x, sc8);
        __half2 hb = __hmul2(*(__half2*)&u.y, sc8);
        *(uint2*)&Qs[r * 36 + (c4h >> 1)] = make_uint2(*(unsigned*)&ha, *(unsigned*)&hb);
    }

    float l_part[4][2], acc_o[4][2][4];
#pragma unroll
    for (int mi = 0; mi < 4; mi++)
#pragma unroll
        for (int hf = 0; hf < 2; hf++) l_part[mi][hf] = 0.f;
#pragma unroll
    for (int mi = 0; mi < 4; mi++)
#pragma unroll
        for (int ni = 0; ni < 2; ni++)
#pragma unroll
            for (int c = 0; c < 4; c++) acc_o[mi][ni][c] = 0.f;

    for (int tk = 0; tk < 8; tk++) {
        __syncthreads();
#pragma unroll
        for (int p = 0; p < 8; p++) {
            int r = p * 16 + r0;
            *(uint2*)&Ks[r * 36 + (c4h >> 1)] =
                *(const uint2*)(kp + (long)(tk * 128 + r) * 768 + c4h);
        }
#pragma unroll
        for (int p = 0; p < 4; p++) {
            int q = p * 16 + r0;
            uint2 e = *(const uint2*)(vp + (long)(tk * 128 + 2 * q) * 768 + c4h);
            uint2 o = *(const uint2*)(vp + (long)(tk * 128 + 2 * q + 1) * 768 + c4h);
            *(uint4*)&Vs[q * 72 + c4h] = make_uint4(
                ilo(e.x, o.x), ihi(e.x, o.x), ilo(e.y, o.y), ihi(e.y, o.y));
        }
        __syncthreads();

        float s[4][4][4];
#pragma unroll
        for (int mi = 0; mi < 4; mi++)
#pragma unroll
            for (int ni = 0; ni < 4; ni++)
#pragma unroll
                for (int c = 0; c < 4; c++) s[mi][ni][c] = 0.f;
#pragma unroll
        for (int ks = 0; ks < 4; ks++) {
            int kb2 = ks * 8;
            unsigned af[4][4], bf[4][2];
#pragma unroll
            for (int mi = 0; mi < 4; mi++) {
                int ma = wm * 64 + mi * 16 + g;
                af[mi][0] = Qs[ma * 36 + kb2 + t4];
                af[mi][1] = Qs[(ma + 8) * 36 + kb2 + t4];
                af[mi][2] = Qs[ma * 36 + kb2 + t4 + 4];
                af[mi][3] = Qs[(ma + 8) * 36 + kb2 + t4 + 4];
            }
#pragma unroll
            for (int ni = 0; ni < 4; ni++) {
                int nb = wn * 32 + ni * 8 + g;
                bf[ni][0] = Ks[nb * 36 + kb2 + t4];
                bf[ni][1] = Ks[nb * 36 + kb2 + t4 + 4];
            }
#pragma unroll
            for (int mi = 0; mi < 4; mi++)
#pragma unroll
                for (int ni = 0; ni < 4; ni++)
                    mma16(s[mi][ni], af[mi], bf[ni]);
        }

        // exp + local l accumulation (no shuffles, no smem); write P
#pragma unroll
        for (int mi = 0; mi < 4; mi++) {
            int r = wm * 64 + mi * 16 + g;
#pragma unroll
            for (int ni = 0; ni < 4; ni++) {
                float p0 = __expf(s[mi][ni][0]);
                float p1 = __expf(s[mi][ni][1]);
                float p2 = __expf(s[mi][ni][2]);
                float p3 = __expf(s[mi][ni][3]);
                l_part[mi][0] += p0 + p1;
                l_part[mi][1] += p2 + p3;
                int c2 = wn * 16 + ni * 4 + t4;
                Ps[r * 68 + c2]       = h2p(p0, p1);
                Ps[(r + 8) * 68 + c2] = h2p(p2, p3);
            }
        }
        __syncthreads();

#pragma unroll
        for (int ks = 0; ks < 8; ks++) {
            int kb2 = ks * 8;
            unsigned af[4][4], bf[2][2];
#pragma unroll
            for (int mi = 0; mi < 4; mi++) {
                int ma = wm * 64 + mi * 16 + g;
                af[mi][0] = Ps[ma * 68 + kb2 + t4];
                af[mi][1] = Ps[(ma + 8) * 68 + kb2 + t4];
                af[mi][2] = Ps[ma * 68 + kb2 + t4 + 4];
                af[mi][3] = Ps[(ma + 8) * 68 + kb2 + t4 + 4];
            }
#pragma unroll
            for (int ni = 0; ni < 2; ni++) {
                int nb = wn * 16 + ni * 8 + g;
                bf[ni][0] = Vs[(kb2 + t4) * 72 + nb];
                bf[ni][1] = Vs[(kb2 + t4 + 4) * 72 + nb];
            }
#pragma unroll
            for (int mi = 0; mi < 4; mi++)
#pragma unroll
                for (int ni = 0; ni < 2; ni++)
                    mma16(acc_o[mi][ni], af[mi], bf[ni]);
        }
    }

    // ---- final l reduction: quad shuffle + one cross-warp smem pass ----
    __syncthreads();
#pragma unroll
    for (int mi = 0; mi < 4; mi++)
#pragma unroll
        for (int hf = 0; hf < 2; hf++) {
            float ls = l_part[mi][hf];
            ls += __shfl_xor_sync(0xffffffffu, ls, 1);
            ls += __shfl_xor_sync(0xffffffffu, ls, 2);
            if (t4 == 0) red[wn * 128 + wm * 64 + mi * 16 + hf * 8 + g] = ls;
        }
    __syncthreads();
    float l_run[4][2];
#pragma unroll
    for (int mi = 0; mi < 4; mi++)
#pragma unroll
        for (int hf = 0; hf < 2; hf++) {
            int r = wm * 64 + mi * 16 + hf * 8 + g;
            l_run[mi][hf] = red[r] + red[128 + r] + red[256 + r] + red[384 + r];
        }

#pragma unroll
    for (int mi = 0; mi < 4; mi++) {
        int row = m0 + wm * 64 + mi * 16 + g;
        float inv0 = 1.f / l_run[mi][0], inv1 = 1.f / l_run[mi][1];
#pragma unroll
        for (int ni = 0; ni < 2; ni++) {
            int col = h * 64 + wn * 16 + ni * 8 + t4 * 2;
            long o0 = ((long)b * NCC + row) * 256 + col;
            long o1 = ((long)b * NCC + row + 8) * 256 + col;
            *(unsigned*)&attnoh[o0] = h2p(acc_o[mi][ni][0] * inv0, acc_o[mi][ni][1] * inv0);
            *(unsigned*)&attnoh[o1] = h2p(acc_o[mi][ni][2] * inv1, acc_o[mi][ni][3] * inv1);
        }
    }
}

// ===================== flash cross-attention (deferred l-reduction, 3 syncs/iter) ====
#define CROSS_SMEM (27904 * 4)

__global__ void __launch_bounds__(256, 2) flash_cross_k(
    const unsigned short* __restrict__ qth, const unsigned short* __restrict__ rep2h,
    unsigned short* __restrict__ deth)
{
    extern __shared__ unsigned smu[];
    unsigned* Qs  = smu;
    unsigned* KVs = smu + 8448;
    unsigned* Vsc = smu + 16896;
    unsigned* Psc = smu + 25344;
    float*    red = (float*)(smu + 27648);

    const int b = blockIdx.z;
    const int m0 = blockIdx.x * 64;
    const unsigned short* qb  = qth   + (long)b * NTT * 256;
    const unsigned short* kvb = rep2h + (long)b * NCC * 256;

    const int tid = threadIdx.x, wid = tid >> 5, lane = tid & 31;
    const int g = lane >> 2, t4 = lane & 3;
    const int wm = wid & 1, wn = wid >> 1;
    const int c4h = (tid & 63) * 4, r0 = tid >> 6;

    const __half2 sc16 = __floats2half2_rn(0.0625f, 0.0625f);
#pragma unroll
    for (int p = 0; p < 16; p++) {
        int r = p * 4 + r0;
        uint2 u = *(const uint2*)(qb + (long)(m0 + r) * 256 + c4h);
        __half2 ha = __hmul2(*(__half2*)&u.x, sc16);
        __half2 hb = __hmul2(*(__half2*)&u.y, sc16);
        *(uint2*)&Qs[r * 132 + (c4h >> 1)] = make_uint2(*(unsigned*)&ha, *(unsigned*)&hb);
    }

    float l_part[2][2], acc_o[2][8][4];
#pragma unroll
    for (int mi = 0; mi < 2; mi++)
#pragma unroll
        for (int hf = 0; hf < 2; hf++) l_part[mi][hf] = 0.f;
#pragma unroll
    for (int mi = 0; mi < 2; mi++)
#pragma unroll
        for (int ni = 0; ni < 8; ni++)
#pragma unroll
            for (int c = 0; c < 4; c++) acc_o[mi][ni][c] = 0.f;

    for (int tk = 0; tk < 16; tk++) {
        __syncthreads();
#pragma unroll
        for (int p = 0; p < 8; p++) {
            int q = p * 4 + r0;
            uint2 e = *(const uint2*)(kvb + (long)(tk * 64 + 2 * q) * 256 + c4h);
            uint2 o = *(const uint2*)(kvb + (long)(tk * 64 + 2 * q + 1) * 256 + c4h);
            *(uint2*)&KVs[(2 * q) * 132 + (c4h >> 1)]     = e;
            *(uint2*)&KVs[(2 * q + 1) * 132 + (c4h >> 1)] = o;
            *(uint4*)&Vsc[q * 264 + c4h] = make_uint4(
                ilo(e.x, o.x), ihi(e.x, o.x), ilo(e.y, o.y), ihi(e.y, o.y));
        }
        __syncthreads();

        float s[2][2][4];
#pragma unroll
        for (int mi = 0; mi < 2; mi++)
#pragma unroll
            for (int ni = 0; ni < 2; ni++)
#pragma unroll
                for (int c = 0; c < 4; c++) s[mi][ni][c] = 0.f;
#pragma unroll
        for (int ks = 0; ks < 16; ks++) {
            int kb2 = ks * 8;
            unsigned af[2][4], bf[2][2];
#pragma unroll
            for (int mi = 0; mi < 2; mi++) {
                int ma = wm * 32 + mi * 16 + g;
                af[mi][0] = Qs[ma * 132 + kb2 + t4];
                af[mi][1] = Qs[(ma + 8) * 132 + kb2 + t4];
                af[mi][2] = Qs[ma * 132 + kb2 + t4 + 4];
                af[mi][3] = Qs[(ma + 8) * 132 + kb2 + t4 + 4];
            }
#pragma unroll
            for (int ni = 0; ni < 2; ni++) {
                int nb = wn * 16 + ni * 8 + g;
                bf[ni][0] = KVs[nb * 132 + kb2 + t4];
                bf[ni][1] = KVs[nb * 132 + kb2 + t4 + 4];
            }
#pragma unroll
            for (int mi = 0; mi < 2; mi++)
#pragma unroll
                for (int ni = 0; ni < 2; ni++)
                    mma16(s[mi][ni], af[mi], bf[ni]);
        }

        // exp + local l accumulation; write P
#pragma unroll
        for (int mi = 0; mi < 2; mi++) {
            int r = wm * 32 + mi * 16 + g;
#pragma unroll
            for (int ni = 0; ni < 2; ni++) {
                float p0 = __expf(s[mi][ni][0]);
                float p1 = __expf(s[mi][ni][1]);
                float p2 = __expf(s[mi][ni][2]);
                float p3 = __expf(s[mi][ni][3]);
                l_part[mi][0] += p0 + p1;
                l_part[mi][1] += p2 + p3;
                int c2 = wn * 8 + ni * 4 + t4;
                Psc[r * 36 + c2]       = h2p(p0, p1);
                Psc[(r + 8) * 36 + c2] = h2p(p2, p3);
            }
        }
        __syncthreads();

#pragma unroll
        for (int ks = 0; ks < 4; ks++) {
            int kb2 = ks * 8;
            unsigned af[2][4], bf[8][2];
#pragma unroll
            for (int mi = 0; mi < 2; mi++) {
                int ma = wm * 32 + mi * 16 + g;
                af[mi][0] = Psc[ma * 36 + kb2 + t4];
                af[mi][1] = Psc[(ma + 8) * 36 + kb2 + t4];
                af[mi][2] = Psc[ma * 36 + kb2 + t4 + 4];
                af[mi][3] = Psc[(ma + 8) * 36 + kb2 + t4 + 4];
            }
#pragma unroll
            for (int ni = 0; ni < 8; ni++) {
                int nb = wn * 64 + ni * 8 + g;
                bf[ni][0] = Vsc[(kb2 + t4) * 264 + nb];
                bf[ni][1] = Vsc[(kb2 + t4 + 4) * 264 + nb];
            }
#pragma unroll
            for (int mi = 0; mi < 2; mi++)
#pragma unroll
                for (int ni = 0; ni < 8; ni++)
                    mma16(acc_o[mi][ni], af[mi], bf[ni]);
        }
    }

    // ---- final l reduction ----
    __syncthreads();
#pragma unroll
    for (int mi = 0; mi < 2; mi++)
#pragma unroll
        for (int hf = 0; hf < 2; hf++) {
            float ls = l_part[mi][hf];
            ls += __shfl_xor_sync(0xffffffffu, ls, 1);
            ls += __shfl_xor_sync(0xffffffffu, ls, 2);
            if (t4 == 0) red[wn * 64 + wm * 32 + mi * 16 + hf * 8 + g] = ls;
        }
    __syncthreads();
    float l_run[2][2];
#pragma unroll
    for (int mi = 0; mi < 2; mi++)
#pragma unroll
        for (int hf = 0; hf < 2; hf++) {
            int r = wm * 32 + mi * 16 + hf * 8 + g;
            l_run[mi][hf] = red[r] + red[64 + r] + red[128 + r] + red[192 + r];
        }

#pragma unroll
    for (int mi = 0; mi < 2; mi++) {
        int row = m0 + wm * 32 + mi * 16 + g;
        float inv0 = 1.f / l_run[mi][0], inv1 = 1.f / l_run[mi][1];
#pragma unroll
        for (int ni = 0; ni < 8; ni++) {
            int col = wn * 64 + ni * 8 + t4 * 2;
            long o0 = ((long)b * NTT + row) * 256 + col;
            long o1 = ((long)b * NTT + row + 8) * 256 + col;
            *(unsigned*)&deth[o0] = h2p(acc_o[mi][ni][0] * inv0, acc_o[mi][ni][1] * inv0);
            *(unsigned*)&deth[o1] = h2p(acc_o[mi][ni][2] * inv1, acc_o[mi][ni][3] * inv1);
        }
    }
}

// ===================== small kernels =====================

__global__ void mean1_k(const float* __restrict__ h, float* __restrict__ part)
{
    int b = blockIdx.x, ch = blockIdx.y, j = threadIdx.x * 4;
    const float* p = h + (long)b * NCC * RD + (long)ch * 32 * RD + j;
    float4 s = make_float4(0.f, 0.f, 0.f, 0.f);
#pragma unroll 4
    for (int n = 0; n < 32; n++) {
        float4 v = *(const float4*)(p + (long)n * RD);
        s.x += v.x; s.y += v.y; s.z += v.z; s.w += v.w;
    }
    *(float4*)&part[(long)(b * 32 + ch) * RD + j] = s;
}

__global__ void mean2_k(const float* __restrict__ part, float* __restrict__ out)
{
    int b = blockIdx.x, j = threadIdx.x;
    float s = 0.f;
#pragma unroll
    for (int c = 0; c < 32; c++) s += part[(long)(b * 32 + c) * RD + j];
    out[b * RD + j] = s * (1.f / NCC);
}

__global__ void latent_k(const float* __restrict__ hmean,
                         const float* __restrict__ pw, const float* __restrict__ pb,
                         const float* __restrict__ mw, const float* __restrict__ mb,
                         const float* __restrict__ sw, const float* __restrict__ sb,
                         const float* __restrict__ eps, float* __restrict__ z)
{
    __shared__ float h2s[LHD];
    int b = blockIdx.x, tid = threadIdx.x;
    if (tid < LHD) {
        float s = pb[tid];
        const float* hm = hmean + b * RD;
        for (int k = 0; k < RD; k++) s += hm[k] * pw[k * LHD + tid];
        h2s[tid] = s;
    }
    __syncthreads();
    float mu = mb[tid], ls = sb[tid];
    for (int k = 0; k < LHD; k++) {
        mu += h2s[k] * mw[k * RD + tid];
        ls += h2s[k] * sw[k * RD + tid];
    }
    float sig = 0.9f / (1.f + expf(-ls)) + 0.1f;
    z[b * RD + tid] = mu + sig * eps[b * RD + tid];
}

// dec2 (K=128, N=16) fused with mu/sigma epilogue
__global__ void __launch_bounds__(256) dec2_k(
    const float* __restrict__ dh, const float* __restrict__ w2,
    const float* __restrict__ b2, float* __restrict__ out)
{
    __shared__ float w[128][17];
    __shared__ float a[16][132];
    int tid = threadIdx.x;
    for (int i = tid; i < 128 * 16; i += 256) { int k = i >> 4, c = i & 15; w[k][c] = w2[i]; }
    long row0 = (long)blockIdx.x * 16;
    for (int i = tid; i < 512; i += 256) {
        int r = i >> 5, c4 = (i & 31) * 4;
        *(float4*)&a[r][c4] = *(const float4*)&dh[(row0 + r) * 128 + c4];
    }
    __syncthreads();
    int r = tid >> 4, c = tid & 15;
    float s = b2[c];
#pragma unroll
    for (int k = 0; k < 128; k++) s += a[r][k] * w[k][c];
    long row = row0 + r;
    const long TOT = (long)BB * NTT * CTRLD;
    if (c < CTRLD) out[row * CTRLD + c] = s;
    else {
        float sp = fmaxf(s, 0.f) + log1pf(expf(-fabsf(s)));
        out[TOT + row * CTRLD + (c - CTRLD)] = 0.9f * sp + 0.1f;
    }
}

// ===================== host side =====================

static void* symv(const void* s) { void* p = nullptr; cudaGetSymbolAddress(&p, s); return p; }

extern "C" void kernel_launch(void* const* d_in, const int* in_sizes, int n_in,
                              void* d_out, int out_size)
{
    const float* context_x = (const float*)d_in[0];
    const float* context_y = (const float*)d_in[1];
    const float* target_x  = (const float*)d_in[2];
    const float* pred_ctrl = (const float*)d_in[3];
    const float* eps       = (const float*)d_in[4];
    const float* ce_w1 = (const float*)d_in[5];  const float* ce_b1 = (const float*)d_in[6];
    const float* ce_w2 = (const float*)d_in[7];  const float* ce_b2 = (const float*)d_in[8];
    const float* sa_in_w = (const float*)d_in[9];  const float* sa_in_b = (const float*)d_in[10];
    const float* sa_out_w = (const float*)d_in[11]; const float* sa_out_b = (const float*)d_in[12];
    const float* sa_ln_g = (const float*)d_in[13];  const float* sa_ln_b = (const float*)d_in[14];
    const float* qp_w = (const float*)d_in[15]; const float* qp_b = (const float*)d_in[16];
    const float* le_w1 = (const float*)d_in[17]; const float* le_b1 = (const float*)d_in[18];
    const float* le_w2 = (const float*)d_in[19]; const float* le_b2 = (const float*)d_in[20];
    const float* le_pw = (const float*)d_in[21]; const float* le_pb = (const float*)d_in[22];
    const float* le_mw = (const float*)d_in[23]; const float* le_mb = (const float*)d_in[24];
    const float* le_sw = (const float*)d_in[25]; const float* le_sb = (const float*)d_in[26];
    const float* dec_w1 = (const float*)d_in[27]; const float* dec_b1 = (const float*)d_in[28];
    const float* dec_w2 = (const float*)d_in[29]; const float* dec_b2 = (const float*)d_in[30];
    float* out = (float*)d_out;

    unsigned short* h12h  = (unsigned short*)symv(g_h12h);
    float* rep   = (float*)symv(g_rep);
    float* hle   = (float*)symv(g_hle);
    float* part  = (float*)symv(g_part);
    float* hmean = (float*)symv(g_hmean);
    float* z     = (float*)symv(g_z);
    unsigned short* qkvh   = (unsigned short*)symv(g_qkvh);
    unsigned short* attnoh = (unsigned short*)symv(g_attnoh);
    unsigned short* rep2h  = (unsigned short*)symv(g_rep2h);
    unsigned short* qth    = (unsigned short*)symv(g_qth);
    unsigned short* deth   = (unsigned short*)symv(g_deth);
    float* dh    = (float*)symv(g_dh);

    const int MC = BB * NCC;   // 16384
    const int MT = BB * NTT;   // 32768

    static cudaStream_t s2 = nullptr;
    static cudaEvent_t ev0 = nullptr, evA = nullptr, evB = nullptr, evC = nullptr;
    if (!s2) {
        cudaStreamCreateWithFlags(&s2, cudaStreamNonBlocking);
        cudaEventCreateWithFlags(&ev0, cudaEventDisableTiming);
        cudaEventCreateWithFlags(&evA, cudaEventDisableTiming);
        cudaEventCreateWithFlags(&evB, cudaEventDisableTiming);
        cudaEventCreateWithFlags(&evC, cudaEventDisableTiming);
    }

    cudaFuncSetAttribute(flash_self_k,  cudaFuncAttributeMaxDynamicSharedMemorySize, SELF_SMEM);
    cudaFuncSetAttribute(flash_cross_k, cudaFuncAttributeMaxDynamicSharedMemorySize, CROSS_SMEM);

    // legal fork: ev0 on capture stream BEFORE s2's first op
    cudaEventRecord(ev0, 0);
    cudaStreamWaitEvent(s2, ev0, 0);

    // qt (half out) on s2
    mma_gemm<32, 0, 0, 0, 1, 0><<<dim3(MT / 128, 2, 1), 256, 0, s2>>>(target_x, qp_w, qp_b, (float*)qth,
        MT, RD, GAPD, GAPD, RD, RD, 1.f, nullptr, nullptr, nullptr, nullptr, nullptr);
    cudaEventRecord(evC, s2);

    // merged MLP1 (le|ce) -> half
    mma_gemm<32, 1, 2, 1, 1, 0><<<dim3(MC / 128, 2, 1), 256>>>(nullptr, le_w1, le_b1, (float*)h12h,
        MC, 2 * HIDD, CIN, CIN, HIDD, 2 * HIDD, 1.f, context_y, context_x, nullptr,
        ce_w1, ce_b1);

    // fork: latent path on s2
    cudaEventRecord(evA, 0);
    cudaStreamWaitEvent(s2, evA, 0);
    mma_gemm<32, 0, 0, 0, 0, 1><<<dim3(MC / 128, 2, 1), 256, 0, s2>>>((const float*)h12h, le_w2, le_b2, hle,
        MC, RD, HIDD, 2 * HIDD, RD, RD, 1.f, nullptr, nullptr, nullptr, nullptr, nullptr);
    mean1_k<<<dim3(BB, 32), 64, 0, s2>>>(hle, part);
    mean2_k<<<BB, 256, 0, s2>>>(part, hmean);
    latent_k<<<BB, 256, 0, s2>>>(hmean, le_pw, le_pb, le_mw, le_mb, le_sw, le_sb, eps, z);
    cudaEventRecord(evB, s2);

    // deterministic path (A = ce half of h12h)
    mma_gemm<32, 0, 0, 0, 0, 1><<<dim3(MC / 128, 2, 1), 256>>>((const float*)(h12h + HIDD), ce_w2, ce_b2, rep,
        MC, RD, HIDD, 2 * HIDD, RD, RD, 1.f, nullptr, nullptr, nullptr, nullptr, nullptr);

    mma_gemm<32, 0, 0, 0, 1, 0><<<dim3(MC / 128, 6, 1), 256>>>(rep, sa_in_w, sa_in_b, (float*)qkvh,
        MC, 3 * RD, RD, RD, 3 * RD, 3 * RD, 1.f, nullptr, nullptr, nullptr, nullptr, nullptr);

    flash_self_k<<<dim3(NCC / 128, NHD, BB), 256, SELF_SMEM>>>(qkvh, attnoh);

    // fused oproj + residual + LN -> rep2h
    gemm_ln_k<<<MC / 128, 256>>>(attnoh, sa_out_w, sa_out_b, rep, sa_ln_g, sa_ln_b, rep2h);

    // cross attention (join qt)
    cudaStreamWaitEvent(0, evC, 0);
    flash_cross_k<<<dim3(NTT / 64, 1, BB), 256, CROSS_SMEM>>>(qth, rep2h, deth);

    // join latent path, then decoder (dec1 GEMM + dec2)
    cudaStreamWaitEvent(0, evB, 0);
    mma_gemm<32, 1, 1, 0, 0, 0><<<dim3(MT / 128, 1, 1), 256>>>((const float*)deth, dec_w1, dec_b1, dh,
        MT, HIDD, DIN, DIN, HIDD, HIDD, 1.f, z, target_x, pred_ctrl, nullptr, nullptr);
    dec2_k<<<MT / 16, 256>>>(dh, dec_w2, dec_b2, out);
}

// round 15
// speedup vs baseline: 1.6144x; 1.0032x over previous
#include <cuda_runtime.h>
#include <cuda_fp16.h>
#include <math.h>

// ---- problem dims ----
#define BB 16
#define NCC 1024
#define NTT 2048
#define GAPD 128
#define CTRLD 8
#define RD 256
#define NHD 4
#define HDD 64
#define HIDD 128
#define LHD 192
#define CIN (CTRLD + GAPD)          // 136
#define DIN (2 * RD + GAPD + CTRLD) // 648

// ---- scratch ----
__device__ unsigned short g_h12h [BB * NCC * 2 * HIDD];
__device__ float g_rep  [BB * NCC * RD];
__device__ float g_part [BB * 32 * HIDD];
__device__ float g_hm1  [BB * HIDD];
__device__ float g_z    [BB * RD];
__device__ unsigned short g_qkvh [BB * NCC * 3 * RD];
__device__ unsigned short g_attnoh[BB * NCC * RD];
__device__ unsigned short g_rep2h[BB * NCC * RD];
__device__ unsigned short g_qth  [(size_t)BB * NTT * RD];
__device__ unsigned short g_deth [(size_t)BB * NTT * RD];
__device__ float g_dh   [BB * NTT * HIDD];

// ===================== fp16 mma helpers =====================
__device__ __forceinline__ unsigned h2p(float a, float b) {
    __half2 h = __floats2half2_rn(a, b);
    return *reinterpret_cast<unsigned*>(&h);
}
__device__ __forceinline__ void mma16(float* d, const unsigned* a, const unsigned* b) {
    asm volatile(
        "mma.sync.aligned.m16n8k16.row.col.f32.f16.f16.f32 "
        "{%0,%1,%2,%3},{%4,%5,%6,%7},{%8,%9},{%0,%1,%2,%3};\n"
        : "+f"(d[0]), "+f"(d[1]), "+f"(d[2]), "+f"(d[3])
        : "r"(a[0]), "r"(a[1]), "r"(a[2]), "r"(a[3]), "r"(b[0]), "r"(b[1]));
}
__device__ __forceinline__ float4 ld_guard(const float* src, int gk, int K) {
    if (gk + 4 <= K) return *(const float4*)src;
    float4 v = make_float4(0.f, 0.f, 0.f, 0.f);
    if (gk     < K) v.x = src[0];
    if (gk + 1 < K) v.y = src[1];
    if (gk + 2 < K) v.z = src[2];
    if (gk + 3 < K) v.w = src[3];
    return v;
}
__device__ __forceinline__ unsigned ilo(unsigned a, unsigned b) { return __byte_perm(a, b, 0x5410); }
__device__ __forceinline__ unsigned ihi(unsigned a, unsigned b) { return __byte_perm(a, b, 0x7632); }

// ===================== fp16 GEMM (reg-pipelined), B = [K,N] row-major ====
#define XBM 128
#define XBK 32

// MODE 0: plain A. MODE 1: A = [deth(half) | z | tx | pc], K=DIN. MODE 2: A = [cy | cx], K=CIN.
// HA 1: A is half (MODE 0). BMODE 1: B cols split B/B2. OUTH 1: C half.
template<int WNT, int ACT, int MODE, int BMODE, int OUTH, int HA>
__global__ void __launch_bounds__(256) mma_gemm(
    const float* __restrict__ A, const float* __restrict__ B,
    const float* __restrict__ bias, float* __restrict__ C,
    int M, int N, int K, int lda, int ldb, int ldc,
    float alpha,
    const float* __restrict__ zt, const float* __restrict__ txt,
    const float* __restrict__ pct,
    const float* __restrict__ B2, const float* __restrict__ bias2)
{
    constexpr int XBN_ = WNT * 4;
    constexpr int NI = WNT / 8;

    __shared__ unsigned As2[XBM][20];
    __shared__ unsigned Bs2[XBK / 2][XBN_ + 8];

    int tid = threadIdx.x;
    int wid = tid >> 5, lane = tid & 31;
    int g = lane >> 2, t4 = lane & 3;
    int wm = wid & 1, wn = wid >> 1;
    int m0 = blockIdx.x * XBM, n0 = blockIdx.y * XBN_;

    float acc[4][NI][4];
#pragma unroll
    for (int i = 0; i < 4; i++)
#pragma unroll
        for (int j = 0; j < NI; j++)
#pragma unroll
            for (int l = 0; l < 4; l++) acc[i][j][l] = 0.f;

    float4 ra[4]; uint2 rah[4];
    float4 rbE[2], rbO[2];
    constexpr int C4  = XBN_ / 4;
    constexpr int RP2 = 256 / C4;
    constexpr int ITS2 = (XBK / 2) / RP2;

    const int ac = (tid & 7) * 4;
    const int ar = tid >> 3;
    const int bc4 = tid % C4;
    const int brb = tid / C4;

    auto loadA = [&](int k0) {
        int gk = k0 + ac;
#pragma unroll
        for (int p = 0; p < 4; p++) {
            int gm = m0 + p * 32 + ar;
            if (MODE == 1) {
                if (gk < RD) {
                    rah[p] = *(const uint2*)((const unsigned short*)A + (long)gm * RD + gk);
                } else {
                    const float* s;
                    if (gk < 2 * RD)             s = zt  + (long)(gm >> 11) * RD + (gk - RD);
                    else if (gk < 2 * RD + GAPD) s = txt + (long)gm * GAPD + (gk - 2 * RD);
                    else if (gk < DIN)           s = pct + (long)gm * CTRLD + (gk - 2 * RD - GAPD);
                    else                         s = nullptr;
                    ra[p] = s ? *(const float4*)s : make_float4(0.f, 0.f, 0.f, 0.f);
                }
            } else if (MODE == 2) {
                const float* s;
                if (gk < CTRLD)    s = zt  + (long)gm * CTRLD + gk;
                else if (gk < CIN) s = txt + (long)gm * GAPD + (gk - CTRLD);
                else               s = nullptr;
                ra[p] = s ? *(const float4*)s : make_float4(0.f, 0.f, 0.f, 0.f);
            } else if (HA) {
                const unsigned short* Ah = (const unsigned short*)A;
                rah[p] = (gk + 4 <= K) ? *(const uint2*)(Ah + (long)gm * lda + gk)
                                       : make_uint2(0u, 0u);
            } else {
                ra[p] = ld_guard(A + (long)gm * lda + gk, gk, K);
            }
        }
    };
    auto loadB = [&](int k0) {
        int gn = n0 + bc4 * 4;
#pragma unroll
        for (int it = 0; it < ITS2; it++) {
            int kp = k0 + (it * RP2 + brb) * 2;
            if (BMODE == 1) {
                const float* base0 = (gn < HIDD) ? B : B2;
                int gq = (gn < HIDD) ? gn : gn - HIDD;
                rbE[it] = (kp     < K) ? *(const float4*)(base0 + (long)kp * ldb + gq)
                                       : make_float4(0.f, 0.f, 0.f, 0.f);
                rbO[it] = (kp + 1 < K) ? *(const float4*)(base0 + (long)(kp + 1) * ldb + gq)
                                       : make_float4(0.f, 0.f, 0.f, 0.f);
            } else {
                bool okn = (gn + 3 < N);
                rbE[it] = (kp     < K && okn) ? *(const float4*)(B + (long)kp * ldb + gn)
                                              : make_float4(0.f, 0.f, 0.f, 0.f);
                rbO[it] = (kp + 1 < K && okn) ? *(const float4*)(B + (long)(kp + 1) * ldb + gn)
                                              : make_float4(0.f, 0.f, 0.f, 0.f);
            }
        }
    };
    auto stsAB = [&](int k0) {
        int gk = k0 + ac;
#pragma unroll
        for (int p = 0; p < 4; p++) {
            if ((MODE == 1 && gk < RD) || (HA && MODE == 0)) {
                *(uint2*)&As2[p * 32 + ar][ac >> 1] = rah[p];
            } else {
                uint2 u = make_uint2(h2p(ra[p].x, ra[p].y), h2p(ra[p].z, ra[p].w));
                *(uint2*)&As2[p * 32 + ar][ac >> 1] = u;
            }
        }
#pragma unroll
        for (int it = 0; it < ITS2; it++) {
            uint4 u = make_uint4(h2p(rbE[it].x, rbO[it].x), h2p(rbE[it].y, rbO[it].y),
                                 h2p(rbE[it].z, rbO[it].z), h2p(rbE[it].w, rbO[it].w));
            *(uint4*)&Bs2[it * RP2 + brb][bc4 * 4] = u;
        }
    };

    int kT = (K + XBK - 1) / XBK;
    loadA(0); loadB(0);

    for (int t = 0; t < kT; t++) {
        stsAB(t * XBK);
        __syncthreads();
        if (t + 1 < kT) { loadA((t + 1) * XBK); loadB((t + 1) * XBK); }
#pragma unroll
        for (int ks = 0; ks < 2; ks++) {
            int kb2 = ks * 8;
            unsigned af[4][4], bf[NI][2];
#pragma unroll
            for (int mi = 0; mi < 4; mi++) {
                int ma = wm * 64 + mi * 16 + g;
                af[mi][0] = As2[ma    ][kb2 + t4];
                af[mi][1] = As2[ma + 8][kb2 + t4];
                af[mi][2] = As2[ma    ][kb2 + t4 + 4];
                af[mi][3] = As2[ma + 8][kb2 + t4 + 4];
            }
#pragma unroll
            for (int ni = 0; ni < NI; ni++) {
                int nb = wn * WNT + ni * 8 + g;
                bf[ni][0] = Bs2[kb2 + t4    ][nb];
                bf[ni][1] = Bs2[kb2 + t4 + 4][nb];
            }
#pragma unroll
            for (int mi = 0; mi < 4; mi++)
#pragma unroll
                for (int ni = 0; ni < NI; ni++)
                    mma16(acc[mi][ni], af[mi], bf[ni]);
        }
        __syncthreads();
    }

#pragma unroll
    for (int mi = 0; mi < 4; mi++) {
        int gm = m0 + wm * 64 + mi * 16 + g;
#pragma unroll
        for (int ni = 0; ni < NI; ni++) {
            int gn = n0 + wn * WNT + ni * 8 + t4 * 2;
            if (gn >= N) continue;
            float b0, b1;
            if (BMODE == 1) {
                const float* bp = (gn < HIDD) ? bias : bias2;
                int gq = (gn < HIDD) ? gn : gn - HIDD;
                b0 = bp[gq]; b1 = bp[gq + 1];
            } else {
                b0 = bias ? bias[gn] : 0.f;
                b1 = bias ? bias[gn + 1] : 0.f;
            }
            float v0 = acc[mi][ni][0] * alpha + b0;
            float v1 = acc[mi][ni][1] * alpha + b1;
            float v2 = acc[mi][ni][2] * alpha + b0;
            float v3 = acc[mi][ni][3] * alpha + b1;
            if (ACT == 1) {
                v0 = fmaxf(v0, 0.f); v1 = fmaxf(v1, 0.f);
                v2 = fmaxf(v2, 0.f); v3 = fmaxf(v3, 0.f);
            }
            if (OUTH) {
                unsigned short* Ch = (unsigned short*)C;
                *(unsigned*)&Ch[(long)gm * ldc + gn]       = h2p(v0, v1);
                *(unsigned*)&Ch[(long)(gm + 8) * ldc + gn] = h2p(v2, v3);
            } else {
                *(float2*)&C[(long)gm * ldc + gn]       = make_float2(v0, v1);
                *(float2*)&C[(long)(gm + 8) * ldc + gn] = make_float2(v2, v3);
            }
        }
    }
}

// ===================== fused oproj GEMM + residual + LayerNorm =====================
__global__ void __launch_bounds__(256) gemm_ln_k(
    const unsigned short* __restrict__ Ah, const float* __restrict__ B,
    const float* __restrict__ bias, const float* __restrict__ resid,
    const float* __restrict__ lng, const float* __restrict__ lnb,
    unsigned short* __restrict__ outh)
{
    __shared__ unsigned As2[128][20];
    __shared__ unsigned Bs2[16][264];
    __shared__ float red[512];

    const int K = RD;
    int tid = threadIdx.x;
    int wid = tid >> 5, lane = tid & 31;
    int g = lane >> 2, t4 = lane & 3;
    int wm = wid & 1, wn = wid >> 1;
    int m0 = blockIdx.x * 128;

    float acc[4][8][4];
#pragma unroll
    for (int i = 0; i < 4; i++)
#pragma unroll
        for (int j = 0; j < 8; j++)
#pragma unroll
            for (int l = 0; l < 4; l++) acc[i][j][l] = 0.f;

    uint2 rah[4];
    float4 rbE[4], rbO[4];
    const int ac = (tid & 7) * 4;
    const int ar = tid >> 3;
    const int bc4 = tid & 63;
    const int brb = tid >> 6;

    auto loadA = [&](int k0) {
        int gk = k0 + ac;
#pragma unroll
        for (int p = 0; p < 4; p++)
            rah[p] = *(const uint2*)(Ah + (long)(m0 + p * 32 + ar) * RD + gk);
    };
    auto loadB = [&](int k0) {
#pragma unroll
        for (int it = 0; it < 4; it++) {
            int kp = k0 + (it * 4 + brb) * 2;
            rbE[it] = *(const float4*)(B + (long)kp * RD + bc4 * 4);
            rbO[it] = *(const float4*)(B + (long)(kp + 1) * RD + bc4 * 4);
        }
    };
    auto stsAB = [&]() {
#pragma unroll
        for (int p = 0; p < 4; p++)
            *(uint2*)&As2[p * 32 + ar][ac >> 1] = rah[p];
#pragma unroll
        for (int it = 0; it < 4; it++) {
            uint4 u = make_uint4(h2p(rbE[it].x, rbO[it].x), h2p(rbE[it].y, rbO[it].y),
                                 h2p(rbE[it].z, rbO[it].z), h2p(rbE[it].w, rbO[it].w));
            *(uint4*)&Bs2[it * 4 + brb][bc4 * 4] = u;
        }
    };

    loadA(0); loadB(0);
    for (int t = 0; t < K / XBK; t++) {
        stsAB();
        __syncthreads();
        if (t + 1 < K / XBK) { loadA((t + 1) * XBK); loadB((t + 1) * XBK); }
#pragma unroll
        for (int ks = 0; ks < 2; ks++) {
            int kb2 = ks * 8;
            unsigned af[4][4], bf[8][2];
#pragma unroll
            for (int mi = 0; mi < 4; mi++) {
                int ma = wm * 64 + mi * 16 + g;
                af[mi][0] = As2[ma    ][kb2 + t4];
                af[mi][1] = As2[ma + 8][kb2 + t4];
                af[mi][2] = As2[ma    ][kb2 + t4 + 4];
                af[mi][3] = As2[ma + 8][kb2 + t4 + 4];
            }
#pragma unroll
            for (int ni = 0; ni < 8; ni++) {
                int nb = wn * 64 + ni * 8 + g;
                bf[ni][0] = Bs2[kb2 + t4    ][nb];
                bf[ni][1] = Bs2[kb2 + t4 + 4][nb];
            }
#pragma unroll
            for (int mi = 0; mi < 4; mi++)
#pragma unroll
                for (int ni = 0; ni < 8; ni++)
                    mma16(acc[mi][ni], af[mi], bf[ni]);
        }
        __syncthreads();
    }

#pragma unroll
    for (int mi = 0; mi < 4; mi++) {
        int gr = m0 + wm * 64 + mi * 16 + g;
#pragma unroll
        for (int ni = 0; ni < 8; ni++) {
            int col = wn * 64 + ni * 8 + t4 * 2;
            float2 r0 = *(const float2*)&resid[(long)gr * RD + col];
            float2 r1 = *(const float2*)&resid[(long)(gr + 8) * RD + col];
            float b0 = bias[col], b1 = bias[col + 1];
            acc[mi][ni][0] += b0 + r0.x; acc[mi][ni][1] += b1 + r0.y;
            acc[mi][ni][2] += b0 + r1.x; acc[mi][ni][3] += b1 + r1.y;
        }
    }

    float mean[4][2];
#pragma unroll
    for (int mi = 0; mi < 4; mi++)
#pragma unroll
        for (int hf = 0; hf < 2; hf++) {
            float s = 0.f;
#pragma unroll
            for (int ni = 0; ni < 8; ni++) s += acc[mi][ni][hf * 2] + acc[mi][ni][hf * 2 + 1];
            s += __shfl_xor_sync(0xffffffffu, s, 1);
            s += __shfl_xor_sync(0xffffffffu, s, 2);
            if (t4 == 0) red[wn * 128 + wm * 64 + mi * 16 + hf * 8 + g] = s;
        }
    __syncthreads();
#pragma unroll
    for (int mi = 0; mi < 4; mi++)
#pragma unroll
        for (int hf = 0; hf < 2; hf++) {
            int r = wm * 64 + mi * 16 + hf * 8 + g;
            mean[mi][hf] = (red[r] + red[128 + r] + red[256 + r] + red[384 + r]) * (1.f / RD);
        }
    __syncthreads();

    float inv[4][2];
#pragma unroll
    for (int mi = 0; mi < 4; mi++)
#pragma unroll
        for (int hf = 0; hf < 2; hf++) {
            float s = 0.f;
#pragma unroll
            for (int ni = 0; ni < 8; ni++) {
                float d0 = acc[mi][ni][hf * 2]     - mean[mi][hf];
                float d1 = acc[mi][ni][hf * 2 + 1] - mean[mi][hf];
                s += d0 * d0 + d1 * d1;
            }
            s += __shfl_xor_sync(0xffffffffu, s, 1);
            s += __shfl_xor_sync(0xffffffffu, s, 2);
            if (t4 == 0) red[wn * 128 + wm * 64 + mi * 16 + hf * 8 + g] = s;
        }
    __syncthreads();
#pragma unroll
    for (int mi = 0; mi < 4; mi++)
#pragma unroll
        for (int hf = 0; hf < 2; hf++) {
            int r = wm * 64 + mi * 16 + hf * 8 + g;
            float var = (red[r] + red[128 + r] + red[256 + r] + red[384 + r]) * (1.f / RD);
            inv[mi][hf] = rsqrtf(var + 1e-5f);
        }

#pragma unroll
    for (int mi = 0; mi < 4; mi++) {
        int gr = m0 + wm * 64 + mi * 16 + g;
#pragma unroll
        for (int ni = 0; ni < 8; ni++) {
            int col = wn * 64 + ni * 8 + t4 * 2;
            float g0 = lng[col], g1 = lng[col + 1];
            float c0 = lnb[col], c1 = lnb[col + 1];
            float v0 = (acc[mi][ni][0] - mean[mi][0]) * inv[mi][0] * g0 + c0;
            float v1 = (acc[mi][ni][1] - mean[mi][0]) * inv[mi][0] * g1 + c1;
            float v2 = (acc[mi][ni][2] - mean[mi][1]) * inv[mi][1] * g0 + c0;
            float v3 = (acc[mi][ni][3] - mean[mi][1]) * inv[mi][1] * g1 + c1;
            *(unsigned*)&outh[(long)gr * RD + col]       = h2p(v0, v1);
            *(unsigned*)&outh[(long)(gr + 8) * RD + col] = h2p(v2, v3);
        }
    }
}

// ===================== flash self-attention (deferred l-reduction) ====
#define SELF_SMEM (23040 * 4)

__global__ void __launch_bounds__(256, 2) flash_self_k(
    const unsigned short* __restrict__ qkvh, unsigned short* __restrict__ attnoh)
{
    extern __shared__ unsigned smu[];
    unsigned* Qs = smu;
    unsigned* Ks = smu + 4608;
    unsigned* Vs = smu + 9216;
    unsigned* Ps = smu + 13824;
    float*    red = (float*)(smu + 22528);

    const int b = blockIdx.z, h = blockIdx.y;
    const int m0 = blockIdx.x * 128;
    const unsigned short* base = qkvh + (long)b * NCC * 768;
    const unsigned short* qp = base + h * 64;
    const unsigned short* kp = base + 256 + h * 64;
    const unsigned short* vp = base + 512 + h * 64;

    const int tid = threadIdx.x, wid = tid >> 5, lane = tid & 31;
    const int g = lane >> 2, t4 = lane & 3;
    const int wm = wid & 1, wn = wid >> 1;
    const int c4h = (tid & 15) * 4, r0 = tid >> 4;

    const __half2 sc8 = __floats2half2_rn(0.125f, 0.125f);
#pragma unroll
    for (int p = 0; p < 8; p++) {
        int r = p * 16 + r0;
        uint2 u = *(const uint2*)(qp + (long)(m0 + r) * 768 + c4h);
        __half2 ha = __hmul2(*(__half2*)&u.x, sc8);
        __half2 hb = __hmul2(*(__half2*)&u.y, sc8);
        *(uint2*)&Qs[r * 36 + (c4h >> 1)] = make_uint2(*(unsigned*)&ha, *(unsigned*)&hb);
    }

    float l_part[4][2], acc_o[4][2][4];
#pragma unroll
    for (int mi = 0; mi < 4; mi++)
#pragma unroll
        for (int hf = 0; hf < 2; hf++) l_part[mi][hf] = 0.f;
#pragma unroll
    for (int mi = 0; mi < 4; mi++)
#pragma unroll
        for (int ni = 0; ni < 2; ni++)
#pragma unroll
            for (int c = 0; c < 4; c++) acc_o[mi][ni][c] = 0.f;

    for (int tk = 0; tk < 8; tk++) {
        __syncthreads();
#pragma unroll
        for (int p = 0; p < 8; p++) {
            int r = p * 16 + r0;
            *(uint2*)&Ks[r * 36 + (c4h >> 1)] =
                *(const uint2*)(kp + (long)(tk * 128 + r) * 768 + c4h);
        }
#pragma unroll
        for (int p = 0; p < 4; p++) {
            int q = p * 16 + r0;
            uint2 e = *(const uint2*)(vp + (long)(tk * 128 + 2 * q) * 768 + c4h);
            uint2 o = *(const uint2*)(vp + (long)(tk * 128 + 2 * q + 1) * 768 + c4h);
            *(uint4*)&Vs[q * 72 + c4h] = make_uint4(
                ilo(e.x, o.x), ihi(e.x, o.x), ilo(e.y, o.y), ihi(e.y, o.y));
        }
        __syncthreads();

        float s[4][4][4];
#pragma unroll
        for (int mi = 0; mi < 4; mi++)
#pragma unroll
            for (int ni = 0; ni < 4; ni++)
#pragma unroll
                for (int c = 0; c < 4; c++) s[mi][ni][c] = 0.f;
#pragma unroll
        for (int ks = 0; ks < 4; ks++) {
            int kb2 = ks * 8;
            unsigned af[4][4], bf[4][2];
#pragma unroll
            for (int mi = 0; mi < 4; mi++) {
                int ma = wm * 64 + mi * 16 + g;
                af[mi][0] = Qs[ma * 36 + kb2 + t4];
                af[mi][1] = Qs[(ma + 8) * 36 + kb2 + t4];
                af[mi][2] = Qs[ma * 36 + kb2 + t4 + 4];
                af[mi][3] = Qs[(ma + 8) * 36 + kb2 + t4 + 4];
            }
#pragma unroll
            for (int ni = 0; ni < 4; ni++) {
                int nb = wn * 32 + ni * 8 + g;
                bf[ni][0] = Ks[nb * 36 + kb2 + t4];
                bf[ni][1] = Ks[nb * 36 + kb2 + t4 + 4];
            }
#pragma unroll
            for (int mi = 0; mi < 4; mi++)
#pragma unroll
                for (int ni = 0; ni < 4; ni++)
                    mma16(s[mi][ni], af[mi], bf[ni]);
        }

#pragma unroll
        for (int mi = 0; mi < 4; mi++) {
            int r = wm * 64 + mi * 16 + g;
#pragma unroll
            for (int ni = 0; ni < 4; ni++) {
                float p0 = __expf(s[mi][ni][0]);
                float p1 = __expf(s[mi][ni][1]);
                float p2 = __expf(s[mi][ni][2]);
                float p3 = __expf(s[mi][ni][3]);
                l_part[mi][0] += p0 + p1;
                l_part[mi][1] += p2 + p3;
                int c2 = wn * 16 + ni * 4 + t4;
                Ps[r * 68 + c2]       = h2p(p0, p1);
                Ps[(r + 8) * 68 + c2] = h2p(p2, p3);
            }
        }
        __syncthreads();

#pragma unroll
        for (int ks = 0; ks < 8; ks++) {
            int kb2 = ks * 8;
            unsigned af[4][4], bf[2][2];
#pragma unroll
            for (int mi = 0; mi < 4; mi++) {
                int ma = wm * 64 + mi * 16 + g;
                af[mi][0] = Ps[ma * 68 + kb2 + t4];
                af[mi][1] = Ps[(ma + 8) * 68 + kb2 + t4];
                af[mi][2] = Ps[ma * 68 + kb2 + t4 + 4];
                af[mi][3] = Ps[(ma + 8) * 68 + kb2 + t4 + 4];
            }
#pragma unroll
            for (int ni = 0; ni < 2; ni++) {
                int nb = wn * 16 + ni * 8 + g;
                bf[ni][0] = Vs[(kb2 + t4) * 72 + nb];
                bf[ni][1] = Vs[(kb2 + t4 + 4) * 72 + nb];
            }
#pragma unroll
            for (int mi = 0; mi < 4; mi++)
#pragma unroll
                for (int ni = 0; ni < 2; ni++)
                    mma16(acc_o[mi][ni], af[mi], bf[ni]);
        }
    }

    __syncthreads();
#pragma unroll
    for (int mi = 0; mi < 4; mi++)
#pragma unroll
        for (int hf = 0; hf < 2; hf++) {
            float ls = l_part[mi][hf];
            ls += __shfl_xor_sync(0xffffffffu, ls, 1);
            ls += __shfl_xor_sync(0xffffffffu, ls, 2);
            if (t4 == 0) red[wn * 128 + wm * 64 + mi * 16 + hf * 8 + g] = ls;
        }
    __syncthreads();
    float l_run[4][2];
#pragma unroll
    for (int mi = 0; mi < 4; mi++)
#pragma unroll
        for (int hf = 0; hf < 2; hf++) {
            int r = wm * 64 + mi * 16 + hf * 8 + g;
            l_run[mi][hf] = red[r] + red[128 + r] + red[256 + r] + red[384 + r];
        }

#pragma unroll
    for (int mi = 0; mi < 4; mi++) {
        int row = m0 + wm * 64 + mi * 16 + g;
        float inv0 = 1.f / l_run[mi][0], inv1 = 1.f / l_run[mi][1];
#pragma unroll
        for (int ni = 0; ni < 2; ni++) {
            int col = h * 64 + wn * 16 + ni * 8 + t4 * 2;
            long o0 = ((long)b * NCC + row) * 256 + col;
            long o1 = ((long)b * NCC + row + 8) * 256 + col;
            *(unsigned*)&attnoh[o0] = h2p(acc_o[mi][ni][0] * inv0, acc_o[mi][ni][1] * inv0);
            *(unsigned*)&attnoh[o1] = h2p(acc_o[mi][ni][2] * inv1, acc_o[mi][ni][3] * inv1);
        }
    }
}

// ===================== flash cross-attention (deferred l-reduction) ====
#define CROSS_SMEM (27904 * 4)

__global__ void __launch_bounds__(256, 2) flash_cross_k(
    const unsigned short* __restrict__ qth, const unsigned short* __restrict__ rep2h,
    unsigned short* __restrict__ deth)
{
    extern __shared__ unsigned smu[];
    unsigned* Qs  = smu;
    unsigned* KVs = smu + 8448;
    unsigned* Vsc = smu + 16896;
    unsigned* Psc = smu + 25344;
    float*    red = (float*)(smu + 27648);

    const int b = blockIdx.z;
    const int m0 = blockIdx.x * 64;
    const unsigned short* qb  = qth   + (long)b * NTT * 256;
    const unsigned short* kvb = rep2h + (long)b * NCC * 256;

    const int tid = threadIdx.x, wid = tid >> 5, lane = tid & 31;
    const int g = lane >> 2, t4 = lane & 3;
    const int wm = wid & 1, wn = wid >> 1;
    const int c4h = (tid & 63) * 4, r0 = tid >> 6;

    const __half2 sc16 = __floats2half2_rn(0.0625f, 0.0625f);
#pragma unroll
    for (int p = 0; p < 16; p++) {
        int r = p * 4 + r0;
        uint2 u = *(const uint2*)(qb + (long)(m0 + r) * 256 + c4h);
        __half2 ha = __hmul2(*(__half2*)&u.x, sc16);
        __half2 hb = __hmul2(*(__half2*)&u.y, sc16);
        *(uint2*)&Qs[r * 132 + (c4h >> 1)] = make_uint2(*(unsigned*)&ha, *(unsigned*)&hb);
    }

    float l_part[2][2], acc_o[2][8][4];
#pragma unroll
    for (int mi = 0; mi < 2; mi++)
#pragma unroll
        for (int hf = 0; hf < 2; hf++) l_part[mi][hf] = 0.f;
#pragma unroll
    for (int mi = 0; mi < 2; mi++)
#pragma unroll
        for (int ni = 0; ni < 8; ni++)
#pragma unroll
            for (int c = 0; c < 4; c++) acc_o[mi][ni][c] = 0.f;

    for (int tk = 0; tk < 16; tk++) {
        __syncthreads();
#pragma unroll
        for (int p = 0; p < 8; p++) {
            int q = p * 4 + r0;
            uint2 e = *(const uint2*)(kvb + (long)(tk * 64 + 2 * q) * 256 + c4h);
            uint2 o = *(const uint2*)(kvb + (long)(tk * 64 + 2 * q + 1) * 256 + c4h);
            *(uint2*)&KVs[(2 * q) * 132 + (c4h >> 1)]     = e;
            *(uint2*)&KVs[(2 * q + 1) * 132 + (c4h >> 1)] = o;
            *(uint4*)&Vsc[q * 264 + c4h] = make_uint4(
                ilo(e.x, o.x), ihi(e.x, o.x), ilo(e.y, o.y), ihi(e.y, o.y));
        }
        __syncthreads();

        float s[2][2][4];
#pragma unroll
        for (int mi = 0; mi < 2; mi++)
#pragma unroll
            for (int ni = 0; ni < 2; ni++)
#pragma unroll
                for (int c = 0; c < 4; c++) s[mi][ni][c] = 0.f;
#pragma unroll
        for (int ks = 0; ks < 16; ks++) {
            int kb2 = ks * 8;
            unsigned af[2][4], bf[2][2];
#pragma unroll
            for (int mi = 0; mi < 2; mi++) {
                int ma = wm * 32 + mi * 16 + g;
                af[mi][0] = Qs[ma * 132 + kb2 + t4];
                af[mi][1] = Qs[(ma + 8) * 132 + kb2 + t4];
                af[mi][2] = Qs[ma * 132 + kb2 + t4 + 4];
                af[mi][3] = Qs[(ma + 8) * 132 + kb2 + t4 + 4];
            }
#pragma unroll
            for (int ni = 0; ni < 2; ni++) {
                int nb = wn * 16 + ni * 8 + g;
                bf[ni][0] = KVs[nb * 132 + kb2 + t4];
                bf[ni][1] = KVs[nb * 132 + kb2 + t4 + 4];
            }
#pragma unroll
            for (int mi = 0; mi < 2; mi++)
#pragma unroll
                for (int ni = 0; ni < 2; ni++)
                    mma16(s[mi][ni], af[mi], bf[ni]);
        }

#pragma unroll
        for (int mi = 0; mi < 2; mi++) {
            int r = wm * 32 + mi * 16 + g;
#pragma unroll
            for (int ni = 0; ni < 2; ni++) {
                float p0 = __expf(s[mi][ni][0]);
                float p1 = __expf(s[mi][ni][1]);
                float p2 = __expf(s[mi][ni][2]);
                float p3 = __expf(s[mi][ni][3]);
                l_part[mi][0] += p0 + p1;
                l_part[mi][1] += p2 + p3;
                int c2 = wn * 8 + ni * 4 + t4;
                Psc[r * 36 + c2]       = h2p(p0, p1);
                Psc[(r + 8) * 36 + c2] = h2p(p2, p3);
            }
        }
        __syncthreads();

#pragma unroll
        for (int ks = 0; ks < 4; ks++) {
            int kb2 = ks * 8;
            unsigned af[2][4], bf[8][2];
#pragma unroll
            for (int mi = 0; mi < 2; mi++) {
                int ma = wm * 32 + mi * 16 + g;
                af[mi][0] = Psc[ma * 36 + kb2 + t4];
                af[mi][1] = Psc[(ma + 8) * 36 + kb2 + t4];
                af[mi][2] = Psc[ma * 36 + kb2 + t4 + 4];
                af[mi][3] = Psc[(ma + 8) * 36 + kb2 + t4 + 4];
            }
#pragma unroll
            for (int ni = 0; ni < 8; ni++) {
                int nb = wn * 64 + ni * 8 + g;
                bf[ni][0] = Vsc[(kb2 + t4) * 264 + nb];
                bf[ni][1] = Vsc[(kb2 + t4 + 4) * 264 + nb];
            }
#pragma unroll
            for (int mi = 0; mi < 2; mi++)
#pragma unroll
                for (int ni = 0; ni < 8; ni++)
                    mma16(acc_o[mi][ni], af[mi], bf[ni]);
        }
    }

    __syncthreads();
#pragma unroll
    for (int mi = 0; mi < 2; mi++)
#pragma unroll
        for (int hf = 0; hf < 2; hf++) {
            float ls = l_part[mi][hf];
            ls += __shfl_xor_sync(0xffffffffu, ls, 1);
            ls += __shfl_xor_sync(0xffffffffu, ls, 2);
            if (t4 == 0) red[wn * 64 + wm * 32 + mi * 16 + hf * 8 + g] = ls;
        }
    __syncthreads();
    float l_run[2][2];
#pragma unroll
    for (int mi = 0; mi < 2; mi++)
#pragma unroll
        for (int hf = 0; hf < 2; hf++) {
            int r = wm * 32 + mi * 16 + hf * 8 + g;
            l_run[mi][hf] = red[r] + red[64 + r] + red[128 + r] + red[192 + r];
        }

#pragma unroll
    for (int mi = 0; mi < 2; mi++) {
        int row = m0 + wm * 32 + mi * 16 + g;
        float inv0 = 1.f / l_run[mi][0], inv1 = 1.f / l_run[mi][1];
#pragma unroll
        for (int ni = 0; ni < 8; ni++) {
            int col = wn * 64 + ni * 8 + t4 * 2;
            long o0 = ((long)b * NTT + row) * 256 + col;
            long o1 = ((long)b * NTT + row + 8) * 256 + col;
            *(unsigned*)&deth[o0] = h2p(acc_o[mi][ni][0] * inv0, acc_o[mi][ni][1] * inv0);
            *(unsigned*)&deth[o1] = h2p(acc_o[mi][ni][2] * inv1, acc_o[mi][ni][3] * inv1);
        }
    }
}

// ===================== small kernels =====================

// partial mean of h12h le-half (cols 0..127, half) over 32-row chunks
__global__ void mean1h_k(const unsigned short* __restrict__ h12h, float* __restrict__ part)
{
    int b = blockIdx.x, ch = blockIdx.y, j = threadIdx.x * 4;  // 32 threads
    const unsigned short* p = h12h + ((long)b * NCC + ch * 32) * 256 + j;
    float4 s = make_float4(0.f, 0.f, 0.f, 0.f);
#pragma unroll 4
    for (int n = 0; n < 32; n++) {
        uint2 u = *(const uint2*)(p + (long)n * 256);
        __half2 a = *(__half2*)&u.x, c = *(__half2*)&u.y;
        s.x += __low2float(a); s.y += __high2float(a);
        s.z += __low2float(c); s.w += __high2float(c);
    }
    *(float4*)&part[(long)(b * 32 + ch) * HIDD + j] = s;
}

__global__ void mean2_k(const float* __restrict__ part, float* __restrict__ out)
{
    int b = blockIdx.x, j = threadIdx.x;  // 128 threads
    float s = 0.f;
#pragma unroll
    for (int c = 0; c < 32; c++) s += part[(long)(b * 32 + c) * HIDD + j];
    out[b * HIDD + j] = s * (1.f / NCC);
}

// latent: hm2 = hm1 @ le_w2 + le_b2 (tiny GEMV), then penultimate + mu/sigma heads
__global__ void latent_k(const float* __restrict__ hm1,
                         const float* __restrict__ w2, const float* __restrict__ b2,
                         const float* __restrict__ pw, const float* __restrict__ pb,
                         const float* __restrict__ mw, const float* __restrict__ mb,
                         const float* __restrict__ sw, const float* __restrict__ sb,
                         const float* __restrict__ eps, float* __restrict__ z)
{
    __shared__ float hm1s[HIDD];
    __shared__ float hm2[RD];
    __shared__ float h2s[LHD];
    int b = blockIdx.x, tid = threadIdx.x;  // 256 threads
    if (tid < HIDD) hm1s[tid] = hm1[b * HIDD + tid];
    __syncthreads();
    {
        float s = b2[tid];
        for (int k = 0; k < HIDD; k++) s += hm1s[k] * w2[k * RD + tid];
        hm2[tid] = s;
    }
    __syncthreads();
    if (tid < LHD) {
        float s = pb[tid];
        for (int k = 0; k < RD; k++) s += hm2[k] * pw[k * LHD + tid];
        h2s[tid] = s;
    }
    __syncthreads();
    float mu = mb[tid], ls = sb[tid];
    for (int k = 0; k < LHD; k++) {
        mu += h2s[k] * mw[k * RD + tid];
        ls += h2s[k] * sw[k * RD + tid];
    }
    float sig = 0.9f / (1.f + expf(-ls)) + 0.1f;
    z[b * RD + tid] = mu + sig * eps[b * RD + tid];
}

// dec2 (K=128, N=16) fused with mu/sigma epilogue
__global__ void __launch_bounds__(256) dec2_k(
    const float* __restrict__ dh, const float* __restrict__ w2,
    const float* __restrict__ b2, float* __restrict__ out)
{
    __shared__ float w[128][17];
    __shared__ float a[16][132];
    int tid = threadIdx.x;
    for (int i = tid; i < 128 * 16; i += 256) { int k = i >> 4, c = i & 15; w[k][c] = w2[i]; }
    long row0 = (long)blockIdx.x * 16;
    for (int i = tid; i < 512; i += 256) {
        int r = i >> 5, c4 = (i & 31) * 4;
        *(float4*)&a[r][c4] = *(const float4*)&dh[(row0 + r) * 128 + c4];
    }
    __syncthreads();
    int r = tid >> 4, c = tid & 15;
    float s = b2[c];
#pragma unroll
    for (int k = 0; k < 128; k++) s += a[r][k] * w[k][c];
    long row = row0 + r;
    const long TOT = (long)BB * NTT * CTRLD;
    if (c < CTRLD) out[row * CTRLD + c] = s;
    else {
        float sp = fmaxf(s, 0.f) + log1pf(expf(-fabsf(s)));
        out[TOT + row * CTRLD + (c - CTRLD)] = 0.9f * sp + 0.1f;
    }
}

// ===================== host side =====================

static void* symv(const void* s) { void* p = nullptr; cudaGetSymbolAddress(&p, s); return p; }

extern "C" void kernel_launch(void* const* d_in, const int* in_sizes, int n_in,
                              void* d_out, int out_size)
{
    const float* context_x = (const float*)d_in[0];
    const float* context_y = (const float*)d_in[1];
    const float* target_x  = (const float*)d_in[2];
    const float* pred_ctrl = (const float*)d_in[3];
    const float* eps       = (const float*)d_in[4];
    const float* ce_w1 = (const float*)d_in[5];  const float* ce_b1 = (const float*)d_in[6];
    const float* ce_w2 = (const float*)d_in[7];  const float* ce_b2 = (const float*)d_in[8];
    const float* sa_in_w = (const float*)d_in[9];  const float* sa_in_b = (const float*)d_in[10];
    const float* sa_out_w = (const float*)d_in[11]; const float* sa_out_b = (const float*)d_in[12];
    const float* sa_ln_g = (const float*)d_in[13];  const float* sa_ln_b = (const float*)d_in[14];
    const float* qp_w = (const float*)d_in[15]; const float* qp_b = (const float*)d_in[16];
    const float* le_w1 = (const float*)d_in[17]; const float* le_b1 = (const float*)d_in[18];
    const float* le_w2 = (const float*)d_in[19]; const float* le_b2 = (const float*)d_in[20];
    const float* le_pw = (const float*)d_in[21]; const float* le_pb = (const float*)d_in[22];
    const float* le_mw = (const float*)d_in[23]; const float* le_mb = (const float*)d_in[24];
    const float* le_sw = (const float*)d_in[25]; const float* le_sb = (const float*)d_in[26];
    const float* dec_w1 = (const float*)d_in[27]; const float* dec_b1 = (const float*)d_in[28];
    const float* dec_w2 = (const float*)d_in[29]; const float* dec_b2 = (const float*)d_in[30];
    float* out = (float*)d_out;

    unsigned short* h12h  = (unsigned short*)symv(g_h12h);
    float* rep   = (float*)symv(g_rep);
    float* part  = (float*)symv(g_part);
    float* hm1   = (float*)symv(g_hm1);
    float* z     = (float*)symv(g_z);
    unsigned short* qkvh   = (unsigned short*)symv(g_qkvh);
    unsigned short* attnoh = (unsigned short*)symv(g_attnoh);
    unsigned short* rep2h  = (unsigned short*)symv(g_rep2h);
    unsigned short* qth    = (unsigned short*)symv(g_qth);
    unsigned short* deth   = (unsigned short*)symv(g_deth);
    float* dh    = (float*)symv(g_dh);

    const int MC = BB * NCC;   // 16384
    const int MT = BB * NTT;   // 32768

    static cudaStream_t s2 = nullptr;
    static cudaEvent_t ev0 = nullptr, evA = nullptr, evB = nullptr, evC = nullptr;
    if (!s2) {
        cudaStreamCreateWithFlags(&s2, cudaStreamNonBlocking);
        cudaEventCreateWithFlags(&ev0, cudaEventDisableTiming);
        cudaEventCreateWithFlags(&evA, cudaEventDisableTiming);
        cudaEventCreateWithFlags(&evB, cudaEventDisableTiming);
        cudaEventCreateWithFlags(&evC, cudaEventDisableTiming);
    }

    cudaFuncSetAttribute(flash_self_k,  cudaFuncAttributeMaxDynamicSharedMemorySize, SELF_SMEM);
    cudaFuncSetAttribute(flash_cross_k, cudaFuncAttributeMaxDynamicSharedMemorySize, CROSS_SMEM);

    // legal fork: ev0 on capture stream BEFORE s2's first op
    cudaEventRecord(ev0, 0);
    cudaStreamWaitEvent(s2, ev0, 0);

    // qt (half out) on s2
    mma_gemm<32, 0, 0, 0, 1, 0><<<dim3(MT / 128, 2, 1), 256, 0, s2>>>(target_x, qp_w, qp_b, (float*)qth,
        MT, RD, GAPD, GAPD, RD, RD, 1.f, nullptr, nullptr, nullptr, nullptr, nullptr);
    cudaEventRecord(evC, s2);

    // merged MLP1 (le|ce) -> half
    mma_gemm<32, 1, 2, 1, 1, 0><<<dim3(MC / 128, 2, 1), 256>>>(nullptr, le_w1, le_b1, (float*)h12h,
        MC, 2 * HIDD, CIN, CIN, HIDD, 2 * HIDD, 1.f, context_y, context_x, nullptr,
        ce_w1, ce_b1);

    // fork: latent path on s2 (mean-before-GEMM: linear, exact)
    cudaEventRecord(evA, 0);
    cudaStreamWaitEvent(s2, evA, 0);
    mean1h_k<<<dim3(BB, 32), 32, 0, s2>>>(h12h, part);
    mean2_k<<<BB, 128, 0, s2>>>(part, hm1);
    latent_k<<<BB, 256, 0, s2>>>(hm1, le_w2, le_b2, le_pw, le_pb, le_mw, le_mb,
                                 le_sw, le_sb, eps, z);
    cudaEventRecord(evB, s2);

    // deterministic path (A = ce half of h12h)
    mma_gemm<32, 0, 0, 0, 0, 1><<<dim3(MC / 128, 2, 1), 256>>>((const float*)(h12h + HIDD), ce_w2, ce_b2, rep,
        MC, RD, HIDD, 2 * HIDD, RD, RD, 1.f, nullptr, nullptr, nullptr, nullptr, nullptr);

    mma_gemm<32, 0, 0, 0, 1, 0><<<dim3(MC / 128, 6, 1), 256>>>(rep, sa_in_w, sa_in_b, (float*)qkvh,
        MC, 3 * RD, RD, RD, 3 * RD, 3 * RD, 1.f, nullptr, nullptr, nullptr, nullptr, nullptr);

    flash_self_k<<<dim3(NCC / 128, NHD, BB), 256, SELF_SMEM>>>(qkvh, attnoh);

    // fused oproj + residual + LN -> rep2h
    gemm_ln_k<<<MC / 128, 256>>>(attnoh, sa_out_w, sa_out_b, rep, sa_ln_g, sa_ln_b, rep2h);

    // cross attention (join qt)
    cudaStreamWaitEvent(0, evC, 0);
    flash_cross_k<<<dim3(NTT / 64, 1, BB), 256, CROSS_SMEM>>>(qth, rep2h, deth);

    // join latent path, then decoder (dec1 GEMM + dec2)
    cudaStreamWaitEvent(0, evB, 0);
    mma_gemm<32, 1, 1, 0, 0, 0><<<dim3(MT / 128, 1, 1), 256>>>((const float*)deth, dec_w1, dec_b1, dh,
        MT, HIDD, DIN, DIN, HIDD, HIDD, 1.f, z, target_x, pred_ctrl, nullptr, nullptr);
    dec2_k<<<MT / 16, 256>>>(dh, dec_w2, dec_b2, out);
}